// round 4
// baseline (speedup 1.0000x reference)
#include <cuda_runtime.h>
#include <cuda_bf16.h>
#include <math.h>
#include <stdint.h>

#define TOKENS 4096
#define EMB    768
#define NLAYER 12
#define NHEAD  12
#define HDIM   64
#define SEQ    1024
#define NBATCH 4
#define VOCAB  50257
#define FFDIM  3072
#define QKVDIM 2304

// -------------------- scratch (static device globals; no allocation) --------
__device__ float g_x  [TOKENS * EMB];
__device__ float g_a  [TOKENS * EMB];
__device__ float g_qkv[TOKENS * QKVDIM];
__device__ float g_y  [TOKENS * EMB];
__device__ float g_m  [TOKENS * FFDIM];
// pre-split transposed weights ([N,K] K-major, bf16 hi/lo)
__device__ __nv_bfloat16 g_qkvH[(size_t)NLAYER * QKVDIM * EMB];
__device__ __nv_bfloat16 g_qkvL[(size_t)NLAYER * QKVDIM * EMB];
__device__ __nv_bfloat16 g_atpH[(size_t)NLAYER * EMB * EMB];
__device__ __nv_bfloat16 g_atpL[(size_t)NLAYER * EMB * EMB];
__device__ __nv_bfloat16 g_fcH [(size_t)NLAYER * FFDIM * EMB];
__device__ __nv_bfloat16 g_fcL [(size_t)NLAYER * FFDIM * EMB];
__device__ __nv_bfloat16 g_fpH [(size_t)NLAYER * EMB * FFDIM];
__device__ __nv_bfloat16 g_fpL [(size_t)NLAYER * EMB * FFDIM];
__device__ __nv_bfloat16 g_lmH [(size_t)VOCAB * EMB];
__device__ __nv_bfloat16 g_lmL [(size_t)VOCAB * EMB];

// ------------------------------------------------------------- helpers
__device__ __forceinline__ float gelu_f(float x) {
    float x3 = x * x * x;
    return 0.5f * x * (1.f + tanhf(0.7978845608028654f * (x + 0.044715f * x3)));
}
// pack two floats as bf16x2 (low half = first element)
__device__ __forceinline__ uint32_t pack_bf16(float x0, float x1) {
    uint32_t u;
    asm("{.reg .b16 l,h; cvt.rn.bf16.f32 l,%1; cvt.rn.bf16.f32 h,%2; mov.b32 %0,{l,h};}"
        : "=r"(u) : "f"(x0), "f"(x1));
    return u;
}
__device__ __forceinline__ void split2(float x0, float x1, uint32_t& h, uint32_t& l) {
    h = pack_bf16(x0, x1);
    float h0 = __uint_as_float((h & 0xFFFFu) << 16);
    float h1 = __uint_as_float(h & 0xFFFF0000u);
    l = pack_bf16(x0 - h0, x1 - h1);
}
__device__ __forceinline__ void mma_bf16(float* c, const uint32_t* a, const uint32_t* b) {
    asm volatile(
        "mma.sync.aligned.m16n8k16.row.col.f32.bf16.bf16.f32 "
        "{%0,%1,%2,%3}, {%4,%5,%6,%7}, {%8,%9}, {%0,%1,%2,%3};"
        : "+f"(c[0]), "+f"(c[1]), "+f"(c[2]), "+f"(c[3])
        : "r"(a[0]), "r"(a[1]), "r"(a[2]), "r"(a[3]), "r"(b[0]), "r"(b[1]));
}

// ---------------------------------------------------------------- embedding
__global__ void embed_kernel(const int* __restrict__ tok,
                             const float* __restrict__ wte,
                             const float* __restrict__ wpe,
                             float* __restrict__ x) {
    int idx = blockIdx.x * blockDim.x + threadIdx.x;
    if (idx >= TOKENS * EMB) return;
    int t = idx / EMB;
    int e = idx - t * EMB;
    x[idx] = wte[(size_t)tok[t] * EMB + e] + wpe[e];
}

// ---------------------------------------------------------------- layernorm
__global__ void ln_kernel(const float* __restrict__ x,
                          const float* __restrict__ w,
                          const float* __restrict__ bb,
                          float* __restrict__ o) {
    int row = blockIdx.x;
    const float* xr = x + (size_t)row * EMB;
    int t = threadIdx.x;
    float v0 = xr[t], v1 = xr[t + 256], v2 = xr[t + 512];
    float s  = v0 + v1 + v2;
    float sq = v0 * v0 + v1 * v1 + v2 * v2;
    #pragma unroll
    for (int off = 16; off; off >>= 1) {
        s  += __shfl_xor_sync(0xffffffffu, s, off);
        sq += __shfl_xor_sync(0xffffffffu, sq, off);
    }
    __shared__ float rs[8], rq[8];
    __shared__ float s_mean, s_rstd;
    int wid = t >> 5;
    if ((t & 31) == 0) { rs[wid] = s; rq[wid] = sq; }
    __syncthreads();
    if (t == 0) {
        float S = 0.f, Q = 0.f;
        #pragma unroll
        for (int i = 0; i < 8; i++) { S += rs[i]; Q += rq[i]; }
        float mean = S * (1.f / EMB);
        s_mean = mean;
        s_rstd = rsqrtf(Q * (1.f / EMB) - mean * mean + 1e-5f);
    }
    __syncthreads();
    float mean = s_mean, rstd = s_rstd;
    float* orow = o + (size_t)row * EMB;
    orow[t]       = (v0 - mean) * rstd * w[t]       + bb[t];
    orow[t + 256] = (v1 - mean) * rstd * w[t + 256] + bb[t + 256];
    orow[t + 512] = (v2 - mean) * rstd * w[t + 512] + bb[t + 512];
}

// --------------------------------------------- transpose + bf16 hi/lo split
// in [K,N] fp32 -> oh/ol [N,K] bf16, per layer (blockIdx.z)
__global__ void transpose_split_kernel(const float* __restrict__ in,
                                       __nv_bfloat16* __restrict__ oh,
                                       __nv_bfloat16* __restrict__ ol,
                                       int K, int N) {
    __shared__ float t[32][33];
    const size_t off = (size_t)blockIdx.z * K * N;
    int n0 = blockIdx.x * 32, k0 = blockIdx.y * 32;
    int x = threadIdx.x, y = threadIdx.y;
    #pragma unroll
    for (int i = 0; i < 32; i += 8)
        t[y + i][x] = in[off + (size_t)(k0 + y + i) * N + n0 + x];
    __syncthreads();
    #pragma unroll
    for (int i = 0; i < 32; i += 8) {
        float v = t[x][y + i];
        __nv_bfloat16 h = __float2bfloat16(v);
        __nv_bfloat16 l = __float2bfloat16(v - __bfloat162float(h));
        size_t o = off + (size_t)(n0 + y + i) * K + k0 + x;
        oh[o] = h; ol[o] = l;
    }
}

// ------------------------------------------------- elementwise bf16 split
__global__ void split_kernel(const float* __restrict__ in,
                             __nv_bfloat16* __restrict__ oh,
                             __nv_bfloat16* __restrict__ ol, int n) {
    int i = blockIdx.x * blockDim.x + threadIdx.x;
    if (i >= n) return;
    float v = in[i];
    __nv_bfloat16 h = __float2bfloat16(v);
    __nv_bfloat16 l = __float2bfloat16(v - __bfloat162float(h));
    oh[i] = h; ol[i] = l;
}

// --------------------------------------------- bf16 split-3 mma.sync GEMM
// C[M,N] = A[M,K] @ B[N,K]^T, A fp32 runtime-split, B pre-split bf16 hi/lo.
// EPI: 0 = +bias, 1 = +bias+residual, 2 = +bias+gelu, 3 = plain (N guarded)
// CTA 128x128x32, 8 warps as 2(m)x4(n), warp tile 64x32.
#define BP 40   // smem pitch in bf16 units (80 bytes: 16B-aligned, conflict-free)
template <int EPI>
__global__ void __launch_bounds__(256)
gemm_bf16(const float* __restrict__ A,
          const __nv_bfloat16* __restrict__ Bh, const __nv_bfloat16* __restrict__ Bl,
          const float* __restrict__ bias, const float* __restrict__ res,
          float* __restrict__ C, int M, int N, int K) {
    extern __shared__ __nv_bfloat16 sm[];
    __nv_bfloat16* sAh = sm;                 // 2 x [128][BP]
    __nv_bfloat16* sAl = sm + 2 * 128 * BP;
    __nv_bfloat16* sBh = sm + 4 * 128 * BP;
    __nv_bfloat16* sBl = sm + 6 * 128 * BP;

    const int tid  = threadIdx.x;
    const int wid  = tid >> 5;
    const int lane = tid & 31;
    const int grp  = lane >> 2;
    const int tig  = lane & 3;
    const int bm = blockIdx.y * 128;
    const int bn = blockIdx.x * 128;
    const int wm0 = (wid & 1) * 64;
    const int wn0 = (wid >> 1) * 32;

    // staging coords
    const int arow = tid >> 1;          // A: 128 rows x 2 half-rows (16 floats)
    const int acol = (tid & 1) * 16;    //   each thread: 4 float4 = 16 floats
    const int brow = tid >> 1;          // B: 128 rows x 2 uint4 (8 bf16 each)
    const int bq   = (tid & 1) * 8;

    float cf[4][4][4];
    #pragma unroll
    for (int i = 0; i < 4; i++)
        #pragma unroll
        for (int j = 0; j < 4; j++)
            #pragma unroll
            for (int r = 0; r < 4; r++) cf[i][j][r] = 0.f;

    const int KC = K >> 5;

    float4 av[4];
    uint4  ubh[2], ubl[2];

    // ---- prologue: ldg chunk 0 ----
    {
        const float* ap = A + (size_t)(bm + arow) * K + acol;
        #pragma unroll
        for (int i = 0; i < 4; i++) av[i] = *(const float4*)(ap + i * 4);
        bool ok = (EPI != 3) || (bn + brow < N);
        const __nv_bfloat16* bph = Bh + (size_t)(bn + brow) * K + bq;
        const __nv_bfloat16* bpl = Bl + (size_t)(bn + brow) * K + bq;
        if (ok) {
            ubh[0] = *(const uint4*)bph; ubh[1] = *(const uint4*)(bph + 16);
            ubl[0] = *(const uint4*)bpl; ubl[1] = *(const uint4*)(bpl + 16);
        } else {
            ubh[0] = ubh[1] = ubl[0] = ubl[1] = make_uint4(0, 0, 0, 0);
        }
    }

    for (int c = 0; c < KC; c++) {
        const int p = c & 1;
        // ---- store staged chunk into smem buffer p ----
        {
            __nv_bfloat16* dAh = sAh + p * 128 * BP + arow * BP + acol;
            __nv_bfloat16* dAl = sAl + p * 128 * BP + arow * BP + acol;
            #pragma unroll
            for (int i = 0; i < 4; i++) {
                uint32_t h0, l0, h1, l1;
                split2(av[i].x, av[i].y, h0, l0);
                split2(av[i].z, av[i].w, h1, l1);
                *(uint2*)(dAh + i * 4) = make_uint2(h0, h1);
                *(uint2*)(dAl + i * 4) = make_uint2(l0, l1);
            }
            __nv_bfloat16* dBh = sBh + p * 128 * BP + brow * BP + bq;
            __nv_bfloat16* dBl = sBl + p * 128 * BP + brow * BP + bq;
            *(uint4*)dBh = ubh[0]; *(uint4*)(dBh + 16) = ubh[1];
            *(uint4*)dBl = ubl[0]; *(uint4*)(dBl + 16) = ubl[1];
        }
        __syncthreads();

        // ---- prefetch next chunk ----
        if (c + 1 < KC) {
            const int k0 = (c + 1) << 5;
            const float* ap = A + (size_t)(bm + arow) * K + k0 + acol;
            #pragma unroll
            for (int i = 0; i < 4; i++) av[i] = *(const float4*)(ap + i * 4);
            bool ok = (EPI != 3) || (bn + brow < N);
            const __nv_bfloat16* bph = Bh + (size_t)(bn + brow) * K + k0 + bq;
            const __nv_bfloat16* bpl = Bl + (size_t)(bn + brow) * K + k0 + bq;
            if (ok) {
                ubh[0] = *(const uint4*)bph; ubh[1] = *(const uint4*)(bph + 16);
                ubl[0] = *(const uint4*)bpl; ubl[1] = *(const uint4*)(bpl + 16);
            } else {
                ubh[0] = ubh[1] = ubl[0] = ubl[1] = make_uint4(0, 0, 0, 0);
            }
        }

        // ---- mma over 2 k-steps of 16 ----
        const __nv_bfloat16* cAh = sAh + p * 128 * BP;
        const __nv_bfloat16* cAl = sAl + p * 128 * BP;
        const __nv_bfloat16* cBh = sBh + p * 128 * BP;
        const __nv_bfloat16* cBl = sBl + p * 128 * BP;
        #pragma unroll
        for (int ks = 0; ks < 2; ks++) {
            const int k0 = ks * 16;
            uint32_t bh[4][2], bl[4][2];
            #pragma unroll
            for (int nt = 0; nt < 4; nt++) {
                const __nv_bfloat16* bp = cBh + (wn0 + nt * 8 + grp) * BP + k0 + 2 * tig;
                bh[nt][0] = *(const uint32_t*)bp;
                bh[nt][1] = *(const uint32_t*)(bp + 8);
                const __nv_bfloat16* bp2 = cBl + (wn0 + nt * 8 + grp) * BP + k0 + 2 * tig;
                bl[nt][0] = *(const uint32_t*)bp2;
                bl[nt][1] = *(const uint32_t*)(bp2 + 8);
            }
            #pragma unroll
            for (int mt = 0; mt < 4; mt++) {
                uint32_t ah[4], al[4];
                const __nv_bfloat16* ap = cAh + (wm0 + mt * 16 + grp) * BP + k0 + 2 * tig;
                ah[0] = *(const uint32_t*)ap;
                ah[1] = *(const uint32_t*)(ap + 8 * BP);
                ah[2] = *(const uint32_t*)(ap + 8);
                ah[3] = *(const uint32_t*)(ap + 8 * BP + 8);
                const __nv_bfloat16* ap2 = cAl + (wm0 + mt * 16 + grp) * BP + k0 + 2 * tig;
                al[0] = *(const uint32_t*)ap2;
                al[1] = *(const uint32_t*)(ap2 + 8 * BP);
                al[2] = *(const uint32_t*)(ap2 + 8);
                al[3] = *(const uint32_t*)(ap2 + 8 * BP + 8);
                #pragma unroll
                for (int nt = 0; nt < 4; nt++) {
                    mma_bf16(cf[mt][nt], ah, bh[nt]);
                    mma_bf16(cf[mt][nt], al, bh[nt]);
                    mma_bf16(cf[mt][nt], ah, bl[nt]);
                }
            }
        }
        __syncthreads();
    }

    // ---------------- epilogue ----------------
    #pragma unroll
    for (int mt = 0; mt < 4; mt++) {
        #pragma unroll
        for (int half = 0; half < 2; half++) {
            const int row = bm + wm0 + mt * 16 + grp + half * 8;
            #pragma unroll
            for (int nt = 0; nt < 4; nt++) {
                const int col = bn + wn0 + nt * 8 + 2 * tig;
                float v0 = cf[mt][nt][half * 2 + 0];
                float v1 = cf[mt][nt][half * 2 + 1];
                if (EPI == 3) {
                    if (col < N)     C[(size_t)row * N + col]     = v0;
                    if (col + 1 < N) C[(size_t)row * N + col + 1] = v1;
                } else {
                    v0 += bias[col];
                    v1 += bias[col + 1];
                    if (EPI == 1) {
                        const float* rp = res + (size_t)row * N + col;
                        v0 += rp[0]; v1 += rp[1];
                    }
                    if (EPI == 2) { v0 = gelu_f(v0); v1 = gelu_f(v1); }
                    *(float2*)(C + (size_t)row * N + col) = make_float2(v0, v1);
                }
            }
        }
    }
}

// ---------------------------------------------------- fused flash attention
#define AP 68
__global__ void __launch_bounds__(256)
attn_kernel(const float* __restrict__ qkv, float* __restrict__ y) {
    extern __shared__ float smf[];
    float* sQT = smf;
    float* sKT = smf + 64 * AP;
    float* sV  = smf + 2 * 64 * AP;
    float* sS  = smf + 3 * 64 * AP;

    const int tq = blockIdx.x, h = blockIdx.y, b = blockIdx.z;
    const int t  = threadIdx.x;
    const int r0 = (t >> 4) << 2;
    const int c0 = (t & 15) << 2;
    const float scale = 0.036084391824351615f;  // 1/sqrt(768)

    const size_t qbase = ((size_t)b * SEQ + (size_t)tq * 64) * QKVDIM + h * HDIM;
    #pragma unroll
    for (int it = 0; it < 4; it++) {
        int i   = t + it * 256;
        int row = (i >> 2) & 63;
        int kq  = (i & 3) | ((i >> 8) << 2);
        float4 v = *(const float4*)(qkv + qbase + (size_t)row * QKVDIM + kq * 4);
        int kk = kq * 4;
        sQT[(kk + 0) * AP + row] = v.x; sQT[(kk + 1) * AP + row] = v.y;
        sQT[(kk + 2) * AP + row] = v.z; sQT[(kk + 3) * AP + row] = v.w;
    }

    float m[4], l[4], acc[4][4];
    #pragma unroll
    for (int i = 0; i < 4; i++) {
        m[i] = -1e30f; l[i] = 0.f;
        #pragma unroll
        for (int j = 0; j < 4; j++) acc[i][j] = 0.f;
    }

    for (int ks = 0; ks <= tq; ks++) {
        __syncthreads();
        const size_t kbase = ((size_t)b * SEQ + (size_t)ks * 64) * QKVDIM + h * HDIM + EMB;
        #pragma unroll
        for (int it = 0; it < 4; it++) {
            int i   = t + it * 256;
            int row = (i >> 2) & 63;
            int kq  = (i & 3) | ((i >> 8) << 2);
            float4 kv = *(const float4*)(qkv + kbase + (size_t)row * QKVDIM + kq * 4);
            float4 vv = *(const float4*)(qkv + kbase + EMB + (size_t)row * QKVDIM + kq * 4);
            int kk = kq * 4;
            sKT[(kk + 0) * AP + row] = kv.x; sKT[(kk + 1) * AP + row] = kv.y;
            sKT[(kk + 2) * AP + row] = kv.z; sKT[(kk + 3) * AP + row] = kv.w;
            *(float4*)&sV[row * AP + kk] = vv;
        }
        __syncthreads();

        float sc[4][4];
        #pragma unroll
        for (int i = 0; i < 4; i++)
            #pragma unroll
            for (int j = 0; j < 4; j++) sc[i][j] = 0.f;

        #pragma unroll 16
        for (int k = 0; k < 64; k++) {
            float4 qv = *(const float4*)&sQT[k * AP + r0];
            float4 kv = *(const float4*)&sKT[k * AP + c0];
            float qa[4] = {qv.x, qv.y, qv.z, qv.w};
            float ka[4] = {kv.x, kv.y, kv.z, kv.w};
            #pragma unroll
            for (int i = 0; i < 4; i++)
                #pragma unroll
                for (int j = 0; j < 4; j++)
                    sc[i][j] += qa[i] * ka[j];
        }

        const bool diag = (ks == tq);
        #pragma unroll
        for (int i = 0; i < 4; i++)
            #pragma unroll
            for (int j = 0; j < 4; j++) {
                float v = sc[i][j] * scale;
                if (diag && (c0 + j > r0 + i)) v = -1e30f;
                sc[i][j] = v;
            }

        #pragma unroll
        for (int i = 0; i < 4; i++) {
            float tmax = fmaxf(fmaxf(sc[i][0], sc[i][1]), fmaxf(sc[i][2], sc[i][3]));
            #pragma unroll
            for (int off = 1; off < 16; off <<= 1)
                tmax = fmaxf(tmax, __shfl_xor_sync(0xffffffffu, tmax, off));
            float nm   = fmaxf(m[i], tmax);
            float corr = __expf(m[i] - nm);
            m[i] = nm;
            float rs = 0.f;
            #pragma unroll
            for (int j = 0; j < 4; j++) {
                float p = __expf(sc[i][j] - nm);
                sc[i][j] = p;
                rs += p;
            }
            #pragma unroll
            for (int off = 1; off < 16; off <<= 1)
                rs += __shfl_xor_sync(0xffffffffu, rs, off);
            l[i] = l[i] * corr + rs;
            acc[i][0] *= corr; acc[i][1] *= corr;
            acc[i][2] *= corr; acc[i][3] *= corr;
            *(float4*)&sS[(r0 + i) * AP + c0] =
                make_float4(sc[i][0], sc[i][1], sc[i][2], sc[i][3]);
        }
        __syncthreads();

        #pragma unroll 8
        for (int c = 0; c < 64; c++) {
            float4 v = *(const float4*)&sV[c * AP + c0];
            #pragma unroll
            for (int i = 0; i < 4; i++) {
                float p = sS[(r0 + i) * AP + c];
                acc[i][0] += p * v.x; acc[i][1] += p * v.y;
                acc[i][2] += p * v.z; acc[i][3] += p * v.w;
            }
        }
    }

    #pragma unroll
    for (int i = 0; i < 4; i++) {
        float inv = 1.f / l[i];
        float4 o = make_float4(acc[i][0] * inv, acc[i][1] * inv,
                               acc[i][2] * inv, acc[i][3] * inv);
        *(float4*)(y + ((size_t)b * SEQ + (size_t)tq * 64 + r0 + i) * EMB
                     + h * HDIM + c0) = o;
    }
}

// -------------------------------------------------------------------- launch
extern "C" void kernel_launch(void* const* d_in, const int* in_sizes, int n_in,
                              void* d_out, int out_size) {
    const int*   tokens = (const int*)  d_in[0];
    const float* wte    = (const float*)d_in[1];
    const float* wpe    = (const float*)d_in[2];
    const float* ln1w   = (const float*)d_in[3];
    const float* ln1b   = (const float*)d_in[4];
    const float* qkvw   = (const float*)d_in[5];
    const float* qkvb   = (const float*)d_in[6];
    const float* atpw   = (const float*)d_in[7];
    const float* atpb   = (const float*)d_in[8];
    const float* ln2w   = (const float*)d_in[9];
    const float* ln2b   = (const float*)d_in[10];
    const float* fcw    = (const float*)d_in[11];
    const float* fcb    = (const float*)d_in[12];
    const float* fpw    = (const float*)d_in[13];
    const float* fpb    = (const float*)d_in[14];
    const float* lnfw   = (const float*)d_in[15];
    const float* lnfb   = (const float*)d_in[16];
    const float* lmw    = (const float*)d_in[17];
    float* out = (float*)d_out;

    float *px, *pa, *pqkv, *py, *pm;
    __nv_bfloat16 *qh, *ql, *ah, *al, *fh, *fl, *ph, *pl, *lh, *ll;
    cudaGetSymbolAddress((void**)&px,   g_x);
    cudaGetSymbolAddress((void**)&pa,   g_a);
    cudaGetSymbolAddress((void**)&pqkv, g_qkv);
    cudaGetSymbolAddress((void**)&py,   g_y);
    cudaGetSymbolAddress((void**)&pm,   g_m);
    cudaGetSymbolAddress((void**)&qh, g_qkvH); cudaGetSymbolAddress((void**)&ql, g_qkvL);
    cudaGetSymbolAddress((void**)&ah, g_atpH); cudaGetSymbolAddress((void**)&al, g_atpL);
    cudaGetSymbolAddress((void**)&fh, g_fcH);  cudaGetSymbolAddress((void**)&fl, g_fcL);
    cudaGetSymbolAddress((void**)&ph, g_fpH);  cudaGetSymbolAddress((void**)&pl, g_fpL);
    cudaGetSymbolAddress((void**)&lh, g_lmH);  cudaGetSymbolAddress((void**)&ll, g_lmL);

    const int gsmem = 8 * 128 * BP * sizeof(__nv_bfloat16);  // 81920
    cudaFuncSetAttribute(gemm_bf16<0>, cudaFuncAttributeMaxDynamicSharedMemorySize, gsmem);
    cudaFuncSetAttribute(gemm_bf16<1>, cudaFuncAttributeMaxDynamicSharedMemorySize, gsmem);
    cudaFuncSetAttribute(gemm_bf16<2>, cudaFuncAttributeMaxDynamicSharedMemorySize, gsmem);
    cudaFuncSetAttribute(gemm_bf16<3>, cudaFuncAttributeMaxDynamicSharedMemorySize, gsmem);

    const size_t attn_smem = (size_t)4 * 64 * AP * sizeof(float);
    cudaFuncSetAttribute(attn_kernel,
                         cudaFuncAttributeMaxDynamicSharedMemorySize,
                         (int)attn_smem);

    // ---- weight transpose + split (per replay; deterministic) ----
    dim3 tb(32, 8);
    transpose_split_kernel<<<dim3(QKVDIM / 32, EMB / 32, NLAYER), tb>>>(qkvw, qh, ql, EMB, QKVDIM);
    transpose_split_kernel<<<dim3(EMB / 32,    EMB / 32, NLAYER), tb>>>(atpw, ah, al, EMB, EMB);
    transpose_split_kernel<<<dim3(FFDIM / 32,  EMB / 32, NLAYER), tb>>>(fcw,  fh, fl, EMB, FFDIM);
    transpose_split_kernel<<<dim3(EMB / 32,  FFDIM / 32, NLAYER), tb>>>(fpw,  ph, pl, FFDIM, EMB);
    split_kernel<<<(VOCAB * EMB + 255) / 256, 256>>>(lmw, lh, ll, VOCAB * EMB);

    embed_kernel<<<(TOKENS * EMB + 255) / 256, 256>>>(tokens, wte, wpe, px);

    for (int i = 0; i < NLAYER; i++) {
        ln_kernel<<<TOKENS, 256>>>(px, ln1w + i * EMB, ln1b + i * EMB, pa);

        gemm_bf16<0><<<dim3(QKVDIM / 128, TOKENS / 128), 256, gsmem>>>(
            pa, qh + (size_t)i * QKVDIM * EMB, ql + (size_t)i * QKVDIM * EMB,
            qkvb + i * QKVDIM, nullptr, pqkv, TOKENS, QKVDIM, EMB);

        attn_kernel<<<dim3(SEQ / 64, NHEAD, NBATCH), 256, attn_smem>>>(pqkv, py);

        gemm_bf16<1><<<dim3(EMB / 128, TOKENS / 128), 256, gsmem>>>(
            py, ah + (size_t)i * EMB * EMB, al + (size_t)i * EMB * EMB,
            atpb + i * EMB, px, px, TOKENS, EMB, EMB);

        ln_kernel<<<TOKENS, 256>>>(px, ln2w + i * EMB, ln2b + i * EMB, pa);

        gemm_bf16<2><<<dim3(FFDIM / 128, TOKENS / 128), 256, gsmem>>>(
            pa, fh + (size_t)i * FFDIM * EMB, fl + (size_t)i * FFDIM * EMB,
            fcb + i * FFDIM, nullptr, pm, TOKENS, FFDIM, EMB);

        gemm_bf16<1><<<dim3(EMB / 128, TOKENS / 128), 256, gsmem>>>(
            pm, ph + (size_t)i * EMB * FFDIM, pl + (size_t)i * EMB * FFDIM,
            fpb + i * EMB, px, px, TOKENS, EMB, FFDIM);
    }

    ln_kernel<<<TOKENS, 256>>>(px, lnfw, lnfb, pa);

    gemm_bf16<3><<<dim3((VOCAB + 127) / 128, TOKENS / 128), 256, gsmem>>>(
        pa, lh, ll, nullptr, nullptr, out, TOKENS, VOCAB, EMB);
}

// round 5
// speedup vs baseline: 1.9591x; 1.9591x over previous
#include <cuda_runtime.h>
#include <cuda_fp16.h>
#include <math.h>
#include <stdint.h>

#define TOKENS 4096
#define EMB    768
#define NLAYER 12
#define NHEAD  12
#define HDIM   64
#define SEQ    1024
#define NBATCH 4
#define VOCAB  50257
#define FFDIM  3072
#define QKVDIM 2304

// -------------------- scratch (static device globals; no allocation) --------
__device__ float g_x  [TOKENS * EMB];
__device__ float g_a  [TOKENS * EMB];
__device__ float g_qkv[TOKENS * QKVDIM];
__device__ float g_y  [TOKENS * EMB];
__device__ float g_m  [TOKENS * FFDIM];
// pre-split transposed weights ([N,K] K-major, fp16 hi/lo: hi+lo == fp32 weight)
__device__ __half g_qkvH[(size_t)NLAYER * QKVDIM * EMB];
__device__ __half g_qkvL[(size_t)NLAYER * QKVDIM * EMB];
__device__ __half g_atpH[(size_t)NLAYER * EMB * EMB];
__device__ __half g_atpL[(size_t)NLAYER * EMB * EMB];
__device__ __half g_fcH [(size_t)NLAYER * FFDIM * EMB];
__device__ __half g_fcL [(size_t)NLAYER * FFDIM * EMB];
__device__ __half g_fpH [(size_t)NLAYER * EMB * FFDIM];
__device__ __half g_fpL [(size_t)NLAYER * EMB * FFDIM];
__device__ __half g_lmH [(size_t)VOCAB * EMB];
__device__ __half g_lmL [(size_t)VOCAB * EMB];

// ------------------------------------------------------------- helpers
__device__ __forceinline__ float gelu_f(float x) {
    float x3 = x * x * x;
    return 0.5f * x * (1.f + tanhf(0.7978845608028654f * (x + 0.044715f * x3)));
}
// pack two floats as fp16x2 (low half = first element)
__device__ __forceinline__ uint32_t pack_f16(float x0, float x1) {
    uint32_t u;
    asm("{.reg .b16 l,h; cvt.rn.f16.f32 l,%1; cvt.rn.f16.f32 h,%2; mov.b32 %0,{l,h};}"
        : "=r"(u) : "f"(x0), "f"(x1));
    return u;
}
__device__ __forceinline__ void mma_f16(float* c, const uint32_t* a, const uint32_t* b) {
    asm volatile(
        "mma.sync.aligned.m16n8k16.row.col.f32.f16.f16.f32 "
        "{%0,%1,%2,%3}, {%4,%5,%6,%7}, {%8,%9}, {%0,%1,%2,%3};"
        : "+f"(c[0]), "+f"(c[1]), "+f"(c[2]), "+f"(c[3])
        : "r"(a[0]), "r"(a[1]), "r"(a[2]), "r"(a[3]), "r"(b[0]), "r"(b[1]));
}

// ---------------------------------------------------------------- embedding
__global__ void embed_kernel(const int* __restrict__ tok,
                             const float* __restrict__ wte,
                             const float* __restrict__ wpe,
                             float* __restrict__ x) {
    int idx = blockIdx.x * blockDim.x + threadIdx.x;
    if (idx >= TOKENS * EMB) return;
    int t = idx / EMB;
    int e = idx - t * EMB;
    x[idx] = wte[(size_t)tok[t] * EMB + e] + wpe[e];
}

// ---------------------------------------------------------------- layernorm
__global__ void ln_kernel(const float* __restrict__ x,
                          const float* __restrict__ w,
                          const float* __restrict__ bb,
                          float* __restrict__ o) {
    int row = blockIdx.x;
    const float* xr = x + (size_t)row * EMB;
    int t = threadIdx.x;
    float v0 = xr[t], v1 = xr[t + 256], v2 = xr[t + 512];
    float s  = v0 + v1 + v2;
    float sq = v0 * v0 + v1 * v1 + v2 * v2;
    #pragma unroll
    for (int off = 16; off; off >>= 1) {
        s  += __shfl_xor_sync(0xffffffffu, s, off);
        sq += __shfl_xor_sync(0xffffffffu, sq, off);
    }
    __shared__ float rs[8], rq[8];
    __shared__ float s_mean, s_rstd;
    int wid = t >> 5;
    if ((t & 31) == 0) { rs[wid] = s; rq[wid] = sq; }
    __syncthreads();
    if (t == 0) {
        float S = 0.f, Q = 0.f;
        #pragma unroll
        for (int i = 0; i < 8; i++) { S += rs[i]; Q += rq[i]; }
        float mean = S * (1.f / EMB);
        s_mean = mean;
        s_rstd = rsqrtf(Q * (1.f / EMB) - mean * mean + 1e-5f);
    }
    __syncthreads();
    float mean = s_mean, rstd = s_rstd;
    float* orow = o + (size_t)row * EMB;
    orow[t]       = (v0 - mean) * rstd * w[t]       + bb[t];
    orow[t + 256] = (v1 - mean) * rstd * w[t + 256] + bb[t + 256];
    orow[t + 512] = (v2 - mean) * rstd * w[t + 512] + bb[t + 512];
}

// --------------------------------------------- transpose + fp16 hi/lo split
// in [K,N] fp32 -> oh/ol [N,K] fp16, per layer (blockIdx.z)
__global__ void transpose_split_kernel(const float* __restrict__ in,
                                       __half* __restrict__ oh,
                                       __half* __restrict__ ol,
                                       int K, int N) {
    __shared__ float t[32][33];
    const size_t off = (size_t)blockIdx.z * K * N;
    int n0 = blockIdx.x * 32, k0 = blockIdx.y * 32;
    int x = threadIdx.x, y = threadIdx.y;
    #pragma unroll
    for (int i = 0; i < 32; i += 8)
        t[y + i][x] = in[off + (size_t)(k0 + y + i) * N + n0 + x];
    __syncthreads();
    #pragma unroll
    for (int i = 0; i < 32; i += 8) {
        float v = t[x][y + i];
        __half h = __float2half_rn(v);
        __half l = __float2half_rn(v - __half2float(h));
        size_t o = off + (size_t)(n0 + y + i) * K + k0 + x;
        oh[o] = h; ol[o] = l;
    }
}

// ------------------------------------------------- elementwise fp16 split
__global__ void split_kernel(const float* __restrict__ in,
                             __half* __restrict__ oh,
                             __half* __restrict__ ol, int n) {
    int i = blockIdx.x * blockDim.x + threadIdx.x;
    if (i >= n) return;
    float v = in[i];
    __half h = __float2half_rn(v);
    __half l = __float2half_rn(v - __half2float(h));
    oh[i] = h; ol[i] = l;
}

// ------------------------------------------- fp16 B-split-2 mma.sync GEMM
// C[M,N] = A[M,K] @ B[N,K]^T, A rounded fp16 at staging, B = Bh + Bl exact.
// EPI: 0 = +bias, 1 = +bias+residual, 2 = +bias+gelu, 3 = plain (N guarded)
// CTA 128x128x32, 8 warps as 2(m)x4(n), warp tile 64x32.
#define BP 40   // smem pitch in fp16 units (80 B: 16B-aligned, conflict-free)
template <int EPI>
__global__ void __launch_bounds__(256)
gemm_f16(const float* __restrict__ A,
         const __half* __restrict__ Bh, const __half* __restrict__ Bl,
         const float* __restrict__ bias, const float* __restrict__ res,
         float* __restrict__ C, int M, int N, int K) {
    extern __shared__ __half sm[];
    __half* sA  = sm;                 // 2 x [128][BP]
    __half* sBh = sm + 2 * 128 * BP;
    __half* sBl = sm + 4 * 128 * BP;

    const int tid  = threadIdx.x;
    const int wid  = tid >> 5;
    const int lane = tid & 31;
    const int grp  = lane >> 2;
    const int tig  = lane & 3;
    const int bm = blockIdx.y * 128;
    const int bn = blockIdx.x * 128;
    const int wm0 = (wid & 1) * 64;
    const int wn0 = (wid >> 1) * 32;

    // staging coords: each thread handles half a row (16 elements of 32)
    const int row16 = tid >> 1;
    const int half16 = (tid & 1) * 16;

    float cf[4][4][4];
    #pragma unroll
    for (int i = 0; i < 4; i++)
        #pragma unroll
        for (int j = 0; j < 4; j++)
            #pragma unroll
            for (int r = 0; r < 4; r++) cf[i][j][r] = 0.f;

    const int KC = K >> 5;

    float4 av[4];
    uint4  ubh[2], ubl[2];

    // ---- prologue: ldg chunk 0 ----
    {
        const float* ap = A + (size_t)(bm + row16) * K + half16;
        #pragma unroll
        for (int i = 0; i < 4; i++) av[i] = *(const float4*)(ap + i * 4);
        bool ok = (EPI != 3) || (bn + row16 < N);
        const __half* bph = Bh + (size_t)(bn + row16) * K + half16;
        const __half* bpl = Bl + (size_t)(bn + row16) * K + half16;
        if (ok) {
            ubh[0] = *(const uint4*)bph; ubh[1] = *(const uint4*)(bph + 8);
            ubl[0] = *(const uint4*)bpl; ubl[1] = *(const uint4*)(bpl + 8);
        } else {
            ubh[0] = ubh[1] = ubl[0] = ubl[1] = make_uint4(0, 0, 0, 0);
        }
    }

    for (int c = 0; c < KC; c++) {
        const int p = c & 1;
        // ---- store staged chunk into smem buffer p ----
        {
            __half* dA = sA + p * 128 * BP + row16 * BP + half16;
            uint32_t w0 = pack_f16(av[0].x, av[0].y);
            uint32_t w1 = pack_f16(av[0].z, av[0].w);
            uint32_t w2 = pack_f16(av[1].x, av[1].y);
            uint32_t w3 = pack_f16(av[1].z, av[1].w);
            uint32_t w4 = pack_f16(av[2].x, av[2].y);
            uint32_t w5 = pack_f16(av[2].z, av[2].w);
            uint32_t w6 = pack_f16(av[3].x, av[3].y);
            uint32_t w7 = pack_f16(av[3].z, av[3].w);
            *(uint4*)dA       = make_uint4(w0, w1, w2, w3);
            *(uint4*)(dA + 8) = make_uint4(w4, w5, w6, w7);
            __half* dBh = sBh + p * 128 * BP + row16 * BP + half16;
            __half* dBl = sBl + p * 128 * BP + row16 * BP + half16;
            *(uint4*)dBh = ubh[0]; *(uint4*)(dBh + 8) = ubh[1];
            *(uint4*)dBl = ubl[0]; *(uint4*)(dBl + 8) = ubl[1];
        }
        __syncthreads();

        // ---- prefetch next chunk ----
        if (c + 1 < KC) {
            const int k0 = (c + 1) << 5;
            const float* ap = A + (size_t)(bm + row16) * K + k0 + half16;
            #pragma unroll
            for (int i = 0; i < 4; i++) av[i] = *(const float4*)(ap + i * 4);
            bool ok = (EPI != 3) || (bn + row16 < N);
            const __half* bph = Bh + (size_t)(bn + row16) * K + k0 + half16;
            const __half* bpl = Bl + (size_t)(bn + row16) * K + k0 + half16;
            if (ok) {
                ubh[0] = *(const uint4*)bph; ubh[1] = *(const uint4*)(bph + 8);
                ubl[0] = *(const uint4*)bpl; ubl[1] = *(const uint4*)(bpl + 8);
            } else {
                ubh[0] = ubh[1] = ubl[0] = ubl[1] = make_uint4(0, 0, 0, 0);
            }
        }

        // ---- mma over 2 k-steps of 16 ----
        const __half* cA  = sA  + p * 128 * BP;
        const __half* cBh = sBh + p * 128 * BP;
        const __half* cBl = sBl + p * 128 * BP;
        #pragma unroll
        for (int ks = 0; ks < 2; ks++) {
            const int k0 = ks * 16;
            uint32_t bh[4][2], bl[4][2];
            #pragma unroll
            for (int nt = 0; nt < 4; nt++) {
                const __half* bp = cBh + (wn0 + nt * 8 + grp) * BP + k0 + 2 * tig;
                bh[nt][0] = *(const uint32_t*)bp;
                bh[nt][1] = *(const uint32_t*)(bp + 8);
                const __half* bp2 = cBl + (wn0 + nt * 8 + grp) * BP + k0 + 2 * tig;
                bl[nt][0] = *(const uint32_t*)bp2;
                bl[nt][1] = *(const uint32_t*)(bp2 + 8);
            }
            #pragma unroll
            for (int mt = 0; mt < 4; mt++) {
                uint32_t a[4];
                const __half* ap = cA + (wm0 + mt * 16 + grp) * BP + k0 + 2 * tig;
                a[0] = *(const uint32_t*)ap;
                a[1] = *(const uint32_t*)(ap + 8 * BP);
                a[2] = *(const uint32_t*)(ap + 8);
                a[3] = *(const uint32_t*)(ap + 8 * BP + 8);
                #pragma unroll
                for (int nt = 0; nt < 4; nt++) {
                    mma_f16(cf[mt][nt], a, bh[nt]);
                    mma_f16(cf[mt][nt], a, bl[nt]);
                }
            }
        }
        __syncthreads();
    }

    // ---------------- epilogue ----------------
    #pragma unroll
    for (int mt = 0; mt < 4; mt++) {
        #pragma unroll
        for (int half = 0; half < 2; half++) {
            const int row = bm + wm0 + mt * 16 + grp + half * 8;
            #pragma unroll
            for (int nt = 0; nt < 4; nt++) {
                const int col = bn + wn0 + nt * 8 + 2 * tig;
                float v0 = cf[mt][nt][half * 2 + 0];
                float v1 = cf[mt][nt][half * 2 + 1];
                if (EPI == 3) {
                    if (col < N)     C[(size_t)row * N + col]     = v0;
                    if (col + 1 < N) C[(size_t)row * N + col + 1] = v1;
                } else {
                    v0 += bias[col];
                    v1 += bias[col + 1];
                    if (EPI == 1) {
                        const float* rp = res + (size_t)row * N + col;
                        v0 += rp[0]; v1 += rp[1];
                    }
                    if (EPI == 2) { v0 = gelu_f(v0); v1 = gelu_f(v1); }
                    *(float2*)(C + (size_t)row * N + col) = make_float2(v0, v1);
                }
            }
        }
    }
}

// ---------------------------------------------------- fused flash attention
#define AP 68
__global__ void __launch_bounds__(256)
attn_kernel(const float* __restrict__ qkv, float* __restrict__ y) {
    extern __shared__ float smf[];
    float* sQT = smf;
    float* sKT = smf + 64 * AP;
    float* sV  = smf + 2 * 64 * AP;
    float* sS  = smf + 3 * 64 * AP;

    const int tq = blockIdx.x, h = blockIdx.y, b = blockIdx.z;
    const int t  = threadIdx.x;
    const int r0 = (t >> 4) << 2;
    const int c0 = (t & 15) << 2;
    const float scale = 0.036084391824351615f;  // 1/sqrt(768)

    const size_t qbase = ((size_t)b * SEQ + (size_t)tq * 64) * QKVDIM + h * HDIM;
    #pragma unroll
    for (int it = 0; it < 4; it++) {
        int i   = t + it * 256;
        int row = (i >> 2) & 63;
        int kq  = (i & 3) | ((i >> 8) << 2);
        float4 v = *(const float4*)(qkv + qbase + (size_t)row * QKVDIM + kq * 4);
        int kk = kq * 4;
        sQT[(kk + 0) * AP + row] = v.x; sQT[(kk + 1) * AP + row] = v.y;
        sQT[(kk + 2) * AP + row] = v.z; sQT[(kk + 3) * AP + row] = v.w;
    }

    float m[4], l[4], acc[4][4];
    #pragma unroll
    for (int i = 0; i < 4; i++) {
        m[i] = -1e30f; l[i] = 0.f;
        #pragma unroll
        for (int j = 0; j < 4; j++) acc[i][j] = 0.f;
    }

    for (int ks = 0; ks <= tq; ks++) {
        __syncthreads();
        const size_t kbase = ((size_t)b * SEQ + (size_t)ks * 64) * QKVDIM + h * HDIM + EMB;
        #pragma unroll
        for (int it = 0; it < 4; it++) {
            int i   = t + it * 256;
            int row = (i >> 2) & 63;
            int kq  = (i & 3) | ((i >> 8) << 2);
            float4 kv = *(const float4*)(qkv + kbase + (size_t)row * QKVDIM + kq * 4);
            float4 vv = *(const float4*)(qkv + kbase + EMB + (size_t)row * QKVDIM + kq * 4);
            int kk = kq * 4;
            sKT[(kk + 0) * AP + row] = kv.x; sKT[(kk + 1) * AP + row] = kv.y;
            sKT[(kk + 2) * AP + row] = kv.z; sKT[(kk + 3) * AP + row] = kv.w;
            *(float4*)&sV[row * AP + kk] = vv;
        }
        __syncthreads();

        float sc[4][4];
        #pragma unroll
        for (int i = 0; i < 4; i++)
            #pragma unroll
            for (int j = 0; j < 4; j++) sc[i][j] = 0.f;

        #pragma unroll 16
        for (int k = 0; k < 64; k++) {
            float4 qv = *(const float4*)&sQT[k * AP + r0];
            float4 kv = *(const float4*)&sKT[k * AP + c0];
            float qa[4] = {qv.x, qv.y, qv.z, qv.w};
            float ka[4] = {kv.x, kv.y, kv.z, kv.w};
            #pragma unroll
            for (int i = 0; i < 4; i++)
                #pragma unroll
                for (int j = 0; j < 4; j++)
                    sc[i][j] += qa[i] * ka[j];
        }

        const bool diag = (ks == tq);
        #pragma unroll
        for (int i = 0; i < 4; i++)
            #pragma unroll
            for (int j = 0; j < 4; j++) {
                float v = sc[i][j] * scale;
                if (diag && (c0 + j > r0 + i)) v = -1e30f;
                sc[i][j] = v;
            }

        #pragma unroll
        for (int i = 0; i < 4; i++) {
            float tmax = fmaxf(fmaxf(sc[i][0], sc[i][1]), fmaxf(sc[i][2], sc[i][3]));
            #pragma unroll
            for (int off = 1; off < 16; off <<= 1)
                tmax = fmaxf(tmax, __shfl_xor_sync(0xffffffffu, tmax, off));
            float nm   = fmaxf(m[i], tmax);
            float corr = __expf(m[i] - nm);
            m[i] = nm;
            float rs = 0.f;
            #pragma unroll
            for (int j = 0; j < 4; j++) {
                float p = __expf(sc[i][j] - nm);
                sc[i][j] = p;
                rs += p;
            }
            #pragma unroll
            for (int off = 1; off < 16; off <<= 1)
                rs += __shfl_xor_sync(0xffffffffu, rs, off);
            l[i] = l[i] * corr + rs;
            acc[i][0] *= corr; acc[i][1] *= corr;
            acc[i][2] *= corr; acc[i][3] *= corr;
            *(float4*)&sS[(r0 + i) * AP + c0] =
                make_float4(sc[i][0], sc[i][1], sc[i][2], sc[i][3]);
        }
        __syncthreads();

        // ---- PV: acc += P @ V  (float4 P loads, 4-column V blocks) ----
        #pragma unroll 4
        for (int cb = 0; cb < 64; cb += 4) {
            float4 v0 = *(const float4*)&sV[(cb + 0) * AP + c0];
            float4 v1 = *(const float4*)&sV[(cb + 1) * AP + c0];
            float4 v2 = *(const float4*)&sV[(cb + 2) * AP + c0];
            float4 v3 = *(const float4*)&sV[(cb + 3) * AP + c0];
            #pragma unroll
            for (int i = 0; i < 4; i++) {
                float4 pv = *(const float4*)&sS[(r0 + i) * AP + cb];
                acc[i][0] += pv.x * v0.x + pv.y * v1.x + pv.z * v2.x + pv.w * v3.x;
                acc[i][1] += pv.x * v0.y + pv.y * v1.y + pv.z * v2.y + pv.w * v3.y;
                acc[i][2] += pv.x * v0.z + pv.y * v1.z + pv.z * v2.z + pv.w * v3.z;
                acc[i][3] += pv.x * v0.w + pv.y * v1.w + pv.z * v2.w + pv.w * v3.w;
            }
        }
    }

    #pragma unroll
    for (int i = 0; i < 4; i++) {
        float inv = 1.f / l[i];
        float4 o = make_float4(acc[i][0] * inv, acc[i][1] * inv,
                               acc[i][2] * inv, acc[i][3] * inv);
        *(float4*)(y + ((size_t)b * SEQ + (size_t)tq * 64 + r0 + i) * EMB
                     + h * HDIM + c0) = o;
    }
}

// -------------------------------------------------------------------- launch
extern "C" void kernel_launch(void* const* d_in, const int* in_sizes, int n_in,
                              void* d_out, int out_size) {
    const int*   tokens = (const int*)  d_in[0];
    const float* wte    = (const float*)d_in[1];
    const float* wpe    = (const float*)d_in[2];
    const float* ln1w   = (const float*)d_in[3];
    const float* ln1b   = (const float*)d_in[4];
    const float* qkvw   = (const float*)d_in[5];
    const float* qkvb   = (const float*)d_in[6];
    const float* atpw   = (const float*)d_in[7];
    const float* atpb   = (const float*)d_in[8];
    const float* ln2w   = (const float*)d_in[9];
    const float* ln2b   = (const float*)d_in[10];
    const float* fcw    = (const float*)d_in[11];
    const float* fcb    = (const float*)d_in[12];
    const float* fpw    = (const float*)d_in[13];
    const float* fpb    = (const float*)d_in[14];
    const float* lnfw   = (const float*)d_in[15];
    const float* lnfb   = (const float*)d_in[16];
    const float* lmw    = (const float*)d_in[17];
    float* out = (float*)d_out;

    float *px, *pa, *pqkv, *py, *pm;
    __half *qh, *ql, *ah, *al, *fh, *fl, *ph, *pl, *lh, *ll;
    cudaGetSymbolAddress((void**)&px,   g_x);
    cudaGetSymbolAddress((void**)&pa,   g_a);
    cudaGetSymbolAddress((void**)&pqkv, g_qkv);
    cudaGetSymbolAddress((void**)&py,   g_y);
    cudaGetSymbolAddress((void**)&pm,   g_m);
    cudaGetSymbolAddress((void**)&qh, g_qkvH); cudaGetSymbolAddress((void**)&ql, g_qkvL);
    cudaGetSymbolAddress((void**)&ah, g_atpH); cudaGetSymbolAddress((void**)&al, g_atpL);
    cudaGetSymbolAddress((void**)&fh, g_fcH);  cudaGetSymbolAddress((void**)&fl, g_fcL);
    cudaGetSymbolAddress((void**)&ph, g_fpH);  cudaGetSymbolAddress((void**)&pl, g_fpL);
    cudaGetSymbolAddress((void**)&lh, g_lmH);  cudaGetSymbolAddress((void**)&ll, g_lmL);

    const int gsmem = 6 * 128 * BP * sizeof(__half);  // 61440
    cudaFuncSetAttribute(gemm_f16<0>, cudaFuncAttributeMaxDynamicSharedMemorySize, gsmem);
    cudaFuncSetAttribute(gemm_f16<1>, cudaFuncAttributeMaxDynamicSharedMemorySize, gsmem);
    cudaFuncSetAttribute(gemm_f16<2>, cudaFuncAttributeMaxDynamicSharedMemorySize, gsmem);
    cudaFuncSetAttribute(gemm_f16<3>, cudaFuncAttributeMaxDynamicSharedMemorySize, gsmem);

    const size_t attn_smem = (size_t)4 * 64 * AP * sizeof(float);
    cudaFuncSetAttribute(attn_kernel,
                         cudaFuncAttributeMaxDynamicSharedMemorySize,
                         (int)attn_smem);

    // ---- weight transpose + fp16 split (per replay; deterministic) ----
    dim3 tb(32, 8);
    transpose_split_kernel<<<dim3(QKVDIM / 32, EMB / 32, NLAYER), tb>>>(qkvw, qh, ql, EMB, QKVDIM);
    transpose_split_kernel<<<dim3(EMB / 32,    EMB / 32, NLAYER), tb>>>(atpw, ah, al, EMB, EMB);
    transpose_split_kernel<<<dim3(FFDIM / 32,  EMB / 32, NLAYER), tb>>>(fcw,  fh, fl, EMB, FFDIM);
    transpose_split_kernel<<<dim3(EMB / 32,  FFDIM / 32, NLAYER), tb>>>(fpw,  ph, pl, FFDIM, EMB);
    split_kernel<<<(VOCAB * EMB + 255) / 256, 256>>>(lmw, lh, ll, VOCAB * EMB);

    embed_kernel<<<(TOKENS * EMB + 255) / 256, 256>>>(tokens, wte, wpe, px);

    for (int i = 0; i < NLAYER; i++) {
        ln_kernel<<<TOKENS, 256>>>(px, ln1w + i * EMB, ln1b + i * EMB, pa);

        gemm_f16<0><<<dim3(QKVDIM / 128, TOKENS / 128), 256, gsmem>>>(
            pa, qh + (size_t)i * QKVDIM * EMB, ql + (size_t)i * QKVDIM * EMB,
            qkvb + i * QKVDIM, nullptr, pqkv, TOKENS, QKVDIM, EMB);

        attn_kernel<<<dim3(SEQ / 64, NHEAD, NBATCH), 256, attn_smem>>>(pqkv, py);

        gemm_f16<1><<<dim3(EMB / 128, TOKENS / 128), 256, gsmem>>>(
            py, ah + (size_t)i * EMB * EMB, al + (size_t)i * EMB * EMB,
            atpb + i * EMB, px, px, TOKENS, EMB, EMB);

        ln_kernel<<<TOKENS, 256>>>(px, ln2w + i * EMB, ln2b + i * EMB, pa);

        gemm_f16<2><<<dim3(FFDIM / 128, TOKENS / 128), 256, gsmem>>>(
            pa, fh + (size_t)i * FFDIM * EMB, fl + (size_t)i * FFDIM * EMB,
            fcb + i * FFDIM, nullptr, pm, TOKENS, FFDIM, EMB);

        gemm_f16<1><<<dim3(EMB / 128, TOKENS / 128), 256, gsmem>>>(
            pm, ph + (size_t)i * EMB * FFDIM, pl + (size_t)i * EMB * FFDIM,
            fpb + i * EMB, px, px, TOKENS, EMB, FFDIM);
    }

    ln_kernel<<<TOKENS, 256>>>(px, lnfw, lnfb, pa);

    gemm_f16<3><<<dim3((VOCAB + 127) / 128, TOKENS / 128), 256, gsmem>>>(
        pa, lh, ll, nullptr, nullptr, out, TOKENS, VOCAB, EMB);
}

// round 6
// speedup vs baseline: 2.5979x; 1.3261x over previous
#include <cuda_runtime.h>
#include <cuda_fp16.h>
#include <math.h>
#include <stdint.h>

#define TOKENS 4096
#define EMB    768
#define NLAYER 12
#define NHEAD  12
#define HDIM   64
#define SEQ    1024
#define NBATCH 4
#define VOCAB  50257
#define FFDIM  3072
#define QKVDIM 2304

// -------------------- scratch (static device globals; no allocation) --------
__device__ float g_x  [TOKENS * EMB];
__device__ float g_a  [TOKENS * EMB];
__device__ float g_qkv[TOKENS * QKVDIM];
__device__ float g_y  [TOKENS * EMB];
__device__ float g_m  [TOKENS * FFDIM];
// pre-split transposed weights ([N,K] K-major, fp16 hi/lo: hi+lo == fp32 weight)
__device__ __half g_qkvH[(size_t)NLAYER * QKVDIM * EMB];
__device__ __half g_qkvL[(size_t)NLAYER * QKVDIM * EMB];
__device__ __half g_atpH[(size_t)NLAYER * EMB * EMB];
__device__ __half g_atpL[(size_t)NLAYER * EMB * EMB];
__device__ __half g_fcH [(size_t)NLAYER * FFDIM * EMB];
__device__ __half g_fcL [(size_t)NLAYER * FFDIM * EMB];
__device__ __half g_fpH [(size_t)NLAYER * EMB * FFDIM];
__device__ __half g_fpL [(size_t)NLAYER * EMB * FFDIM];
__device__ __half g_lmH [(size_t)VOCAB * EMB];
__device__ __half g_lmL [(size_t)VOCAB * EMB];

// ------------------------------------------------------------- helpers
__device__ __forceinline__ float gelu_f(float x) {
    float x3 = x * x * x;
    return 0.5f * x * (1.f + tanhf(0.7978845608028654f * (x + 0.044715f * x3)));
}
__device__ __forceinline__ uint32_t pack_f16(float x0, float x1) {
    uint32_t u;
    asm("{.reg .b16 l,h; cvt.rn.f16.f32 l,%1; cvt.rn.f16.f32 h,%2; mov.b32 %0,{l,h};}"
        : "=r"(u) : "f"(x0), "f"(x1));
    return u;
}
__device__ __forceinline__ void mma_f16(float* c, const uint32_t* a, const uint32_t* b) {
    asm volatile(
        "mma.sync.aligned.m16n8k16.row.col.f32.f16.f16.f32 "
        "{%0,%1,%2,%3}, {%4,%5,%6,%7}, {%8,%9}, {%0,%1,%2,%3};"
        : "+f"(c[0]), "+f"(c[1]), "+f"(c[2]), "+f"(c[3])
        : "r"(a[0]), "r"(a[1]), "r"(a[2]), "r"(a[3]), "r"(b[0]), "r"(b[1]));
}
__device__ __forceinline__ void ldmx4(uint32_t& r0, uint32_t& r1,
                                      uint32_t& r2, uint32_t& r3, uint32_t addr) {
    asm volatile("ldmatrix.sync.aligned.m8n8.x4.shared.b16 {%0,%1,%2,%3}, [%4];"
                 : "=r"(r0), "=r"(r1), "=r"(r2), "=r"(r3) : "r"(addr));
}
__device__ __forceinline__ void cpa16(uint32_t dst, const void* src, int srcsz) {
    asm volatile("cp.async.ca.shared.global [%0], [%1], 16, %2;"
                 :: "r"(dst), "l"(src), "r"(srcsz) : "memory");
}
#define CP_COMMIT() asm volatile("cp.async.commit_group;" ::: "memory")
#define CP_WAIT0()  asm volatile("cp.async.wait_group 0;" ::: "memory")

// ---------------------------------------------------------------- embedding
__global__ void embed_kernel(const int* __restrict__ tok,
                             const float* __restrict__ wte,
                             const float* __restrict__ wpe,
                             float* __restrict__ x) {
    int idx = blockIdx.x * blockDim.x + threadIdx.x;
    if (idx >= TOKENS * EMB) return;
    int t = idx / EMB;
    int e = idx - t * EMB;
    x[idx] = wte[(size_t)tok[t] * EMB + e] + wpe[e];
}

// ---------------------------------------------------------------- layernorm
__global__ void ln_kernel(const float* __restrict__ x,
                          const float* __restrict__ w,
                          const float* __restrict__ bb,
                          float* __restrict__ o) {
    int row = blockIdx.x;
    const float* xr = x + (size_t)row * EMB;
    int t = threadIdx.x;
    float v0 = xr[t], v1 = xr[t + 256], v2 = xr[t + 512];
    float s  = v0 + v1 + v2;
    float sq = v0 * v0 + v1 * v1 + v2 * v2;
    #pragma unroll
    for (int off = 16; off; off >>= 1) {
        s  += __shfl_xor_sync(0xffffffffu, s, off);
        sq += __shfl_xor_sync(0xffffffffu, sq, off);
    }
    __shared__ float rs[8], rq[8];
    __shared__ float s_mean, s_rstd;
    int wid = t >> 5;
    if ((t & 31) == 0) { rs[wid] = s; rq[wid] = sq; }
    __syncthreads();
    if (t == 0) {
        float S = 0.f, Q = 0.f;
        #pragma unroll
        for (int i = 0; i < 8; i++) { S += rs[i]; Q += rq[i]; }
        float mean = S * (1.f / EMB);
        s_mean = mean;
        s_rstd = rsqrtf(Q * (1.f / EMB) - mean * mean + 1e-5f);
    }
    __syncthreads();
    float mean = s_mean, rstd = s_rstd;
    float* orow = o + (size_t)row * EMB;
    orow[t]       = (v0 - mean) * rstd * w[t]       + bb[t];
    orow[t + 256] = (v1 - mean) * rstd * w[t + 256] + bb[t + 256];
    orow[t + 512] = (v2 - mean) * rstd * w[t + 512] + bb[t + 512];
}

// --------------------------------------------- transpose + fp16 hi/lo split
__global__ void transpose_split_kernel(const float* __restrict__ in,
                                       __half* __restrict__ oh,
                                       __half* __restrict__ ol,
                                       int K, int N) {
    __shared__ float t[32][33];
    const size_t off = (size_t)blockIdx.z * K * N;
    int n0 = blockIdx.x * 32, k0 = blockIdx.y * 32;
    int x = threadIdx.x, y = threadIdx.y;
    #pragma unroll
    for (int i = 0; i < 32; i += 8)
        t[y + i][x] = in[off + (size_t)(k0 + y + i) * N + n0 + x];
    __syncthreads();
    #pragma unroll
    for (int i = 0; i < 32; i += 8) {
        float v = t[x][y + i];
        __half h = __float2half_rn(v);
        __half l = __float2half_rn(v - __half2float(h));
        size_t o = off + (size_t)(n0 + y + i) * K + k0 + x;
        oh[o] = h; ol[o] = l;
    }
}

// ------------------------------------------------- elementwise fp16 split
__global__ void split_kernel(const float* __restrict__ in,
                             __half* __restrict__ oh,
                             __half* __restrict__ ol, int n) {
    int i = blockIdx.x * blockDim.x + threadIdx.x;
    if (i >= n) return;
    float v = in[i];
    __half h = __float2half_rn(v);
    __half l = __float2half_rn(v - __half2float(h));
    oh[i] = h; ol[i] = l;
}

// ------------------------------------------- fp16 B-split-2 mma.sync GEMM
// C[M,N] = A[M,K] @ B[N,K]^T, A rounded fp16 at staging, B = Bh + Bl exact.
// EPI: 0 = +bias, 1 = +bias+residual, 2 = +bias+gelu, 3 = plain (N guarded)
// CTA 128x128x32, 8 warps as 2(m)x4(n), warp tile 64x32.
// Fragments via ldmatrix; B staged via cp.async (zero-fill for N tail).
#define BP 40                       // smem pitch in halves (80 B rows)
#define BUFH (128 * BP)             // halves per buffer
template <int EPI>
__global__ void __launch_bounds__(256, 2)
gemm_f16(const float* __restrict__ A,
         const __half* __restrict__ Bh, const __half* __restrict__ Bl,
         const float* __restrict__ bias, const float* __restrict__ res,
         float* __restrict__ C, int M, int N, int K) {
    extern __shared__ __half sm[];
    __half* sA  = sm;                 // 2 x BUFH
    __half* sBh = sm + 2 * BUFH;
    __half* sBl = sm + 4 * BUFH;
    const uint32_t uA  = (uint32_t)__cvta_generic_to_shared(sA);
    const uint32_t uBh = (uint32_t)__cvta_generic_to_shared(sBh);
    const uint32_t uBl = (uint32_t)__cvta_generic_to_shared(sBl);

    const int tid  = threadIdx.x;
    const int wid  = tid >> 5;
    const int lane = tid & 31;
    const int grp  = lane >> 2;
    const int tig  = lane & 3;
    const int bm = blockIdx.y * 128;
    const int bn = blockIdx.x * 128;
    const int wm0 = (wid & 1) * 64;
    const int wn0 = (wid >> 1) * 32;

    // A staging coords: each thread converts/stores 16 floats of one row-half
    const int row16  = tid >> 1;
    const int half16 = (tid & 1) * 16;

    // ldmatrix lane-address components
    const int a_row = (lane & 15);
    const int a_k   = (lane >> 4) << 3;
    const int b_row = (lane & 7) + ((lane >> 4) << 3);
    const int b_k   = ((lane >> 3) & 1) << 3;

    float cf[4][4][4];
    #pragma unroll
    for (int i = 0; i < 4; i++)
        #pragma unroll
        for (int j = 0; j < 4; j++)
            #pragma unroll
            for (int r = 0; r < 4; r++) cf[i][j][r] = 0.f;

    const int KC = K >> 5;
    float4 av[4];

    // ---- B cp.async stage helper (4 x 16B per thread per chunk) ----
    auto stageB = [&](int k0, int p) {
        #pragma unroll
        for (int ps = 0; ps < 2; ps++) {
            int s = tid + ps * 256;
            int row = s >> 2;
            int c16 = (s & 3) * 8;
            int gr = bn + row;
            int sz = 16;
            if (EPI == 3 && gr >= N) { gr = 0; sz = 0; }
            const __half* sh = Bh + (size_t)gr * K + k0 + c16;
            const __half* sl = Bl + (size_t)gr * K + k0 + c16;
            uint32_t doff = (uint32_t)(p * BUFH + row * BP + c16) * 2;
            cpa16(uBh + doff, sh, sz);
            cpa16(uBl + doff, sl, sz);
        }
        CP_COMMIT();
    };

    // ---- prologue: A chunk 0 into regs, B chunk 0 via cp.async ----
    {
        const float* ap = A + (size_t)(bm + row16) * K + half16;
        #pragma unroll
        for (int i = 0; i < 4; i++) av[i] = *(const float4*)(ap + i * 4);
        stageB(0, 0);
    }

    for (int c = 0; c < KC; c++) {
        const int p = c & 1;
        // store staged A into smem buffer p
        {
            __half* dA = sA + p * BUFH + row16 * BP + half16;
            uint32_t w0 = pack_f16(av[0].x, av[0].y);
            uint32_t w1 = pack_f16(av[0].z, av[0].w);
            uint32_t w2 = pack_f16(av[1].x, av[1].y);
            uint32_t w3 = pack_f16(av[1].z, av[1].w);
            uint32_t w4 = pack_f16(av[2].x, av[2].y);
            uint32_t w5 = pack_f16(av[2].z, av[2].w);
            uint32_t w6 = pack_f16(av[3].x, av[3].y);
            uint32_t w7 = pack_f16(av[3].z, av[3].w);
            *(uint4*)dA       = make_uint4(w0, w1, w2, w3);
            *(uint4*)(dA + 8) = make_uint4(w4, w5, w6, w7);
        }
        CP_WAIT0();          // B chunk c resident
        __syncthreads();

        // prefetch chunk c+1
        if (c + 1 < KC) {
            const int k0 = (c + 1) << 5;
            const float* ap = A + (size_t)(bm + row16) * K + k0 + half16;
            #pragma unroll
            for (int i = 0; i < 4; i++) av[i] = *(const float4*)(ap + i * 4);
            stageB(k0, 1 - p);
        }

        // ---- mma over 2 k-steps of 16 ----
        const uint32_t bufA  = uA  + (uint32_t)(p * BUFH) * 2;
        const uint32_t bufBh = uBh + (uint32_t)(p * BUFH) * 2;
        const uint32_t bufBl = uBl + (uint32_t)(p * BUFH) * 2;
        #pragma unroll
        for (int ks = 0; ks < 2; ks++) {
            const int k0 = ks * 16;
            uint32_t bh[4][2], bl[4][2];
            uint32_t bo = (uint32_t)((wn0 + b_row) * BP + k0 + b_k) * 2;
            ldmx4(bh[0][0], bh[0][1], bh[1][0], bh[1][1], bufBh + bo);
            ldmx4(bh[2][0], bh[2][1], bh[3][0], bh[3][1], bufBh + bo + 16 * BP * 2);
            ldmx4(bl[0][0], bl[0][1], bl[1][0], bl[1][1], bufBl + bo);
            ldmx4(bl[2][0], bl[2][1], bl[3][0], bl[3][1], bufBl + bo + 16 * BP * 2);
            #pragma unroll
            for (int mt = 0; mt < 4; mt++) {
                uint32_t a[4];
                uint32_t ao = (uint32_t)((wm0 + mt * 16 + a_row) * BP + k0 + a_k) * 2;
                ldmx4(a[0], a[1], a[2], a[3], bufA + ao);
                #pragma unroll
                for (int nt = 0; nt < 4; nt++) {
                    mma_f16(cf[mt][nt], a, bh[nt]);
                    mma_f16(cf[mt][nt], a, bl[nt]);
                }
            }
        }
        __syncthreads();
    }

    // ---------------- epilogue ----------------
    #pragma unroll
    for (int mt = 0; mt < 4; mt++) {
        #pragma unroll
        for (int half = 0; half < 2; half++) {
            const int row = bm + wm0 + mt * 16 + grp + half * 8;
            #pragma unroll
            for (int nt = 0; nt < 4; nt++) {
                const int col = bn + wn0 + nt * 8 + 2 * tig;
                float v0 = cf[mt][nt][half * 2 + 0];
                float v1 = cf[mt][nt][half * 2 + 1];
                if (EPI == 3) {
                    if (col < N)     C[(size_t)row * N + col]     = v0;
                    if (col + 1 < N) C[(size_t)row * N + col + 1] = v1;
                } else {
                    v0 += bias[col];
                    v1 += bias[col + 1];
                    if (EPI == 1) {
                        const float* rp = res + (size_t)row * N + col;
                        v0 += rp[0]; v1 += rp[1];
                    }
                    if (EPI == 2) { v0 = gelu_f(v0); v1 = gelu_f(v1); }
                    *(float2*)(C + (size_t)row * N + col) = make_float2(v0, v1);
                }
            }
        }
    }
}

// ---------------------------------------------------- fused flash attention
#define AP 68
__global__ void __launch_bounds__(256)
attn_kernel(const float* __restrict__ qkv, float* __restrict__ y) {
    extern __shared__ float smf[];
    float* sQT = smf;
    float* sKT = smf + 64 * AP;
    float* sV  = smf + 2 * 64 * AP;
    float* sS  = smf + 3 * 64 * AP;

    const int tq = blockIdx.x, h = blockIdx.y, b = blockIdx.z;
    const int t  = threadIdx.x;
    const int r0 = (t >> 4) << 2;
    const int c0 = (t & 15) << 2;
    const float scale = 0.036084391824351615f;  // 1/sqrt(768)

    const size_t qbase = ((size_t)b * SEQ + (size_t)tq * 64) * QKVDIM + h * HDIM;
    #pragma unroll
    for (int it = 0; it < 4; it++) {
        int i   = t + it * 256;
        int row = (i >> 2) & 63;
        int kq  = (i & 3) | ((i >> 8) << 2);
        float4 v = *(const float4*)(qkv + qbase + (size_t)row * QKVDIM + kq * 4);
        int kk = kq * 4;
        sQT[(kk + 0) * AP + row] = v.x; sQT[(kk + 1) * AP + row] = v.y;
        sQT[(kk + 2) * AP + row] = v.z; sQT[(kk + 3) * AP + row] = v.w;
    }

    float m[4], l[4], acc[4][4];
    #pragma unroll
    for (int i = 0; i < 4; i++) {
        m[i] = -1e30f; l[i] = 0.f;
        #pragma unroll
        for (int j = 0; j < 4; j++) acc[i][j] = 0.f;
    }

    for (int ks = 0; ks <= tq; ks++) {
        __syncthreads();
        const size_t kbase = ((size_t)b * SEQ + (size_t)ks * 64) * QKVDIM + h * HDIM + EMB;
        #pragma unroll
        for (int it = 0; it < 4; it++) {
            int i   = t + it * 256;
            int row = (i >> 2) & 63;
            int kq  = (i & 3) | ((i >> 8) << 2);
            float4 kv = *(const float4*)(qkv + kbase + (size_t)row * QKVDIM + kq * 4);
            float4 vv = *(const float4*)(qkv + kbase + EMB + (size_t)row * QKVDIM + kq * 4);
            int kk = kq * 4;
            sKT[(kk + 0) * AP + row] = kv.x; sKT[(kk + 1) * AP + row] = kv.y;
            sKT[(kk + 2) * AP + row] = kv.z; sKT[(kk + 3) * AP + row] = kv.w;
            *(float4*)&sV[row * AP + kk] = vv;
        }
        __syncthreads();

        float sc[4][4];
        #pragma unroll
        for (int i = 0; i < 4; i++)
            #pragma unroll
            for (int j = 0; j < 4; j++) sc[i][j] = 0.f;

        #pragma unroll 16
        for (int k = 0; k < 64; k++) {
            float4 qv = *(const float4*)&sQT[k * AP + r0];
            float4 kv = *(const float4*)&sKT[k * AP + c0];
            float qa[4] = {qv.x, qv.y, qv.z, qv.w};
            float ka[4] = {kv.x, kv.y, kv.z, kv.w};
            #pragma unroll
            for (int i = 0; i < 4; i++)
                #pragma unroll
                for (int j = 0; j < 4; j++)
                    sc[i][j] += qa[i] * ka[j];
        }

        const bool diag = (ks == tq);
        #pragma unroll
        for (int i = 0; i < 4; i++)
            #pragma unroll
            for (int j = 0; j < 4; j++) {
                float v = sc[i][j] * scale;
                if (diag && (c0 + j > r0 + i)) v = -1e30f;
                sc[i][j] = v;
            }

        #pragma unroll
        for (int i = 0; i < 4; i++) {
            float tmax = fmaxf(fmaxf(sc[i][0], sc[i][1]), fmaxf(sc[i][2], sc[i][3]));
            #pragma unroll
            for (int off = 1; off < 16; off <<= 1)
                tmax = fmaxf(tmax, __shfl_xor_sync(0xffffffffu, tmax, off));
            float nm   = fmaxf(m[i], tmax);
            float corr = __expf(m[i] - nm);
            m[i] = nm;
            float rs = 0.f;
            #pragma unroll
            for (int j = 0; j < 4; j++) {
                float p = __expf(sc[i][j] - nm);
                sc[i][j] = p;
                rs += p;
            }
            #pragma unroll
            for (int off = 1; off < 16; off <<= 1)
                rs += __shfl_xor_sync(0xffffffffu, rs, off);
            l[i] = l[i] * corr + rs;
            acc[i][0] *= corr; acc[i][1] *= corr;
            acc[i][2] *= corr; acc[i][3] *= corr;
            *(float4*)&sS[(r0 + i) * AP + c0] =
                make_float4(sc[i][0], sc[i][1], sc[i][2], sc[i][3]);
        }
        __syncthreads();

        // ---- PV: acc += P @ V  (float4 P loads, 4-column V blocks) ----
        #pragma unroll 4
        for (int cb = 0; cb < 64; cb += 4) {
            float4 v0 = *(const float4*)&sV[(cb + 0) * AP + c0];
            float4 v1 = *(const float4*)&sV[(cb + 1) * AP + c0];
            float4 v2 = *(const float4*)&sV[(cb + 2) * AP + c0];
            float4 v3 = *(const float4*)&sV[(cb + 3) * AP + c0];
            #pragma unroll
            for (int i = 0; i < 4; i++) {
                float4 pv = *(const float4*)&sS[(r0 + i) * AP + cb];
                acc[i][0] += pv.x * v0.x + pv.y * v1.x + pv.z * v2.x + pv.w * v3.x;
                acc[i][1] += pv.x * v0.y + pv.y * v1.y + pv.z * v2.y + pv.w * v3.y;
                acc[i][2] += pv.x * v0.z + pv.y * v1.z + pv.z * v2.z + pv.w * v3.z;
                acc[i][3] += pv.x * v0.w + pv.y * v1.w + pv.z * v2.w + pv.w * v3.w;
            }
        }
    }

    #pragma unroll
    for (int i = 0; i < 4; i++) {
        float inv = 1.f / l[i];
        float4 o = make_float4(acc[i][0] * inv, acc[i][1] * inv,
                               acc[i][2] * inv, acc[i][3] * inv);
        *(float4*)(y + ((size_t)b * SEQ + (size_t)tq * 64 + r0 + i) * EMB
                     + h * HDIM + c0) = o;
    }
}

// -------------------------------------------------------------------- launch
extern "C" void kernel_launch(void* const* d_in, const int* in_sizes, int n_in,
                              void* d_out, int out_size) {
    const int*   tokens = (const int*)  d_in[0];
    const float* wte    = (const float*)d_in[1];
    const float* wpe    = (const float*)d_in[2];
    const float* ln1w   = (const float*)d_in[3];
    const float* ln1b   = (const float*)d_in[4];
    const float* qkvw   = (const float*)d_in[5];
    const float* qkvb   = (const float*)d_in[6];
    const float* atpw   = (const float*)d_in[7];
    const float* atpb   = (const float*)d_in[8];
    const float* ln2w   = (const float*)d_in[9];
    const float* ln2b   = (const float*)d_in[10];
    const float* fcw    = (const float*)d_in[11];
    const float* fcb    = (const float*)d_in[12];
    const float* fpw    = (const float*)d_in[13];
    const float* fpb    = (const float*)d_in[14];
    const float* lnfw   = (const float*)d_in[15];
    const float* lnfb   = (const float*)d_in[16];
    const float* lmw    = (const float*)d_in[17];
    float* out = (float*)d_out;

    float *px, *pa, *pqkv, *py, *pm;
    __half *qh, *ql, *ah, *al, *fh, *fl, *ph, *pl, *lh, *ll;
    cudaGetSymbolAddress((void**)&px,   g_x);
    cudaGetSymbolAddress((void**)&pa,   g_a);
    cudaGetSymbolAddress((void**)&pqkv, g_qkv);
    cudaGetSymbolAddress((void**)&py,   g_y);
    cudaGetSymbolAddress((void**)&pm,   g_m);
    cudaGetSymbolAddress((void**)&qh, g_qkvH); cudaGetSymbolAddress((void**)&ql, g_qkvL);
    cudaGetSymbolAddress((void**)&ah, g_atpH); cudaGetSymbolAddress((void**)&al, g_atpL);
    cudaGetSymbolAddress((void**)&fh, g_fcH);  cudaGetSymbolAddress((void**)&fl, g_fcL);
    cudaGetSymbolAddress((void**)&ph, g_fpH);  cudaGetSymbolAddress((void**)&pl, g_fpL);
    cudaGetSymbolAddress((void**)&lh, g_lmH);  cudaGetSymbolAddress((void**)&ll, g_lmL);

    const int gsmem = 6 * BUFH * sizeof(__half);  // 61440
    cudaFuncSetAttribute(gemm_f16<0>, cudaFuncAttributeMaxDynamicSharedMemorySize, gsmem);
    cudaFuncSetAttribute(gemm_f16<1>, cudaFuncAttributeMaxDynamicSharedMemorySize, gsmem);
    cudaFuncSetAttribute(gemm_f16<2>, cudaFuncAttributeMaxDynamicSharedMemorySize, gsmem);
    cudaFuncSetAttribute(gemm_f16<3>, cudaFuncAttributeMaxDynamicSharedMemorySize, gsmem);

    const size_t attn_smem = (size_t)4 * 64 * AP * sizeof(float);
    cudaFuncSetAttribute(attn_kernel,
                         cudaFuncAttributeMaxDynamicSharedMemorySize,
                         (int)attn_smem);

    // ---- weight transpose + fp16 split (per replay; deterministic) ----
    dim3 tb(32, 8);
    transpose_split_kernel<<<dim3(QKVDIM / 32, EMB / 32, NLAYER), tb>>>(qkvw, qh, ql, EMB, QKVDIM);
    transpose_split_kernel<<<dim3(EMB / 32,    EMB / 32, NLAYER), tb>>>(atpw, ah, al, EMB, EMB);
    transpose_split_kernel<<<dim3(FFDIM / 32,  EMB / 32, NLAYER), tb>>>(fcw,  fh, fl, EMB, FFDIM);
    transpose_split_kernel<<<dim3(EMB / 32,  FFDIM / 32, NLAYER), tb>>>(fpw,  ph, pl, FFDIM, EMB);
    split_kernel<<<(VOCAB * EMB + 255) / 256, 256>>>(lmw, lh, ll, VOCAB * EMB);

    embed_kernel<<<(TOKENS * EMB + 255) / 256, 256>>>(tokens, wte, wpe, px);

    for (int i = 0; i < NLAYER; i++) {
        ln_kernel<<<TOKENS, 256>>>(px, ln1w + i * EMB, ln1b + i * EMB, pa);

        gemm_f16<0><<<dim3(QKVDIM / 128, TOKENS / 128), 256, gsmem>>>(
            pa, qh + (size_t)i * QKVDIM * EMB, ql + (size_t)i * QKVDIM * EMB,
            qkvb + i * QKVDIM, nullptr, pqkv, TOKENS, QKVDIM, EMB);

        attn_kernel<<<dim3(SEQ / 64, NHEAD, NBATCH), 256, attn_smem>>>(pqkv, py);

        gemm_f16<1><<<dim3(EMB / 128, TOKENS / 128), 256, gsmem>>>(
            py, ah + (size_t)i * EMB * EMB, al + (size_t)i * EMB * EMB,
            atpb + i * EMB, px, px, TOKENS, EMB, EMB);

        ln_kernel<<<TOKENS, 256>>>(px, ln2w + i * EMB, ln2b + i * EMB, pa);

        gemm_f16<2><<<dim3(FFDIM / 128, TOKENS / 128), 256, gsmem>>>(
            pa, fh + (size_t)i * FFDIM * EMB, fl + (size_t)i * FFDIM * EMB,
            fcb + i * FFDIM, nullptr, pm, TOKENS, FFDIM, EMB);

        gemm_f16<1><<<dim3(EMB / 128, TOKENS / 128), 256, gsmem>>>(
            pm, ph + (size_t)i * EMB * FFDIM, pl + (size_t)i * EMB * FFDIM,
            fpb + i * EMB, px, px, TOKENS, EMB, FFDIM);
    }

    ln_kernel<<<TOKENS, 256>>>(px, lnfw, lnfb, pa);

    gemm_f16<3><<<dim3((VOCAB + 127) / 128, TOKENS / 128), 256, gsmem>>>(
        pa, lh, ll, nullptr, nullptr, out, TOKENS, VOCAB, EMB);
}

// round 7
// speedup vs baseline: 3.1156x; 1.1992x over previous
#include <cuda_runtime.h>
#include <cuda_fp16.h>
#include <math.h>
#include <stdint.h>

#define TOKENS 4096
#define EMB    768
#define NLAYER 12
#define NHEAD  12
#define HDIM   64
#define SEQ    1024
#define NBATCH 4
#define VOCAB  50257
#define FFDIM  3072
#define QKVDIM 2304

// -------------------- scratch (static device globals; no allocation) --------
__device__ float g_x  [TOKENS * EMB];
__device__ float g_a  [TOKENS * EMB];
__device__ float g_qkv[TOKENS * QKVDIM];
__device__ float g_y  [TOKENS * EMB];
__device__ float g_m  [TOKENS * FFDIM];
__device__ __half g_qkvH[(size_t)NLAYER * QKVDIM * EMB];
__device__ __half g_qkvL[(size_t)NLAYER * QKVDIM * EMB];
__device__ __half g_atpH[(size_t)NLAYER * EMB * EMB];
__device__ __half g_atpL[(size_t)NLAYER * EMB * EMB];
__device__ __half g_fcH [(size_t)NLAYER * FFDIM * EMB];
__device__ __half g_fcL [(size_t)NLAYER * FFDIM * EMB];
__device__ __half g_fpH [(size_t)NLAYER * EMB * FFDIM];
__device__ __half g_fpL [(size_t)NLAYER * EMB * FFDIM];
__device__ __half g_lmH [(size_t)VOCAB * EMB];
__device__ __half g_lmL [(size_t)VOCAB * EMB];

// ------------------------------------------------------------- helpers
__device__ __forceinline__ float gelu_f(float x) {
    float x3 = x * x * x;
    return 0.5f * x * (1.f + tanhf(0.7978845608028654f * (x + 0.044715f * x3)));
}
__device__ __forceinline__ uint32_t pack_f16(float x0, float x1) {
    uint32_t u;
    asm("{.reg .b16 l,h; cvt.rn.f16.f32 l,%1; cvt.rn.f16.f32 h,%2; mov.b32 %0,{l,h};}"
        : "=r"(u) : "f"(x0), "f"(x1));
    return u;
}
__device__ __forceinline__ void mma_f16(float* c, const uint32_t* a, const uint32_t* b) {
    asm volatile(
        "mma.sync.aligned.m16n8k16.row.col.f32.f16.f16.f32 "
        "{%0,%1,%2,%3}, {%4,%5,%6,%7}, {%8,%9}, {%0,%1,%2,%3};"
        : "+f"(c[0]), "+f"(c[1]), "+f"(c[2]), "+f"(c[3])
        : "r"(a[0]), "r"(a[1]), "r"(a[2]), "r"(a[3]), "r"(b[0]), "r"(b[1]));
}
__device__ __forceinline__ void ldmx4(uint32_t& r0, uint32_t& r1,
                                      uint32_t& r2, uint32_t& r3, uint32_t addr) {
    asm volatile("ldmatrix.sync.aligned.m8n8.x4.shared.b16 {%0,%1,%2,%3}, [%4];"
                 : "=r"(r0), "=r"(r1), "=r"(r2), "=r"(r3) : "r"(addr));
}
__device__ __forceinline__ void ldmx4t(uint32_t& r0, uint32_t& r1,
                                       uint32_t& r2, uint32_t& r3, uint32_t addr) {
    asm volatile("ldmatrix.sync.aligned.m8n8.x4.trans.shared.b16 {%0,%1,%2,%3}, [%4];"
                 : "=r"(r0), "=r"(r1), "=r"(r2), "=r"(r3) : "r"(addr));
}
__device__ __forceinline__ void cpa16(uint32_t dst, const void* src, int srcsz) {
    asm volatile("cp.async.ca.shared.global [%0], [%1], 16, %2;"
                 :: "r"(dst), "l"(src), "r"(srcsz) : "memory");
}
#define CP_COMMIT() asm volatile("cp.async.commit_group;" ::: "memory")
#define CP_WAIT0()  asm volatile("cp.async.wait_group 0;" ::: "memory")

// ---------------------------------------------------------------- embedding
__global__ void embed_kernel(const int* __restrict__ tok,
                             const float* __restrict__ wte,
                             const float* __restrict__ wpe,
                             float* __restrict__ x) {
    int idx = blockIdx.x * blockDim.x + threadIdx.x;
    if (idx >= TOKENS * EMB) return;
    int t = idx / EMB;
    int e = idx - t * EMB;
    x[idx] = wte[(size_t)tok[t] * EMB + e] + wpe[e];
}

// ---------------------------------------------------------------- layernorm
__global__ void ln_kernel(const float* __restrict__ x,
                          const float* __restrict__ w,
                          const float* __restrict__ bb,
                          float* __restrict__ o) {
    int row = blockIdx.x;
    const float* xr = x + (size_t)row * EMB;
    int t = threadIdx.x;
    float v0 = xr[t], v1 = xr[t + 256], v2 = xr[t + 512];
    float s  = v0 + v1 + v2;
    float sq = v0 * v0 + v1 * v1 + v2 * v2;
    #pragma unroll
    for (int off = 16; off; off >>= 1) {
        s  += __shfl_xor_sync(0xffffffffu, s, off);
        sq += __shfl_xor_sync(0xffffffffu, sq, off);
    }
    __shared__ float rs[8], rq[8];
    __shared__ float s_mean, s_rstd;
    int wid = t >> 5;
    if ((t & 31) == 0) { rs[wid] = s; rq[wid] = sq; }
    __syncthreads();
    if (t == 0) {
        float S = 0.f, Q = 0.f;
        #pragma unroll
        for (int i = 0; i < 8; i++) { S += rs[i]; Q += rq[i]; }
        float mean = S * (1.f / EMB);
        s_mean = mean;
        s_rstd = rsqrtf(Q * (1.f / EMB) - mean * mean + 1e-5f);
    }
    __syncthreads();
    float mean = s_mean, rstd = s_rstd;
    float* orow = o + (size_t)row * EMB;
    orow[t]       = (v0 - mean) * rstd * w[t]       + bb[t];
    orow[t + 256] = (v1 - mean) * rstd * w[t + 256] + bb[t + 256];
    orow[t + 512] = (v2 - mean) * rstd * w[t + 512] + bb[t + 512];
}

// --------------------------------------------- transpose + fp16 hi/lo split
__global__ void transpose_split_kernel(const float* __restrict__ in,
                                       __half* __restrict__ oh,
                                       __half* __restrict__ ol,
                                       int K, int N) {
    __shared__ float t[32][33];
    const size_t off = (size_t)blockIdx.z * K * N;
    int n0 = blockIdx.x * 32, k0 = blockIdx.y * 32;
    int x = threadIdx.x, y = threadIdx.y;
    #pragma unroll
    for (int i = 0; i < 32; i += 8)
        t[y + i][x] = in[off + (size_t)(k0 + y + i) * N + n0 + x];
    __syncthreads();
    #pragma unroll
    for (int i = 0; i < 32; i += 8) {
        float v = t[x][y + i];
        __half h = __float2half_rn(v);
        __half l = __float2half_rn(v - __half2float(h));
        size_t o = off + (size_t)(n0 + y + i) * K + k0 + x;
        oh[o] = h; ol[o] = l;
    }
}

// ------------------------------------------------- elementwise fp16 split
__global__ void split_kernel(const float* __restrict__ in,
                             __half* __restrict__ oh,
                             __half* __restrict__ ol, int n) {
    int i = blockIdx.x * blockDim.x + threadIdx.x;
    if (i >= n) return;
    float v = in[i];
    __half h = __float2half_rn(v);
    __half l = __float2half_rn(v - __half2float(h));
    oh[i] = h; ol[i] = l;
}

// ------------------------------------------- fp16 B-split-2 mma.sync GEMM
#define BP 40
#define BUFH (128 * BP)
template <int EPI>
__global__ void __launch_bounds__(256, 2)
gemm_f16(const float* __restrict__ A,
         const __half* __restrict__ Bh, const __half* __restrict__ Bl,
         const float* __restrict__ bias, const float* __restrict__ res,
         float* __restrict__ C, int M, int N, int K) {
    extern __shared__ __half sm[];
    __half* sA  = sm;
    __half* sBh = sm + 2 * BUFH;
    __half* sBl = sm + 4 * BUFH;
    const uint32_t uA  = (uint32_t)__cvta_generic_to_shared(sA);
    const uint32_t uBh = (uint32_t)__cvta_generic_to_shared(sBh);
    const uint32_t uBl = (uint32_t)__cvta_generic_to_shared(sBl);

    const int tid  = threadIdx.x;
    const int wid  = tid >> 5;
    const int lane = tid & 31;
    const int grp  = lane >> 2;
    const int tig  = lane & 3;
    const int bm = blockIdx.y * 128;
    const int bn = blockIdx.x * 128;
    const int wm0 = (wid & 1) * 64;
    const int wn0 = (wid >> 1) * 32;

    const int row16  = tid >> 1;
    const int half16 = (tid & 1) * 16;

    const int a_row = (lane & 15);
    const int a_k   = (lane >> 4) << 3;
    const int b_row = (lane & 7) + ((lane >> 4) << 3);
    const int b_k   = ((lane >> 3) & 1) << 3;

    float cf[4][4][4];
    #pragma unroll
    for (int i = 0; i < 4; i++)
        #pragma unroll
        for (int j = 0; j < 4; j++)
            #pragma unroll
            for (int r = 0; r < 4; r++) cf[i][j][r] = 0.f;

    const int KC = K >> 5;
    float4 av[4];

    auto stageB = [&](int k0, int p) {
        #pragma unroll
        for (int ps = 0; ps < 2; ps++) {
            int s = tid + ps * 256;
            int row = s >> 2;
            int c16 = (s & 3) * 8;
            int gr = bn + row;
            int sz = 16;
            if (EPI == 3 && gr >= N) { gr = 0; sz = 0; }
            const __half* sh = Bh + (size_t)gr * K + k0 + c16;
            const __half* sl = Bl + (size_t)gr * K + k0 + c16;
            uint32_t doff = (uint32_t)(p * BUFH + row * BP + c16) * 2;
            cpa16(uBh + doff, sh, sz);
            cpa16(uBl + doff, sl, sz);
        }
        CP_COMMIT();
    };

    {
        const float* ap = A + (size_t)(bm + row16) * K + half16;
        #pragma unroll
        for (int i = 0; i < 4; i++) av[i] = *(const float4*)(ap + i * 4);
        stageB(0, 0);
    }

    for (int c = 0; c < KC; c++) {
        const int p = c & 1;
        {
            __half* dA = sA + p * BUFH + row16 * BP + half16;
            uint32_t w0 = pack_f16(av[0].x, av[0].y);
            uint32_t w1 = pack_f16(av[0].z, av[0].w);
            uint32_t w2 = pack_f16(av[1].x, av[1].y);
            uint32_t w3 = pack_f16(av[1].z, av[1].w);
            uint32_t w4 = pack_f16(av[2].x, av[2].y);
            uint32_t w5 = pack_f16(av[2].z, av[2].w);
            uint32_t w6 = pack_f16(av[3].x, av[3].y);
            uint32_t w7 = pack_f16(av[3].z, av[3].w);
            *(uint4*)dA       = make_uint4(w0, w1, w2, w3);
            *(uint4*)(dA + 8) = make_uint4(w4, w5, w6, w7);
        }
        CP_WAIT0();
        __syncthreads();

        if (c + 1 < KC) {
            const int k0 = (c + 1) << 5;
            const float* ap = A + (size_t)(bm + row16) * K + k0 + half16;
            #pragma unroll
            for (int i = 0; i < 4; i++) av[i] = *(const float4*)(ap + i * 4);
            stageB(k0, 1 - p);
        }

        const uint32_t bufA  = uA  + (uint32_t)(p * BUFH) * 2;
        const uint32_t bufBh = uBh + (uint32_t)(p * BUFH) * 2;
        const uint32_t bufBl = uBl + (uint32_t)(p * BUFH) * 2;
        #pragma unroll
        for (int ks = 0; ks < 2; ks++) {
            const int k0 = ks * 16;
            uint32_t bh[4][2], bl[4][2];
            uint32_t bo = (uint32_t)((wn0 + b_row) * BP + k0 + b_k) * 2;
            ldmx4(bh[0][0], bh[0][1], bh[1][0], bh[1][1], bufBh + bo);
            ldmx4(bh[2][0], bh[2][1], bh[3][0], bh[3][1], bufBh + bo + 16 * BP * 2);
            ldmx4(bl[0][0], bl[0][1], bl[1][0], bl[1][1], bufBl + bo);
            ldmx4(bl[2][0], bl[2][1], bl[3][0], bl[3][1], bufBl + bo + 16 * BP * 2);
            #pragma unroll
            for (int mt = 0; mt < 4; mt++) {
                uint32_t a[4];
                uint32_t ao = (uint32_t)((wm0 + mt * 16 + a_row) * BP + k0 + a_k) * 2;
                ldmx4(a[0], a[1], a[2], a[3], bufA + ao);
                #pragma unroll
                for (int nt = 0; nt < 4; nt++) {
                    mma_f16(cf[mt][nt], a, bh[nt]);
                    mma_f16(cf[mt][nt], a, bl[nt]);
                }
            }
        }
        __syncthreads();
    }

    #pragma unroll
    for (int mt = 0; mt < 4; mt++) {
        #pragma unroll
        for (int half = 0; half < 2; half++) {
            const int row = bm + wm0 + mt * 16 + grp + half * 8;
            #pragma unroll
            for (int nt = 0; nt < 4; nt++) {
                const int col = bn + wn0 + nt * 8 + 2 * tig;
                float v0 = cf[mt][nt][half * 2 + 0];
                float v1 = cf[mt][nt][half * 2 + 1];
                if (EPI == 3) {
                    if (col < N)     C[(size_t)row * N + col]     = v0;
                    if (col + 1 < N) C[(size_t)row * N + col + 1] = v1;
                } else {
                    v0 += bias[col];
                    v1 += bias[col + 1];
                    if (EPI == 1) {
                        const float* rp = res + (size_t)row * N + col;
                        v0 += rp[0]; v1 += rp[1];
                    }
                    if (EPI == 2) { v0 = gelu_f(v0); v1 = gelu_f(v1); }
                    *(float2*)(C + (size_t)row * N + col) = make_float2(v0, v1);
                }
            }
        }
    }
}

// ------------------------------------ fp16 mma.sync flash attention
// Block: 128 threads (4 warps), one 64-row Q tile x (head, batch).
// Warp w owns Q rows 16w..16w+15. Q split-2 x K-hi; P fp16 x V split-2.
#define APT 72                       // half pitch (144 B rows)
#define ATILE (64 * APT)
__global__ void __launch_bounds__(128)
attn_mma(const float* __restrict__ qkv, float* __restrict__ y) {
    extern __shared__ __half sh[];
    __half* sQh = sh;                // Q hi   [64][APT]
    __half* sQl = sh + ATILE;        // Q lo
    __half* sKh = sh + 2 * ATILE;    // K hi   [kpos][d]
    __half* sVh = sh + 3 * ATILE;    // V hi   [kpos][d]
    __half* sVl = sh + 4 * ATILE;    // V lo
    const uint32_t uQh = (uint32_t)__cvta_generic_to_shared(sQh);
    const uint32_t uQl = (uint32_t)__cvta_generic_to_shared(sQl);
    const uint32_t uKh = (uint32_t)__cvta_generic_to_shared(sKh);
    const uint32_t uVh = (uint32_t)__cvta_generic_to_shared(sVh);
    const uint32_t uVl = (uint32_t)__cvta_generic_to_shared(sVl);

    const int tq = blockIdx.x, h = blockIdx.y, b = blockIdx.z;
    const int tid  = threadIdx.x;
    const int wid  = tid >> 5;
    const int lane = tid & 31;
    const int grp  = lane >> 2;
    const int tig  = lane & 3;
    const float scale = 0.036084391824351615f;  // 1/sqrt(768)

    // staging coords: row = tid>>1, 32-col half = (tid&1)*32
    const int srow = tid >> 1;
    const int scol = (tid & 1) * 32;

    // ldmatrix coords
    const int a_row = lane & 15;
    const int a_k   = (lane >> 4) << 3;
    const int b_row = (lane & 7) + ((lane >> 4) << 3);
    const int b_k   = ((lane >> 3) & 1) << 3;

    // ---- stage Q tile (fp32 -> fp16 hi/lo) ----
    {
        const float* qp = qkv + ((size_t)b * SEQ + (size_t)tq * 64 + srow) * QKVDIM
                        + h * HDIM + scol;
        __half* dh = sQh + srow * APT + scol;
        __half* dl = sQl + srow * APT + scol;
        #pragma unroll
        for (int i = 0; i < 8; i++) {
            float4 v = *(const float4*)(qp + i * 4);
            uint32_t h0 = pack_f16(v.x, v.y), h1 = pack_f16(v.z, v.w);
            __half2 p0 = *(__half2*)&h0, p1 = *(__half2*)&h1;
            uint32_t l0 = pack_f16(v.x - __half2float(p0.x), v.y - __half2float(p0.y));
            uint32_t l1 = pack_f16(v.z - __half2float(p1.x), v.w - __half2float(p1.y));
            *(uint2*)(dh + i * 4) = make_uint2(h0, h1);
            *(uint2*)(dl + i * 4) = make_uint2(l0, l1);
        }
    }
    __syncthreads();

    // ---- load Q fragments into registers (kept for whole block) ----
    uint32_t qh[4][4], ql[4][4];
    #pragma unroll
    for (int kt = 0; kt < 4; kt++) {
        uint32_t ao = (uint32_t)((wid * 16 + a_row) * APT + kt * 16 + a_k) * 2;
        ldmx4(qh[kt][0], qh[kt][1], qh[kt][2], qh[kt][3], uQh + ao);
        ldmx4(ql[kt][0], ql[kt][1], ql[kt][2], ql[kt][3], uQl + ao);
    }

    float o[8][4];
    #pragma unroll
    for (int nt = 0; nt < 8; nt++)
        #pragma unroll
        for (int r = 0; r < 4; r++) o[nt][r] = 0.f;
    float m0 = -1e30f, m1 = -1e30f, l0 = 0.f, l1 = 0.f;

    const int row_g0 = tq * 64 + wid * 16 + grp;
    const int row_g1 = row_g0 + 8;

    for (int ks = 0; ks <= tq; ks++) {
        __syncthreads();   // prior V reads done; Q frags already in regs
        // ---- stage K (hi) and V (hi/lo) ----
        {
            const size_t base = ((size_t)b * SEQ + (size_t)ks * 64 + srow) * QKVDIM
                              + h * HDIM + scol;
            const float* kp = qkv + base + EMB;
            const float* vp = qkv + base + 2 * EMB;
            __half* dk  = sKh + srow * APT + scol;
            __half* dvh = sVh + srow * APT + scol;
            __half* dvl = sVl + srow * APT + scol;
            #pragma unroll
            for (int i = 0; i < 8; i++) {
                float4 kv = *(const float4*)(kp + i * 4);
                uint32_t k0 = pack_f16(kv.x, kv.y), k1 = pack_f16(kv.z, kv.w);
                *(uint2*)(dk + i * 4) = make_uint2(k0, k1);
                float4 vv = *(const float4*)(vp + i * 4);
                uint32_t h0 = pack_f16(vv.x, vv.y), h1 = pack_f16(vv.z, vv.w);
                __half2 p0 = *(__half2*)&h0, p1 = *(__half2*)&h1;
                uint32_t l0v = pack_f16(vv.x - __half2float(p0.x), vv.y - __half2float(p0.y));
                uint32_t l1v = pack_f16(vv.z - __half2float(p1.x), vv.w - __half2float(p1.y));
                *(uint2*)(dvh + i * 4) = make_uint2(h0, h1);
                *(uint2*)(dvl + i * 4) = make_uint2(l0v, l1v);
            }
        }
        __syncthreads();

        // ---- S = Q K^T (fp32 accum) ----
        float s[8][4];
        #pragma unroll
        for (int nt = 0; nt < 8; nt++)
            #pragma unroll
            for (int r = 0; r < 4; r++) s[nt][r] = 0.f;
        #pragma unroll
        for (int kt = 0; kt < 4; kt++) {
            #pragma unroll
            for (int ntp = 0; ntp < 4; ntp++) {
                uint32_t kb[2][2];
                uint32_t bo = (uint32_t)((ntp * 16 + b_row) * APT + kt * 16 + b_k) * 2;
                ldmx4(kb[0][0], kb[0][1], kb[1][0], kb[1][1], uKh + bo);
                mma_f16(s[2 * ntp + 0], qh[kt], kb[0]);
                mma_f16(s[2 * ntp + 0], ql[kt], kb[0]);
                mma_f16(s[2 * ntp + 1], qh[kt], kb[1]);
                mma_f16(s[2 * ntp + 1], ql[kt], kb[1]);
            }
        }

        // ---- scale + causal mask ----
        const bool diag = (ks == tq);
        #pragma unroll
        for (int nt = 0; nt < 8; nt++) {
            int c = ks * 64 + nt * 8 + 2 * tig;
            #pragma unroll
            for (int r = 0; r < 4; r++) s[nt][r] *= scale;
            if (diag) {
                if (c > row_g0)     s[nt][0] = -1e30f;
                if (c + 1 > row_g0) s[nt][1] = -1e30f;
                if (c > row_g1)     s[nt][2] = -1e30f;
                if (c + 1 > row_g1) s[nt][3] = -1e30f;
            }
        }

        // ---- online softmax (rows grp / grp+8; 4 lanes per row) ----
        float t0 = -1e30f, t1 = -1e30f;
        #pragma unroll
        for (int nt = 0; nt < 8; nt++) {
            t0 = fmaxf(t0, fmaxf(s[nt][0], s[nt][1]));
            t1 = fmaxf(t1, fmaxf(s[nt][2], s[nt][3]));
        }
        #pragma unroll
        for (int off = 1; off < 4; off <<= 1) {
            t0 = fmaxf(t0, __shfl_xor_sync(0xffffffffu, t0, off));
            t1 = fmaxf(t1, __shfl_xor_sync(0xffffffffu, t1, off));
        }
        float nm0 = fmaxf(m0, t0), nm1 = fmaxf(m1, t1);
        float cr0 = __expf(m0 - nm0), cr1 = __expf(m1 - nm1);
        m0 = nm0; m1 = nm1;
        float rs0 = 0.f, rs1 = 0.f;
        uint32_t p01[8], p23[8];
        #pragma unroll
        for (int nt = 0; nt < 8; nt++) {
            float e0 = __expf(s[nt][0] - nm0);
            float e1 = __expf(s[nt][1] - nm0);
            float e2 = __expf(s[nt][2] - nm1);
            float e3 = __expf(s[nt][3] - nm1);
            rs0 += e0 + e1; rs1 += e2 + e3;
            p01[nt] = pack_f16(e0, e1);
            p23[nt] = pack_f16(e2, e3);
        }
        #pragma unroll
        for (int off = 1; off < 4; off <<= 1) {
            rs0 += __shfl_xor_sync(0xffffffffu, rs0, off);
            rs1 += __shfl_xor_sync(0xffffffffu, rs1, off);
        }
        l0 = l0 * cr0 + rs0;
        l1 = l1 * cr1 + rs1;
        #pragma unroll
        for (int nt = 0; nt < 8; nt++) {
            o[nt][0] *= cr0; o[nt][1] *= cr0;
            o[nt][2] *= cr1; o[nt][3] *= cr1;
        }

        // ---- O += P @ V  (V via ldmatrix.trans, hi+lo) ----
        #pragma unroll
        for (int kt = 0; kt < 4; kt++) {
            uint32_t a[4] = { p01[2 * kt], p23[2 * kt], p01[2 * kt + 1], p23[2 * kt + 1] };
            #pragma unroll
            for (int ntp = 0; ntp < 4; ntp++) {
                uint32_t vb[2][2], wb[2][2];
                uint32_t vo = (uint32_t)((kt * 16 + a_row) * APT + ntp * 16 + a_k) * 2;
                ldmx4t(vb[0][0], vb[0][1], vb[1][0], vb[1][1], uVh + vo);
                ldmx4t(wb[0][0], wb[0][1], wb[1][0], wb[1][1], uVl + vo);
                mma_f16(o[2 * ntp + 0], a, vb[0]);
                mma_f16(o[2 * ntp + 0], a, wb[0]);
                mma_f16(o[2 * ntp + 1], a, vb[1]);
                mma_f16(o[2 * ntp + 1], a, wb[1]);
            }
        }
    }

    // ---- write O / l ----
    float inv0 = 1.f / l0, inv1 = 1.f / l1;
    float* y0 = y + ((size_t)b * SEQ + (size_t)tq * 64 + wid * 16 + grp) * EMB + h * HDIM;
    float* y1 = y0 + 8 * EMB;
    #pragma unroll
    for (int nt = 0; nt < 8; nt++) {
        int c = nt * 8 + 2 * tig;
        *(float2*)(y0 + c) = make_float2(o[nt][0] * inv0, o[nt][1] * inv0);
        *(float2*)(y1 + c) = make_float2(o[nt][2] * inv1, o[nt][3] * inv1);
    }
}

// -------------------------------------------------------------------- launch
extern "C" void kernel_launch(void* const* d_in, const int* in_sizes, int n_in,
                              void* d_out, int out_size) {
    const int*   tokens = (const int*)  d_in[0];
    const float* wte    = (const float*)d_in[1];
    const float* wpe    = (const float*)d_in[2];
    const float* ln1w   = (const float*)d_in[3];
    const float* ln1b   = (const float*)d_in[4];
    const float* qkvw   = (const float*)d_in[5];
    const float* qkvb   = (const float*)d_in[6];
    const float* atpw   = (const float*)d_in[7];
    const float* atpb   = (const float*)d_in[8];
    const float* ln2w   = (const float*)d_in[9];
    const float* ln2b   = (const float*)d_in[10];
    const float* fcw    = (const float*)d_in[11];
    const float* fcb    = (const float*)d_in[12];
    const float* fpw    = (const float*)d_in[13];
    const float* fpb    = (const float*)d_in[14];
    const float* lnfw   = (const float*)d_in[15];
    const float* lnfb   = (const float*)d_in[16];
    const float* lmw    = (const float*)d_in[17];
    float* out = (float*)d_out;

    float *px, *pa, *pqkv, *py, *pm;
    __half *qh, *ql, *ah, *al, *fh, *fl, *ph, *pl, *lh, *ll;
    cudaGetSymbolAddress((void**)&px,   g_x);
    cudaGetSymbolAddress((void**)&pa,   g_a);
    cudaGetSymbolAddress((void**)&pqkv, g_qkv);
    cudaGetSymbolAddress((void**)&py,   g_y);
    cudaGetSymbolAddress((void**)&pm,   g_m);
    cudaGetSymbolAddress((void**)&qh, g_qkvH); cudaGetSymbolAddress((void**)&ql, g_qkvL);
    cudaGetSymbolAddress((void**)&ah, g_atpH); cudaGetSymbolAddress((void**)&al, g_atpL);
    cudaGetSymbolAddress((void**)&fh, g_fcH);  cudaGetSymbolAddress((void**)&fl, g_fcL);
    cudaGetSymbolAddress((void**)&ph, g_fpH);  cudaGetSymbolAddress((void**)&pl, g_fpL);
    cudaGetSymbolAddress((void**)&lh, g_lmH);  cudaGetSymbolAddress((void**)&ll, g_lmL);

    const int gsmem = 6 * BUFH * sizeof(__half);  // 61440
    cudaFuncSetAttribute(gemm_f16<0>, cudaFuncAttributeMaxDynamicSharedMemorySize, gsmem);
    cudaFuncSetAttribute(gemm_f16<1>, cudaFuncAttributeMaxDynamicSharedMemorySize, gsmem);
    cudaFuncSetAttribute(gemm_f16<2>, cudaFuncAttributeMaxDynamicSharedMemorySize, gsmem);
    cudaFuncSetAttribute(gemm_f16<3>, cudaFuncAttributeMaxDynamicSharedMemorySize, gsmem);

    const int asmem = 5 * ATILE * sizeof(__half);  // 46080
    cudaFuncSetAttribute(attn_mma, cudaFuncAttributeMaxDynamicSharedMemorySize, asmem);

    dim3 tb(32, 8);
    transpose_split_kernel<<<dim3(QKVDIM / 32, EMB / 32, NLAYER), tb>>>(qkvw, qh, ql, EMB, QKVDIM);
    transpose_split_kernel<<<dim3(EMB / 32,    EMB / 32, NLAYER), tb>>>(atpw, ah, al, EMB, EMB);
    transpose_split_kernel<<<dim3(FFDIM / 32,  EMB / 32, NLAYER), tb>>>(fcw,  fh, fl, EMB, FFDIM);
    transpose_split_kernel<<<dim3(EMB / 32,  FFDIM / 32, NLAYER), tb>>>(fpw,  ph, pl, FFDIM, EMB);
    split_kernel<<<(VOCAB * EMB + 255) / 256, 256>>>(lmw, lh, ll, VOCAB * EMB);

    embed_kernel<<<(TOKENS * EMB + 255) / 256, 256>>>(tokens, wte, wpe, px);

    for (int i = 0; i < NLAYER; i++) {
        ln_kernel<<<TOKENS, 256>>>(px, ln1w + i * EMB, ln1b + i * EMB, pa);

        gemm_f16<0><<<dim3(QKVDIM / 128, TOKENS / 128), 256, gsmem>>>(
            pa, qh + (size_t)i * QKVDIM * EMB, ql + (size_t)i * QKVDIM * EMB,
            qkvb + i * QKVDIM, nullptr, pqkv, TOKENS, QKVDIM, EMB);

        attn_mma<<<dim3(SEQ / 64, NHEAD, NBATCH), 128, asmem>>>(pqkv, py);

        gemm_f16<1><<<dim3(EMB / 128, TOKENS / 128), 256, gsmem>>>(
            py, ah + (size_t)i * EMB * EMB, al + (size_t)i * EMB * EMB,
            atpb + i * EMB, px, px, TOKENS, EMB, EMB);

        ln_kernel<<<TOKENS, 256>>>(px, ln2w + i * EMB, ln2b + i * EMB, pa);

        gemm_f16<2><<<dim3(FFDIM / 128, TOKENS / 128), 256, gsmem>>>(
            pa, fh + (size_t)i * FFDIM * EMB, fl + (size_t)i * FFDIM * EMB,
            fcb + i * FFDIM, nullptr, pm, TOKENS, FFDIM, EMB);

        gemm_f16<1><<<dim3(EMB / 128, TOKENS / 128), 256, gsmem>>>(
            pm, ph + (size_t)i * EMB * FFDIM, pl + (size_t)i * EMB * FFDIM,
            fpb + i * EMB, px, px, TOKENS, EMB, FFDIM);
    }

    ln_kernel<<<TOKENS, 256>>>(px, lnfw, lnfb, pa);

    gemm_f16<3><<<dim3((VOCAB + 127) / 128, TOKENS / 128), 256, gsmem>>>(
        pa, lh, ll, nullptr, nullptr, out, TOKENS, VOCAB, EMB);
}

// round 8
// speedup vs baseline: 4.0263x; 1.2923x over previous
#include <cuda_runtime.h>
#include <cuda_fp16.h>
#include <math.h>
#include <stdint.h>

#define TOKENS 4096
#define EMB    768
#define NLAYER 12
#define NHEAD  12
#define HDIM   64
#define SEQ    1024
#define NBATCH 4
#define VOCAB  50257
#define FFDIM  3072
#define QKVDIM 2304

// -------------------- scratch (static device globals; no allocation) --------
__device__ float  g_x  [TOKENS * EMB];          // fp32 residual stream
__device__ __half g_ah [TOKENS * EMB];          // LN output (GEMM A)
__device__ __half g_qkvh[TOKENS * QKVDIM];      // qkv projection (fp16)
__device__ __half g_yh [TOKENS * EMB];          // attention output (fp16)
__device__ __half g_mh [TOKENS * FFDIM];        // MLP hidden (fp16)
// pre-split transposed weights ([N,K] K-major, fp16 hi/lo)
__device__ __half g_qkvH[(size_t)NLAYER * QKVDIM * EMB];
__device__ __half g_qkvL[(size_t)NLAYER * QKVDIM * EMB];
__device__ __half g_atpH[(size_t)NLAYER * EMB * EMB];
__device__ __half g_atpL[(size_t)NLAYER * EMB * EMB];
__device__ __half g_fcH [(size_t)NLAYER * FFDIM * EMB];
__device__ __half g_fcL [(size_t)NLAYER * FFDIM * EMB];
__device__ __half g_fpH [(size_t)NLAYER * EMB * FFDIM];
__device__ __half g_fpL [(size_t)NLAYER * EMB * FFDIM];
__device__ __half g_lmH [(size_t)VOCAB * EMB];
__device__ __half g_lmL [(size_t)VOCAB * EMB];

// ------------------------------------------------------------- helpers
__device__ __forceinline__ float gelu_f(float x) {
    float x3 = x * x * x;
    return 0.5f * x * (1.f + tanhf(0.7978845608028654f * (x + 0.044715f * x3)));
}
__device__ __forceinline__ uint32_t pack_f16(float x0, float x1) {
    uint32_t u;
    asm("{.reg .b16 l,h; cvt.rn.f16.f32 l,%1; cvt.rn.f16.f32 h,%2; mov.b32 %0,{l,h};}"
        : "=r"(u) : "f"(x0), "f"(x1));
    return u;
}
__device__ __forceinline__ void mma_f16(float* c, const uint32_t* a, const uint32_t* b) {
    asm volatile(
        "mma.sync.aligned.m16n8k16.row.col.f32.f16.f16.f32 "
        "{%0,%1,%2,%3}, {%4,%5,%6,%7}, {%8,%9}, {%0,%1,%2,%3};"
        : "+f"(c[0]), "+f"(c[1]), "+f"(c[2]), "+f"(c[3])
        : "r"(a[0]), "r"(a[1]), "r"(a[2]), "r"(a[3]), "r"(b[0]), "r"(b[1]));
}
__device__ __forceinline__ void ldmx4(uint32_t& r0, uint32_t& r1,
                                      uint32_t& r2, uint32_t& r3, uint32_t addr) {
    asm volatile("ldmatrix.sync.aligned.m8n8.x4.shared.b16 {%0,%1,%2,%3}, [%4];"
                 : "=r"(r0), "=r"(r1), "=r"(r2), "=r"(r3) : "r"(addr));
}
__device__ __forceinline__ void ldmx4t(uint32_t& r0, uint32_t& r1,
                                       uint32_t& r2, uint32_t& r3, uint32_t addr) {
    asm volatile("ldmatrix.sync.aligned.m8n8.x4.trans.shared.b16 {%0,%1,%2,%3}, [%4];"
                 : "=r"(r0), "=r"(r1), "=r"(r2), "=r"(r3) : "r"(addr));
}
__device__ __forceinline__ void cpa16(uint32_t dst, const void* src, int srcsz) {
    asm volatile("cp.async.ca.shared.global [%0], [%1], 16, %2;"
                 :: "r"(dst), "l"(src), "r"(srcsz) : "memory");
}
#define CP_COMMIT() asm volatile("cp.async.commit_group;" ::: "memory")
#define CP_WAIT0()  asm volatile("cp.async.wait_group 0;" ::: "memory")

// ---------------------------------------------------------------- embedding
__global__ void embed_kernel(const int* __restrict__ tok,
                             const float* __restrict__ wte,
                             const float* __restrict__ wpe,
                             float* __restrict__ x) {
    int idx = blockIdx.x * blockDim.x + threadIdx.x;
    if (idx >= TOKENS * EMB) return;
    int t = idx / EMB;
    int e = idx - t * EMB;
    x[idx] = wte[(size_t)tok[t] * EMB + e] + wpe[e];
}

// ------------------------------------------------ layernorm (fp16 output)
__global__ void ln_kernel(const float* __restrict__ x,
                          const float* __restrict__ w,
                          const float* __restrict__ bb,
                          __half* __restrict__ o) {
    int row = blockIdx.x;
    const float* xr = x + (size_t)row * EMB;
    int t = threadIdx.x;
    float v0 = xr[t], v1 = xr[t + 256], v2 = xr[t + 512];
    float s  = v0 + v1 + v2;
    float sq = v0 * v0 + v1 * v1 + v2 * v2;
    #pragma unroll
    for (int off = 16; off; off >>= 1) {
        s  += __shfl_xor_sync(0xffffffffu, s, off);
        sq += __shfl_xor_sync(0xffffffffu, sq, off);
    }
    __shared__ float rs[8], rq[8];
    __shared__ float s_mean, s_rstd;
    int wid = t >> 5;
    if ((t & 31) == 0) { rs[wid] = s; rq[wid] = sq; }
    __syncthreads();
    if (t == 0) {
        float S = 0.f, Q = 0.f;
        #pragma unroll
        for (int i = 0; i < 8; i++) { S += rs[i]; Q += rq[i]; }
        float mean = S * (1.f / EMB);
        s_mean = mean;
        s_rstd = rsqrtf(Q * (1.f / EMB) - mean * mean + 1e-5f);
    }
    __syncthreads();
    float mean = s_mean, rstd = s_rstd;
    __half* orow = o + (size_t)row * EMB;
    orow[t]       = __float2half_rn((v0 - mean) * rstd * w[t]       + bb[t]);
    orow[t + 256] = __float2half_rn((v1 - mean) * rstd * w[t + 256] + bb[t + 256]);
    orow[t + 512] = __float2half_rn((v2 - mean) * rstd * w[t + 512] + bb[t + 512]);
}

// --------------------------------------------- transpose + fp16 hi/lo split
__global__ void transpose_split_kernel(const float* __restrict__ in,
                                       __half* __restrict__ oh,
                                       __half* __restrict__ ol,
                                       int K, int N) {
    __shared__ float t[32][33];
    const size_t off = (size_t)blockIdx.z * K * N;
    int n0 = blockIdx.x * 32, k0 = blockIdx.y * 32;
    int x = threadIdx.x, y = threadIdx.y;
    #pragma unroll
    for (int i = 0; i < 32; i += 8)
        t[y + i][x] = in[off + (size_t)(k0 + y + i) * N + n0 + x];
    __syncthreads();
    #pragma unroll
    for (int i = 0; i < 32; i += 8) {
        float v = t[x][y + i];
        __half h = __float2half_rn(v);
        __half l = __float2half_rn(v - __half2float(h));
        size_t o = off + (size_t)(n0 + y + i) * K + k0 + x;
        oh[o] = h; ol[o] = l;
    }
}

// ------------------------------------------------- elementwise fp16 split
__global__ void split_kernel(const float* __restrict__ in,
                             __half* __restrict__ oh,
                             __half* __restrict__ ol, int n) {
    int i = blockIdx.x * blockDim.x + threadIdx.x;
    if (i >= n) return;
    float v = in[i];
    __half h = __float2half_rn(v);
    __half l = __float2half_rn(v - __half2float(h));
    oh[i] = h; ol[i] = l;
}

// ------------------------------------------- fp16 B-split-2 mma.sync GEMM
// C[M,N] = A[M,K] @ B[N,K]^T.  A fp16 (producer-rounded), B = Bh+Bl exact.
// EPI 0: +bias -> half   | EPI 1: +bias+res(fp32) -> float
// EPI 2: +bias+gelu -> half | EPI 3: plain, N-guard -> float
// CTA 128x128x32, all operands via cp.async double-buffer.
#define BP 40
#define BUFH (128 * BP)
template <int EPI>
__global__ void __launch_bounds__(256, 2)
gemm_f16(const __half* __restrict__ Ah,
         const __half* __restrict__ Bh, const __half* __restrict__ Bl,
         const float* __restrict__ bias, const float* __restrict__ res,
         void* __restrict__ Cv, int M, int N, int K) {
    extern __shared__ __half sm[];
    __half* sA  = sm;
    __half* sBh = sm + 2 * BUFH;
    __half* sBl = sm + 4 * BUFH;
    const uint32_t uA  = (uint32_t)__cvta_generic_to_shared(sA);
    const uint32_t uBh = (uint32_t)__cvta_generic_to_shared(sBh);
    const uint32_t uBl = (uint32_t)__cvta_generic_to_shared(sBl);

    const int tid  = threadIdx.x;
    const int wid  = tid >> 5;
    const int lane = tid & 31;
    const int grp  = lane >> 2;
    const int tig  = lane & 3;
    const int bm = blockIdx.y * 128;
    const int bn = blockIdx.x * 128;
    const int wm0 = (wid & 1) * 64;
    const int wn0 = (wid >> 1) * 32;

    const int a_row = (lane & 15);
    const int a_k   = (lane >> 4) << 3;
    const int b_row = (lane & 7) + ((lane >> 4) << 3);
    const int b_k   = ((lane >> 3) & 1) << 3;

    float cf[4][4][4];
    #pragma unroll
    for (int i = 0; i < 4; i++)
        #pragma unroll
        for (int j = 0; j < 4; j++)
            #pragma unroll
            for (int r = 0; r < 4; r++) cf[i][j][r] = 0.f;

    const int KC = K >> 5;

    auto stage = [&](int k0, int p) {
        #pragma unroll
        for (int ps = 0; ps < 2; ps++) {
            int s = tid + ps * 256;
            int row = s >> 2;
            int c16 = (s & 3) * 8;
            uint32_t doff = (uint32_t)(p * BUFH + row * BP + c16) * 2;
            cpa16(uA + doff, Ah + (size_t)(bm + row) * K + k0 + c16, 16);
            int gr = bn + row, sz = 16;
            if (EPI == 3 && gr >= N) { gr = 0; sz = 0; }
            cpa16(uBh + doff, Bh + (size_t)gr * K + k0 + c16, sz);
            cpa16(uBl + doff, Bl + (size_t)gr * K + k0 + c16, sz);
        }
        CP_COMMIT();
    };

    stage(0, 0);

    for (int c = 0; c < KC; c++) {
        const int p = c & 1;
        CP_WAIT0();
        __syncthreads();
        if (c + 1 < KC) stage((c + 1) << 5, 1 - p);

        const uint32_t bufA  = uA  + (uint32_t)(p * BUFH) * 2;
        const uint32_t bufBh = uBh + (uint32_t)(p * BUFH) * 2;
        const uint32_t bufBl = uBl + (uint32_t)(p * BUFH) * 2;
        #pragma unroll
        for (int ks = 0; ks < 2; ks++) {
            const int k0 = ks * 16;
            uint32_t bh[4][2], bl[4][2];
            uint32_t bo = (uint32_t)((wn0 + b_row) * BP + k0 + b_k) * 2;
            ldmx4(bh[0][0], bh[0][1], bh[1][0], bh[1][1], bufBh + bo);
            ldmx4(bh[2][0], bh[2][1], bh[3][0], bh[3][1], bufBh + bo + 16 * BP * 2);
            ldmx4(bl[0][0], bl[0][1], bl[1][0], bl[1][1], bufBl + bo);
            ldmx4(bl[2][0], bl[2][1], bl[3][0], bl[3][1], bufBl + bo + 16 * BP * 2);
            #pragma unroll
            for (int mt = 0; mt < 4; mt++) {
                uint32_t a[4];
                uint32_t ao = (uint32_t)((wm0 + mt * 16 + a_row) * BP + k0 + a_k) * 2;
                ldmx4(a[0], a[1], a[2], a[3], bufA + ao);
                #pragma unroll
                for (int nt = 0; nt < 4; nt++) {
                    mma_f16(cf[mt][nt], a, bh[nt]);
                    mma_f16(cf[mt][nt], a, bl[nt]);
                }
            }
        }
    }

    // ---------------- epilogue ----------------
    #pragma unroll
    for (int mt = 0; mt < 4; mt++) {
        #pragma unroll
        for (int half = 0; half < 2; half++) {
            const int row = bm + wm0 + mt * 16 + grp + half * 8;
            #pragma unroll
            for (int nt = 0; nt < 4; nt++) {
                const int col = bn + wn0 + nt * 8 + 2 * tig;
                float v0 = cf[mt][nt][half * 2 + 0];
                float v1 = cf[mt][nt][half * 2 + 1];
                if (EPI == 3) {
                    float* C = (float*)Cv;
                    if (col < N)     C[(size_t)row * N + col]     = v0;
                    if (col + 1 < N) C[(size_t)row * N + col + 1] = v1;
                } else {
                    v0 += bias[col];
                    v1 += bias[col + 1];
                    if (EPI == 1) {
                        const float* rp = res + (size_t)row * N + col;
                        v0 += rp[0]; v1 += rp[1];
                        *(float2*)((float*)Cv + (size_t)row * N + col) = make_float2(v0, v1);
                    } else {
                        if (EPI == 2) { v0 = gelu_f(v0); v1 = gelu_f(v1); }
                        *(uint32_t*)((__half*)Cv + (size_t)row * N + col) = pack_f16(v0, v1);
                    }
                }
            }
        }
    }
}

// ------------------------------------ fp16 mma.sync flash attention (v2)
// qkv fp16; pure cp.async staging, K/V double-buffered; no splits.
#define APT 72
#define ATILE (64 * APT)
__global__ void __launch_bounds__(128)
attn_mma(const __half* __restrict__ qkv, __half* __restrict__ y) {
    extern __shared__ __half sh[];
    __half* sQ = sh;                  // [64][APT]
    __half* sK = sh + ATILE;          // 2 x [64][APT]
    __half* sV = sh + 3 * ATILE;      // 2 x [64][APT]
    const uint32_t uQ = (uint32_t)__cvta_generic_to_shared(sQ);
    const uint32_t uK = (uint32_t)__cvta_generic_to_shared(sK);
    const uint32_t uV = (uint32_t)__cvta_generic_to_shared(sV);

    const int tq = blockIdx.x, h = blockIdx.y, b = blockIdx.z;
    const int tid  = threadIdx.x;
    const int wid  = tid >> 5;
    const int lane = tid & 31;
    const int grp  = lane >> 2;
    const int tig  = lane & 3;
    const float scale = 0.036084391824351615f;  // 1/sqrt(768)

    const int a_row = lane & 15;
    const int a_k   = (lane >> 4) << 3;
    const int b_row = (lane & 7) + ((lane >> 4) << 3);
    const int b_k   = ((lane >> 3) & 1) << 3;

    auto stageKV = [&](int ks, int p) {
        #pragma unroll
        for (int ps = 0; ps < 4; ps++) {
            int s = tid + ps * 128;
            int row = s >> 3;
            int ch = (s & 7) * 8;
            const __half* base = qkv + ((size_t)b * SEQ + (size_t)ks * 64 + row) * QKVDIM
                               + h * HDIM + ch;
            uint32_t doff = (uint32_t)(p * ATILE + row * APT + ch) * 2;
            cpa16(uK + doff, base + EMB, 16);
            cpa16(uV + doff, base + 2 * EMB, 16);
        }
        CP_COMMIT();
    };

    // ---- stage Q + KV(0) ----
    #pragma unroll
    for (int ps = 0; ps < 4; ps++) {
        int s = tid + ps * 128;
        int row = s >> 3;
        int ch = (s & 7) * 8;
        cpa16(uQ + (uint32_t)(row * APT + ch) * 2,
              qkv + ((size_t)b * SEQ + (size_t)tq * 64 + row) * QKVDIM + h * HDIM + ch, 16);
    }
    stageKV(0, 0);
    CP_WAIT0();
    __syncthreads();

    // ---- Q fragments (registers, whole block) ----
    uint32_t qf[4][4];
    #pragma unroll
    for (int kt = 0; kt < 4; kt++) {
        uint32_t ao = (uint32_t)((wid * 16 + a_row) * APT + kt * 16 + a_k) * 2;
        ldmx4(qf[kt][0], qf[kt][1], qf[kt][2], qf[kt][3], uQ + ao);
    }

    float o[8][4];
    #pragma unroll
    for (int nt = 0; nt < 8; nt++)
        #pragma unroll
        for (int r = 0; r < 4; r++) o[nt][r] = 0.f;
    float m0 = -1e30f, m1 = -1e30f, l0 = 0.f, l1 = 0.f;

    const int row_g0 = tq * 64 + wid * 16 + grp;
    const int row_g1 = row_g0 + 8;

    for (int ks = 0; ks <= tq; ks++) {
        const int p = ks & 1;
        if (ks > 0) { CP_WAIT0(); __syncthreads(); }
        if (ks + 1 <= tq) stageKV(ks + 1, 1 - p);

        const uint32_t bufK = uK + (uint32_t)(p * ATILE) * 2;
        const uint32_t bufV = uV + (uint32_t)(p * ATILE) * 2;

        // ---- S = Q K^T ----
        float s[8][4];
        #pragma unroll
        for (int nt = 0; nt < 8; nt++)
            #pragma unroll
            for (int r = 0; r < 4; r++) s[nt][r] = 0.f;
        #pragma unroll
        for (int kt = 0; kt < 4; kt++) {
            #pragma unroll
            for (int ntp = 0; ntp < 4; ntp++) {
                uint32_t kb[2][2];
                uint32_t bo = (uint32_t)((ntp * 16 + b_row) * APT + kt * 16 + b_k) * 2;
                ldmx4(kb[0][0], kb[0][1], kb[1][0], kb[1][1], bufK + bo);
                mma_f16(s[2 * ntp + 0], qf[kt], kb[0]);
                mma_f16(s[2 * ntp + 1], qf[kt], kb[1]);
            }
        }

        // ---- scale + causal mask ----
        const bool diag = (ks == tq);
        #pragma unroll
        for (int nt = 0; nt < 8; nt++) {
            int c = ks * 64 + nt * 8 + 2 * tig;
            #pragma unroll
            for (int r = 0; r < 4; r++) s[nt][r] *= scale;
            if (diag) {
                if (c > row_g0)     s[nt][0] = -1e30f;
                if (c + 1 > row_g0) s[nt][1] = -1e30f;
                if (c > row_g1)     s[nt][2] = -1e30f;
                if (c + 1 > row_g1) s[nt][3] = -1e30f;
            }
        }

        // ---- online softmax ----
        float t0 = -1e30f, t1 = -1e30f;
        #pragma unroll
        for (int nt = 0; nt < 8; nt++) {
            t0 = fmaxf(t0, fmaxf(s[nt][0], s[nt][1]));
            t1 = fmaxf(t1, fmaxf(s[nt][2], s[nt][3]));
        }
        #pragma unroll
        for (int off = 1; off < 4; off <<= 1) {
            t0 = fmaxf(t0, __shfl_xor_sync(0xffffffffu, t0, off));
            t1 = fmaxf(t1, __shfl_xor_sync(0xffffffffu, t1, off));
        }
        float nm0 = fmaxf(m0, t0), nm1 = fmaxf(m1, t1);
        float cr0 = __expf(m0 - nm0), cr1 = __expf(m1 - nm1);
        m0 = nm0; m1 = nm1;
        float rs0 = 0.f, rs1 = 0.f;
        uint32_t p01[8], p23[8];
        #pragma unroll
        for (int nt = 0; nt < 8; nt++) {
            float e0 = __expf(s[nt][0] - nm0);
            float e1 = __expf(s[nt][1] - nm0);
            float e2 = __expf(s[nt][2] - nm1);
            float e3 = __expf(s[nt][3] - nm1);
            rs0 += e0 + e1; rs1 += e2 + e3;
            p01[nt] = pack_f16(e0, e1);
            p23[nt] = pack_f16(e2, e3);
        }
        #pragma unroll
        for (int off = 1; off < 4; off <<= 1) {
            rs0 += __shfl_xor_sync(0xffffffffu, rs0, off);
            rs1 += __shfl_xor_sync(0xffffffffu, rs1, off);
        }
        l0 = l0 * cr0 + rs0;
        l1 = l1 * cr1 + rs1;
        #pragma unroll
        for (int nt = 0; nt < 8; nt++) {
            o[nt][0] *= cr0; o[nt][1] *= cr0;
            o[nt][2] *= cr1; o[nt][3] *= cr1;
        }

        // ---- O += P @ V ----
        #pragma unroll
        for (int kt = 0; kt < 4; kt++) {
            uint32_t a[4] = { p01[2 * kt], p23[2 * kt], p01[2 * kt + 1], p23[2 * kt + 1] };
            #pragma unroll
            for (int ntp = 0; ntp < 4; ntp++) {
                uint32_t vb[2][2];
                uint32_t vo = (uint32_t)((kt * 16 + a_row) * APT + ntp * 16 + a_k) * 2;
                ldmx4t(vb[0][0], vb[0][1], vb[1][0], vb[1][1], bufV + vo);
                mma_f16(o[2 * ntp + 0], a, vb[0]);
                mma_f16(o[2 * ntp + 1], a, vb[1]);
            }
        }
    }

    // ---- write O (fp16) ----
    float inv0 = 1.f / l0, inv1 = 1.f / l1;
    __half* y0 = y + ((size_t)b * SEQ + (size_t)tq * 64 + wid * 16 + grp) * EMB + h * HDIM;
    __half* y1 = y0 + 8 * EMB;
    #pragma unroll
    for (int nt = 0; nt < 8; nt++) {
        int c = nt * 8 + 2 * tig;
        *(uint32_t*)(y0 + c) = pack_f16(o[nt][0] * inv0, o[nt][1] * inv0);
        *(uint32_t*)(y1 + c) = pack_f16(o[nt][2] * inv1, o[nt][3] * inv1);
    }
}

// -------------------------------------------------------------------- launch
extern "C" void kernel_launch(void* const* d_in, const int* in_sizes, int n_in,
                              void* d_out, int out_size) {
    const int*   tokens = (const int*)  d_in[0];
    const float* wte    = (const float*)d_in[1];
    const float* wpe    = (const float*)d_in[2];
    const float* ln1w   = (const float*)d_in[3];
    const float* ln1b   = (const float*)d_in[4];
    const float* qkvw   = (const float*)d_in[5];
    const float* qkvb   = (const float*)d_in[6];
    const float* atpw   = (const float*)d_in[7];
    const float* atpb   = (const float*)d_in[8];
    const float* ln2w   = (const float*)d_in[9];
    const float* ln2b   = (const float*)d_in[10];
    const float* fcw    = (const float*)d_in[11];
    const float* fcb    = (const float*)d_in[12];
    const float* fpw    = (const float*)d_in[13];
    const float* fpb    = (const float*)d_in[14];
    const float* lnfw   = (const float*)d_in[15];
    const float* lnfb   = (const float*)d_in[16];
    const float* lmw    = (const float*)d_in[17];
    float* out = (float*)d_out;

    float* px;
    __half *pah, *pqkvh, *pyh, *pmh;
    __half *qh, *ql, *ah, *al, *fh, *fl, *ph, *pl, *lh, *ll;
    cudaGetSymbolAddress((void**)&px,    g_x);
    cudaGetSymbolAddress((void**)&pah,   g_ah);
    cudaGetSymbolAddress((void**)&pqkvh, g_qkvh);
    cudaGetSymbolAddress((void**)&pyh,   g_yh);
    cudaGetSymbolAddress((void**)&pmh,   g_mh);
    cudaGetSymbolAddress((void**)&qh, g_qkvH); cudaGetSymbolAddress((void**)&ql, g_qkvL);
    cudaGetSymbolAddress((void**)&ah, g_atpH); cudaGetSymbolAddress((void**)&al, g_atpL);
    cudaGetSymbolAddress((void**)&fh, g_fcH);  cudaGetSymbolAddress((void**)&fl, g_fcL);
    cudaGetSymbolAddress((void**)&ph, g_fpH);  cudaGetSymbolAddress((void**)&pl, g_fpL);
    cudaGetSymbolAddress((void**)&lh, g_lmH);  cudaGetSymbolAddress((void**)&ll, g_lmL);

    const int gsmem = 6 * BUFH * sizeof(__half);  // 61440
    cudaFuncSetAttribute(gemm_f16<0>, cudaFuncAttributeMaxDynamicSharedMemorySize, gsmem);
    cudaFuncSetAttribute(gemm_f16<1>, cudaFuncAttributeMaxDynamicSharedMemorySize, gsmem);
    cudaFuncSetAttribute(gemm_f16<2>, cudaFuncAttributeMaxDynamicSharedMemorySize, gsmem);
    cudaFuncSetAttribute(gemm_f16<3>, cudaFuncAttributeMaxDynamicSharedMemorySize, gsmem);

    const int asmem = 5 * ATILE * sizeof(__half);  // 46080
    cudaFuncSetAttribute(attn_mma, cudaFuncAttributeMaxDynamicSharedMemorySize, asmem);

    dim3 tb(32, 8);
    transpose_split_kernel<<<dim3(QKVDIM / 32, EMB / 32, NLAYER), tb>>>(qkvw, qh, ql, EMB, QKVDIM);
    transpose_split_kernel<<<dim3(EMB / 32,    EMB / 32, NLAYER), tb>>>(atpw, ah, al, EMB, EMB);
    transpose_split_kernel<<<dim3(FFDIM / 32,  EMB / 32, NLAYER), tb>>>(fcw,  fh, fl, EMB, FFDIM);
    transpose_split_kernel<<<dim3(EMB / 32,  FFDIM / 32, NLAYER), tb>>>(fpw,  ph, pl, FFDIM, EMB);
    split_kernel<<<(VOCAB * EMB + 255) / 256, 256>>>(lmw, lh, ll, VOCAB * EMB);

    embed_kernel<<<(TOKENS * EMB + 255) / 256, 256>>>(tokens, wte, wpe, px);

    for (int i = 0; i < NLAYER; i++) {
        ln_kernel<<<TOKENS, 256>>>(px, ln1w + i * EMB, ln1b + i * EMB, pah);

        gemm_f16<0><<<dim3(QKVDIM / 128, TOKENS / 128), 256, gsmem>>>(
            pah, qh + (size_t)i * QKVDIM * EMB, ql + (size_t)i * QKVDIM * EMB,
            qkvb + i * QKVDIM, nullptr, pqkvh, TOKENS, QKVDIM, EMB);

        attn_mma<<<dim3(SEQ / 64, NHEAD, NBATCH), 128, asmem>>>(pqkvh, pyh);

        gemm_f16<1><<<dim3(EMB / 128, TOKENS / 128), 256, gsmem>>>(
            pyh, ah + (size_t)i * EMB * EMB, al + (size_t)i * EMB * EMB,
            atpb + i * EMB, px, px, TOKENS, EMB, EMB);

        ln_kernel<<<TOKENS, 256>>>(px, ln2w + i * EMB, ln2b + i * EMB, pah);

        gemm_f16<2><<<dim3(FFDIM / 128, TOKENS / 128), 256, gsmem>>>(
            pah, fh + (size_t)i * FFDIM * EMB, fl + (size_t)i * FFDIM * EMB,
            fcb + i * FFDIM, nullptr, pmh, TOKENS, FFDIM, EMB);

        gemm_f16<1><<<dim3(EMB / 128, TOKENS / 128), 256, gsmem>>>(
            pmh, ph + (size_t)i * EMB * FFDIM, pl + (size_t)i * EMB * FFDIM,
            fpb + i * EMB, px, px, TOKENS, EMB, FFDIM);
    }

    ln_kernel<<<TOKENS, 256>>>(px, lnfw, lnfb, pah);

    gemm_f16<3><<<dim3((VOCAB + 127) / 128, TOKENS / 128), 256, gsmem>>>(
        pah, lh, ll, nullptr, nullptr, out, TOKENS, VOCAB, EMB);
}

// round 9
// speedup vs baseline: 4.3560x; 1.0819x over previous
#include <cuda_runtime.h>
#include <cuda_fp16.h>
#include <math.h>
#include <stdint.h>

#define TOKENS 4096
#define EMB    768
#define NLAYER 12
#define NHEAD  12
#define HDIM   64
#define SEQ    1024
#define NBATCH 4
#define VOCAB  50257
#define FFDIM  3072
#define QKVDIM 2304

// -------------------- scratch (static device globals; no allocation) --------
__device__ float  g_x  [TOKENS * EMB];
__device__ __half g_ah [TOKENS * EMB];
__device__ __half g_qkvh[TOKENS * QKVDIM];
__device__ __half g_yh [TOKENS * EMB];
__device__ __half g_mh [TOKENS * FFDIM];
__device__ __half g_qkvH[(size_t)NLAYER * QKVDIM * EMB];
__device__ __half g_qkvL[(size_t)NLAYER * QKVDIM * EMB];
__device__ __half g_atpH[(size_t)NLAYER * EMB * EMB];
__device__ __half g_atpL[(size_t)NLAYER * EMB * EMB];
__device__ __half g_fcH [(size_t)NLAYER * FFDIM * EMB];
__device__ __half g_fcL [(size_t)NLAYER * FFDIM * EMB];
__device__ __half g_fpH [(size_t)NLAYER * EMB * FFDIM];
__device__ __half g_fpL [(size_t)NLAYER * EMB * FFDIM];
__device__ __half g_lmH [(size_t)VOCAB * EMB];

// ------------------------------------------------------------- helpers
__device__ __forceinline__ float gelu_f(float x) {
    float x3 = x * x * x;
    return 0.5f * x * (1.f + tanhf(0.7978845608028654f * (x + 0.044715f * x3)));
}
__device__ __forceinline__ uint32_t pack_f16(float x0, float x1) {
    uint32_t u;
    asm("{.reg .b16 l,h; cvt.rn.f16.f32 l,%1; cvt.rn.f16.f32 h,%2; mov.b32 %0,{l,h};}"
        : "=r"(u) : "f"(x0), "f"(x1));
    return u;
}
__device__ __forceinline__ void mma_f16(float* c, const uint32_t* a, const uint32_t* b) {
    asm volatile(
        "mma.sync.aligned.m16n8k16.row.col.f32.f16.f16.f32 "
        "{%0,%1,%2,%3}, {%4,%5,%6,%7}, {%8,%9}, {%0,%1,%2,%3};"
        : "+f"(c[0]), "+f"(c[1]), "+f"(c[2]), "+f"(c[3])
        : "r"(a[0]), "r"(a[1]), "r"(a[2]), "r"(a[3]), "r"(b[0]), "r"(b[1]));
}
__device__ __forceinline__ void ldmx4(uint32_t& r0, uint32_t& r1,
                                      uint32_t& r2, uint32_t& r3, uint32_t addr) {
    asm volatile("ldmatrix.sync.aligned.m8n8.x4.shared.b16 {%0,%1,%2,%3}, [%4];"
                 : "=r"(r0), "=r"(r1), "=r"(r2), "=r"(r3) : "r"(addr));
}
__device__ __forceinline__ void ldmx4t(uint32_t& r0, uint32_t& r1,
                                       uint32_t& r2, uint32_t& r3, uint32_t addr) {
    asm volatile("ldmatrix.sync.aligned.m8n8.x4.trans.shared.b16 {%0,%1,%2,%3}, [%4];"
                 : "=r"(r0), "=r"(r1), "=r"(r2), "=r"(r3) : "r"(addr));
}
__device__ __forceinline__ void cpa16(uint32_t dst, const void* src, int srcsz) {
    asm volatile("cp.async.ca.shared.global [%0], [%1], 16, %2;"
                 :: "r"(dst), "l"(src), "r"(srcsz) : "memory");
}
#define CP_COMMIT() asm volatile("cp.async.commit_group;" ::: "memory")
#define CP_WAIT0()  asm volatile("cp.async.wait_group 0;" ::: "memory")

// ---------------------------------------------------------------- embedding
__global__ void embed_kernel(const int* __restrict__ tok,
                             const float* __restrict__ wte,
                             const float* __restrict__ wpe,
                             float* __restrict__ x) {
    int idx = blockIdx.x * blockDim.x + threadIdx.x;
    if (idx >= TOKENS * EMB) return;
    int t = idx / EMB;
    int e = idx - t * EMB;
    x[idx] = wte[(size_t)tok[t] * EMB + e] + wpe[e];
}

// ------------------------------------------------ layernorm (fp16 output)
__global__ void ln_kernel(const float* __restrict__ x,
                          const float* __restrict__ w,
                          const float* __restrict__ bb,
                          __half* __restrict__ o) {
    int row = blockIdx.x;
    const float* xr = x + (size_t)row * EMB;
    int t = threadIdx.x;
    float v0 = xr[t], v1 = xr[t + 256], v2 = xr[t + 512];
    float s  = v0 + v1 + v2;
    float sq = v0 * v0 + v1 * v1 + v2 * v2;
    #pragma unroll
    for (int off = 16; off; off >>= 1) {
        s  += __shfl_xor_sync(0xffffffffu, s, off);
        sq += __shfl_xor_sync(0xffffffffu, sq, off);
    }
    __shared__ float rs[8], rq[8];
    __shared__ float s_mean, s_rstd;
    int wid = t >> 5;
    if ((t & 31) == 0) { rs[wid] = s; rq[wid] = sq; }
    __syncthreads();
    if (t == 0) {
        float S = 0.f, Q = 0.f;
        #pragma unroll
        for (int i = 0; i < 8; i++) { S += rs[i]; Q += rq[i]; }
        float mean = S * (1.f / EMB);
        s_mean = mean;
        s_rstd = rsqrtf(Q * (1.f / EMB) - mean * mean + 1e-5f);
    }
    __syncthreads();
    float mean = s_mean, rstd = s_rstd;
    __half* orow = o + (size_t)row * EMB;
    orow[t]       = __float2half_rn((v0 - mean) * rstd * w[t]       + bb[t]);
    orow[t + 256] = __float2half_rn((v1 - mean) * rstd * w[t + 256] + bb[t + 256]);
    orow[t + 512] = __float2half_rn((v2 - mean) * rstd * w[t + 512] + bb[t + 512]);
}

// --------------------------------------------- transpose + fp16 hi/lo split
__global__ void transpose_split_kernel(const float* __restrict__ in,
                                       __half* __restrict__ oh,
                                       __half* __restrict__ ol,
                                       int K, int N) {
    __shared__ float t[32][33];
    const size_t off = (size_t)blockIdx.z * K * N;
    int n0 = blockIdx.x * 32, k0 = blockIdx.y * 32;
    int x = threadIdx.x, y = threadIdx.y;
    #pragma unroll
    for (int i = 0; i < 32; i += 8)
        t[y + i][x] = in[off + (size_t)(k0 + y + i) * N + n0 + x];
    __syncthreads();
    #pragma unroll
    for (int i = 0; i < 32; i += 8) {
        float v = t[x][y + i];
        __half h = __float2half_rn(v);
        __half l = __float2half_rn(v - __half2float(h));
        size_t o = off + (size_t)(n0 + y + i) * K + k0 + x;
        oh[o] = h; ol[o] = l;
    }
}

// ---------------------------------------------- elementwise fp16 convert
__global__ void cvt_kernel(const float* __restrict__ in,
                           __half* __restrict__ oh, int n) {
    int i = blockIdx.x * blockDim.x + threadIdx.x;
    if (i >= n) return;
    oh[i] = __float2half_rn(in[i]);
}

// ------------------------------------------- fp16 mma.sync GEMM
// C[M,N] = A[M,K] @ B[N,K]^T.  A fp16 (producer-rounded).
// EPI 0: B=Bh+Bl, +bias -> half      | EPI 1: B=Bh+Bl, +bias+res(fp32) -> float
// EPI 2: B=Bh+Bl, +bias+gelu -> half | EPI 4: B=Bh only, plain, N-guard -> float
#define BP 40
#define BUFH (128 * BP)
template <int EPI>
__global__ void __launch_bounds__(256, 2)
gemm_f16(const __half* __restrict__ Ah,
         const __half* __restrict__ Bh, const __half* __restrict__ Bl,
         const float* __restrict__ bias, const float* __restrict__ res,
         void* __restrict__ Cv, int M, int N, int K) {
    extern __shared__ __half sm[];
    __half* sA  = sm;
    __half* sBh = sm + 2 * BUFH;
    __half* sBl = sm + 4 * BUFH;
    const uint32_t uA  = (uint32_t)__cvta_generic_to_shared(sA);
    const uint32_t uBh = (uint32_t)__cvta_generic_to_shared(sBh);
    const uint32_t uBl = (uint32_t)__cvta_generic_to_shared(sBl);

    const int tid  = threadIdx.x;
    const int wid  = tid >> 5;
    const int lane = tid & 31;
    const int grp  = lane >> 2;
    const int tig  = lane & 3;
    const int bm = blockIdx.y * 128;
    const int bn = blockIdx.x * 128;
    const int wm0 = (wid & 1) * 64;
    const int wn0 = (wid >> 1) * 32;

    const int a_row = (lane & 15);
    const int a_k   = (lane >> 4) << 3;
    const int b_row = (lane & 7) + ((lane >> 4) << 3);
    const int b_k   = ((lane >> 3) & 1) << 3;

    float cf[4][4][4];
    #pragma unroll
    for (int i = 0; i < 4; i++)
        #pragma unroll
        for (int j = 0; j < 4; j++)
            #pragma unroll
            for (int r = 0; r < 4; r++) cf[i][j][r] = 0.f;

    const int KC = K >> 5;

    auto stage = [&](int k0, int p) {
        #pragma unroll
        for (int ps = 0; ps < 2; ps++) {
            int s = tid + ps * 256;
            int row = s >> 2;
            int c16 = (s & 3) * 8;
            uint32_t doff = (uint32_t)(p * BUFH + row * BP + c16) * 2;
            cpa16(uA + doff, Ah + (size_t)(bm + row) * K + k0 + c16, 16);
            int gr = bn + row, sz = 16;
            if (EPI == 4 && gr >= N) { gr = 0; sz = 0; }
            cpa16(uBh + doff, Bh + (size_t)gr * K + k0 + c16, sz);
            if (EPI != 4)
                cpa16(uBl + doff, Bl + (size_t)gr * K + k0 + c16, sz);
        }
        CP_COMMIT();
    };

    stage(0, 0);

    for (int c = 0; c < KC; c++) {
        const int p = c & 1;
        CP_WAIT0();
        __syncthreads();
        if (c + 1 < KC) stage((c + 1) << 5, 1 - p);

        const uint32_t bufA  = uA  + (uint32_t)(p * BUFH) * 2;
        const uint32_t bufBh = uBh + (uint32_t)(p * BUFH) * 2;
        const uint32_t bufBl = uBl + (uint32_t)(p * BUFH) * 2;
        #pragma unroll
        for (int ks = 0; ks < 2; ks++) {
            const int k0 = ks * 16;
            uint32_t bh[4][2], bl[4][2];
            uint32_t bo = (uint32_t)((wn0 + b_row) * BP + k0 + b_k) * 2;
            ldmx4(bh[0][0], bh[0][1], bh[1][0], bh[1][1], bufBh + bo);
            ldmx4(bh[2][0], bh[2][1], bh[3][0], bh[3][1], bufBh + bo + 16 * BP * 2);
            if (EPI != 4) {
                ldmx4(bl[0][0], bl[0][1], bl[1][0], bl[1][1], bufBl + bo);
                ldmx4(bl[2][0], bl[2][1], bl[3][0], bl[3][1], bufBl + bo + 16 * BP * 2);
            }
            #pragma unroll
            for (int mt = 0; mt < 4; mt++) {
                uint32_t a[4];
                uint32_t ao = (uint32_t)((wm0 + mt * 16 + a_row) * BP + k0 + a_k) * 2;
                ldmx4(a[0], a[1], a[2], a[3], bufA + ao);
                #pragma unroll
                for (int nt = 0; nt < 4; nt++) {
                    mma_f16(cf[mt][nt], a, bh[nt]);
                    if (EPI != 4) mma_f16(cf[mt][nt], a, bl[nt]);
                }
            }
        }
    }

    // ---------------- epilogue ----------------
    #pragma unroll
    for (int mt = 0; mt < 4; mt++) {
        #pragma unroll
        for (int half = 0; half < 2; half++) {
            const int row = bm + wm0 + mt * 16 + grp + half * 8;
            #pragma unroll
            for (int nt = 0; nt < 4; nt++) {
                const int col = bn + wn0 + nt * 8 + 2 * tig;
                float v0 = cf[mt][nt][half * 2 + 0];
                float v1 = cf[mt][nt][half * 2 + 1];
                if (EPI == 4) {
                    float* C = (float*)Cv;
                    if (col < N)     C[(size_t)row * N + col]     = v0;
                    if (col + 1 < N) C[(size_t)row * N + col + 1] = v1;
                } else {
                    v0 += bias[col];
                    v1 += bias[col + 1];
                    if (EPI == 1) {
                        const float* rp = res + (size_t)row * N + col;
                        v0 += rp[0]; v1 += rp[1];
                        *(float2*)((float*)Cv + (size_t)row * N + col) = make_float2(v0, v1);
                    } else {
                        if (EPI == 2) { v0 = gelu_f(v0); v1 = gelu_f(v1); }
                        *(uint32_t*)((__half*)Cv + (size_t)row * N + col) = pack_f16(v0, v1);
                    }
                }
            }
        }
    }
}

// ------------------------------------ fp16 mma.sync flash attention (v3)
// Load-balanced: each block handles complementary Q tiles x and NT-1-x,
// giving constant (NT+1) KV-tile iterations per block.
#define APT 72
#define ATILE (64 * APT)
__global__ void __launch_bounds__(128)
attn_mma(const __half* __restrict__ qkv, __half* __restrict__ y) {
    extern __shared__ __half sh[];
    __half* sQ = sh;                  // [64][APT]
    __half* sK = sh + ATILE;          // 2 x [64][APT]
    __half* sV = sh + 3 * ATILE;      // 2 x [64][APT]
    const uint32_t uQ = (uint32_t)__cvta_generic_to_shared(sQ);
    const uint32_t uK = (uint32_t)__cvta_generic_to_shared(sK);
    const uint32_t uV = (uint32_t)__cvta_generic_to_shared(sV);

    const int NT = SEQ / 64;          // 16 Q tiles
    const int h = blockIdx.y, b = blockIdx.z;
    const int tid  = threadIdx.x;
    const int wid  = tid >> 5;
    const int lane = tid & 31;
    const int grp  = lane >> 2;
    const int tig  = lane & 3;
    const float scale = 0.036084391824351615f;  // 1/sqrt(768)

    const int a_row = lane & 15;
    const int a_k   = (lane >> 4) << 3;
    const int b_row = (lane & 7) + ((lane >> 4) << 3);
    const int b_k   = ((lane >> 3) & 1) << 3;

    auto stageKV = [&](int ks, int p) {
        #pragma unroll
        for (int ps = 0; ps < 4; ps++) {
            int s = tid + ps * 128;
            int row = s >> 3;
            int ch = (s & 7) * 8;
            const __half* base = qkv + ((size_t)b * SEQ + (size_t)ks * 64 + row) * QKVDIM
                               + h * HDIM + ch;
            uint32_t doff = (uint32_t)(p * ATILE + row * APT + ch) * 2;
            cpa16(uK + doff, base + EMB, 16);
            cpa16(uV + doff, base + 2 * EMB, 16);
        }
        CP_COMMIT();
    };

    #pragma unroll 1
    for (int qi = 0; qi < 2; qi++) {
        const int tq = qi == 0 ? (int)blockIdx.x : NT - 1 - (int)blockIdx.x;

        // ---- stage Q + KV(0) ----
        __syncthreads();   // previous phase's smem reads complete
        #pragma unroll
        for (int ps = 0; ps < 4; ps++) {
            int s = tid + ps * 128;
            int row = s >> 3;
            int ch = (s & 7) * 8;
            cpa16(uQ + (uint32_t)(row * APT + ch) * 2,
                  qkv + ((size_t)b * SEQ + (size_t)tq * 64 + row) * QKVDIM + h * HDIM + ch, 16);
        }
        CP_COMMIT();
        stageKV(0, 0);
        CP_WAIT0();
        __syncthreads();

        uint32_t qf[4][4];
        #pragma unroll
        for (int kt = 0; kt < 4; kt++) {
            uint32_t ao = (uint32_t)((wid * 16 + a_row) * APT + kt * 16 + a_k) * 2;
            ldmx4(qf[kt][0], qf[kt][1], qf[kt][2], qf[kt][3], uQ + ao);
        }

        float o[8][4];
        #pragma unroll
        for (int nt = 0; nt < 8; nt++)
            #pragma unroll
            for (int r = 0; r < 4; r++) o[nt][r] = 0.f;
        float m0 = -1e30f, m1 = -1e30f, l0 = 0.f, l1 = 0.f;

        const int row_g0 = tq * 64 + wid * 16 + grp;
        const int row_g1 = row_g0 + 8;

        for (int ks = 0; ks <= tq; ks++) {
            const int p = ks & 1;
            if (ks > 0) { CP_WAIT0(); __syncthreads(); }
            if (ks + 1 <= tq) stageKV(ks + 1, 1 - p);

            const uint32_t bufK = uK + (uint32_t)(p * ATILE) * 2;
            const uint32_t bufV = uV + (uint32_t)(p * ATILE) * 2;

            float s[8][4];
            #pragma unroll
            for (int nt = 0; nt < 8; nt++)
                #pragma unroll
                for (int r = 0; r < 4; r++) s[nt][r] = 0.f;
            #pragma unroll
            for (int kt = 0; kt < 4; kt++) {
                #pragma unroll
                for (int ntp = 0; ntp < 4; ntp++) {
                    uint32_t kb[2][2];
                    uint32_t bo = (uint32_t)((ntp * 16 + b_row) * APT + kt * 16 + b_k) * 2;
                    ldmx4(kb[0][0], kb[0][1], kb[1][0], kb[1][1], bufK + bo);
                    mma_f16(s[2 * ntp + 0], qf[kt], kb[0]);
                    mma_f16(s[2 * ntp + 1], qf[kt], kb[1]);
                }
            }

            const bool diag = (ks == tq);
            #pragma unroll
            for (int nt = 0; nt < 8; nt++) {
                int c = ks * 64 + nt * 8 + 2 * tig;
                #pragma unroll
                for (int r = 0; r < 4; r++) s[nt][r] *= scale;
                if (diag) {
                    if (c > row_g0)     s[nt][0] = -1e30f;
                    if (c + 1 > row_g0) s[nt][1] = -1e30f;
                    if (c > row_g1)     s[nt][2] = -1e30f;
                    if (c + 1 > row_g1) s[nt][3] = -1e30f;
                }
            }

            float t0 = -1e30f, t1 = -1e30f;
            #pragma unroll
            for (int nt = 0; nt < 8; nt++) {
                t0 = fmaxf(t0, fmaxf(s[nt][0], s[nt][1]));
                t1 = fmaxf(t1, fmaxf(s[nt][2], s[nt][3]));
            }
            #pragma unroll
            for (int off = 1; off < 4; off <<= 1) {
                t0 = fmaxf(t0, __shfl_xor_sync(0xffffffffu, t0, off));
                t1 = fmaxf(t1, __shfl_xor_sync(0xffffffffu, t1, off));
            }
            float nm0 = fmaxf(m0, t0), nm1 = fmaxf(m1, t1);
            float cr0 = __expf(m0 - nm0), cr1 = __expf(m1 - nm1);
            m0 = nm0; m1 = nm1;
            float rs0 = 0.f, rs1 = 0.f;
            uint32_t p01[8], p23[8];
            #pragma unroll
            for (int nt = 0; nt < 8; nt++) {
                float e0 = __expf(s[nt][0] - nm0);
                float e1 = __expf(s[nt][1] - nm0);
                float e2 = __expf(s[nt][2] - nm1);
                float e3 = __expf(s[nt][3] - nm1);
                rs0 += e0 + e1; rs1 += e2 + e3;
                p01[nt] = pack_f16(e0, e1);
                p23[nt] = pack_f16(e2, e3);
            }
            #pragma unroll
            for (int off = 1; off < 4; off <<= 1) {
                rs0 += __shfl_xor_sync(0xffffffffu, rs0, off);
                rs1 += __shfl_xor_sync(0xffffffffu, rs1, off);
            }
            l0 = l0 * cr0 + rs0;
            l1 = l1 * cr1 + rs1;
            #pragma unroll
            for (int nt = 0; nt < 8; nt++) {
                o[nt][0] *= cr0; o[nt][1] *= cr0;
                o[nt][2] *= cr1; o[nt][3] *= cr1;
            }

            #pragma unroll
            for (int kt = 0; kt < 4; kt++) {
                uint32_t a[4] = { p01[2 * kt], p23[2 * kt], p01[2 * kt + 1], p23[2 * kt + 1] };
                #pragma unroll
                for (int ntp = 0; ntp < 4; ntp++) {
                    uint32_t vb[2][2];
                    uint32_t vo = (uint32_t)((kt * 16 + a_row) * APT + ntp * 16 + a_k) * 2;
                    ldmx4t(vb[0][0], vb[0][1], vb[1][0], vb[1][1], bufV + vo);
                    mma_f16(o[2 * ntp + 0], a, vb[0]);
                    mma_f16(o[2 * ntp + 1], a, vb[1]);
                }
            }
        }

        float inv0 = 1.f / l0, inv1 = 1.f / l1;
        __half* y0 = y + ((size_t)b * SEQ + (size_t)tq * 64 + wid * 16 + grp) * EMB + h * HDIM;
        __half* y1 = y0 + 8 * EMB;
        #pragma unroll
        for (int nt = 0; nt < 8; nt++) {
            int c = nt * 8 + 2 * tig;
            *(uint32_t*)(y0 + c) = pack_f16(o[nt][0] * inv0, o[nt][1] * inv0);
            *(uint32_t*)(y1 + c) = pack_f16(o[nt][2] * inv1, o[nt][3] * inv1);
        }
    }
}

// -------------------------------------------------------------------- launch
extern "C" void kernel_launch(void* const* d_in, const int* in_sizes, int n_in,
                              void* d_out, int out_size) {
    const int*   tokens = (const int*)  d_in[0];
    const float* wte    = (const float*)d_in[1];
    const float* wpe    = (const float*)d_in[2];
    const float* ln1w   = (const float*)d_in[3];
    const float* ln1b   = (const float*)d_in[4];
    const float* qkvw   = (const float*)d_in[5];
    const float* qkvb   = (const float*)d_in[6];
    const float* atpw   = (const float*)d_in[7];
    const float* atpb   = (const float*)d_in[8];
    const float* ln2w   = (const float*)d_in[9];
    const float* ln2b   = (const float*)d_in[10];
    const float* fcw    = (const float*)d_in[11];
    const float* fcb    = (const float*)d_in[12];
    const float* fpw    = (const float*)d_in[13];
    const float* fpb    = (const float*)d_in[14];
    const float* lnfw   = (const float*)d_in[15];
    const float* lnfb   = (const float*)d_in[16];
    const float* lmw    = (const float*)d_in[17];
    float* out = (float*)d_out;

    float* px;
    __half *pah, *pqkvh, *pyh, *pmh;
    __half *qh, *ql, *ah, *al, *fh, *fl, *ph, *pl, *lh;
    cudaGetSymbolAddress((void**)&px,    g_x);
    cudaGetSymbolAddress((void**)&pah,   g_ah);
    cudaGetSymbolAddress((void**)&pqkvh, g_qkvh);
    cudaGetSymbolAddress((void**)&pyh,   g_yh);
    cudaGetSymbolAddress((void**)&pmh,   g_mh);
    cudaGetSymbolAddress((void**)&qh, g_qkvH); cudaGetSymbolAddress((void**)&ql, g_qkvL);
    cudaGetSymbolAddress((void**)&ah, g_atpH); cudaGetSymbolAddress((void**)&al, g_atpL);
    cudaGetSymbolAddress((void**)&fh, g_fcH);  cudaGetSymbolAddress((void**)&fl, g_fcL);
    cudaGetSymbolAddress((void**)&ph, g_fpH);  cudaGetSymbolAddress((void**)&pl, g_fpL);
    cudaGetSymbolAddress((void**)&lh, g_lmH);

    const int gsmem = 6 * BUFH * sizeof(__half);  // 61440
    cudaFuncSetAttribute(gemm_f16<0>, cudaFuncAttributeMaxDynamicSharedMemorySize, gsmem);
    cudaFuncSetAttribute(gemm_f16<1>, cudaFuncAttributeMaxDynamicSharedMemorySize, gsmem);
    cudaFuncSetAttribute(gemm_f16<2>, cudaFuncAttributeMaxDynamicSharedMemorySize, gsmem);
    cudaFuncSetAttribute(gemm_f16<4>, cudaFuncAttributeMaxDynamicSharedMemorySize, gsmem);

    const int asmem = 5 * ATILE * sizeof(__half);  // 46080
    cudaFuncSetAttribute(attn_mma, cudaFuncAttributeMaxDynamicSharedMemorySize, asmem);

    dim3 tb(32, 8);
    transpose_split_kernel<<<dim3(QKVDIM / 32, EMB / 32, NLAYER), tb>>>(qkvw, qh, ql, EMB, QKVDIM);
    transpose_split_kernel<<<dim3(EMB / 32,    EMB / 32, NLAYER), tb>>>(atpw, ah, al, EMB, EMB);
    transpose_split_kernel<<<dim3(FFDIM / 32,  EMB / 32, NLAYER), tb>>>(fcw,  fh, fl, EMB, FFDIM);
    transpose_split_kernel<<<dim3(EMB / 32,  FFDIM / 32, NLAYER), tb>>>(fpw,  ph, pl, FFDIM, EMB);
    cvt_kernel<<<(VOCAB * EMB + 255) / 256, 256>>>(lmw, lh, VOCAB * EMB);

    embed_kernel<<<(TOKENS * EMB + 255) / 256, 256>>>(tokens, wte, wpe, px);

    for (int i = 0; i < NLAYER; i++) {
        ln_kernel<<<TOKENS, 256>>>(px, ln1w + i * EMB, ln1b + i * EMB, pah);

        gemm_f16<0><<<dim3(QKVDIM / 128, TOKENS / 128), 256, gsmem>>>(
            pah, qh + (size_t)i * QKVDIM * EMB, ql + (size_t)i * QKVDIM * EMB,
            qkvb + i * QKVDIM, nullptr, pqkvh, TOKENS, QKVDIM, EMB);

        attn_mma<<<dim3(SEQ / 128, NHEAD, NBATCH), 128, asmem>>>(pqkvh, pyh);

        gemm_f16<1><<<dim3(EMB / 128, TOKENS / 128), 256, gsmem>>>(
            pyh, ah + (size_t)i * EMB * EMB, al + (size_t)i * EMB * EMB,
            atpb + i * EMB, px, px, TOKENS, EMB, EMB);

        ln_kernel<<<TOKENS, 256>>>(px, ln2w + i * EMB, ln2b + i * EMB, pah);

        gemm_f16<2><<<dim3(FFDIM / 128, TOKENS / 128), 256, gsmem>>>(
            pah, fh + (size_t)i * FFDIM * EMB, fl + (size_t)i * FFDIM * EMB,
            fcb + i * FFDIM, nullptr, pmh, TOKENS, FFDIM, EMB);

        gemm_f16<1><<<dim3(EMB / 128, TOKENS / 128), 256, gsmem>>>(
            pmh, ph + (size_t)i * EMB * FFDIM, pl + (size_t)i * EMB * FFDIM,
            fpb + i * EMB, px, px, TOKENS, EMB, FFDIM);
    }

    ln_kernel<<<TOKENS, 256>>>(px, lnfw, lnfb, pah);

    gemm_f16<4><<<dim3((VOCAB + 127) / 128, TOKENS / 128), 256, gsmem>>>(
        pah, lh, nullptr, nullptr, nullptr, out, TOKENS, VOCAB, EMB);
}

// round 10
// speedup vs baseline: 4.7093x; 1.0811x over previous
#include <cuda_runtime.h>
#include <cuda_fp16.h>
#include <math.h>
#include <stdint.h>

#define TOKENS 4096
#define EMB    768
#define NLAYER 12
#define NHEAD  12
#define HDIM   64
#define SEQ    1024
#define NBATCH 4
#define VOCAB  50257
#define FFDIM  3072
#define QKVDIM 2304

// -------------------- scratch (static device globals; no allocation) --------
__device__ float  g_x  [TOKENS * EMB];
__device__ __half g_ah [TOKENS * EMB];
__device__ __half g_qkvh[TOKENS * QKVDIM];
__device__ __half g_yh [TOKENS * EMB];
__device__ __half g_mh [TOKENS * FFDIM];
__device__ __half g_qkvH[(size_t)NLAYER * QKVDIM * EMB];
__device__ __half g_qkvL[(size_t)NLAYER * QKVDIM * EMB];
__device__ __half g_atpH[(size_t)NLAYER * EMB * EMB];
__device__ __half g_atpL[(size_t)NLAYER * EMB * EMB];
__device__ __half g_fcH [(size_t)NLAYER * FFDIM * EMB];
__device__ __half g_fcL [(size_t)NLAYER * FFDIM * EMB];
__device__ __half g_fpH [(size_t)NLAYER * EMB * FFDIM];
__device__ __half g_fpL [(size_t)NLAYER * EMB * FFDIM];
__device__ __half g_lmH [(size_t)VOCAB * EMB];

// ------------------------------------------------------------- helpers
__device__ __forceinline__ float gelu_f(float x) {
    float x3 = x * x * x;
    return 0.5f * x * (1.f + tanhf(0.7978845608028654f * (x + 0.044715f * x3)));
}
__device__ __forceinline__ uint32_t pack_f16(float x0, float x1) {
    uint32_t u;
    asm("{.reg .b16 l,h; cvt.rn.f16.f32 l,%1; cvt.rn.f16.f32 h,%2; mov.b32 %0,{l,h};}"
        : "=r"(u) : "f"(x0), "f"(x1));
    return u;
}
__device__ __forceinline__ void mma_f16(float* c, const uint32_t* a, const uint32_t* b) {
    asm volatile(
        "mma.sync.aligned.m16n8k16.row.col.f32.f16.f16.f32 "
        "{%0,%1,%2,%3}, {%4,%5,%6,%7}, {%8,%9}, {%0,%1,%2,%3};"
        : "+f"(c[0]), "+f"(c[1]), "+f"(c[2]), "+f"(c[3])
        : "r"(a[0]), "r"(a[1]), "r"(a[2]), "r"(a[3]), "r"(b[0]), "r"(b[1]));
}
__device__ __forceinline__ void ldmx4(uint32_t& r0, uint32_t& r1,
                                      uint32_t& r2, uint32_t& r3, uint32_t addr) {
    asm volatile("ldmatrix.sync.aligned.m8n8.x4.shared.b16 {%0,%1,%2,%3}, [%4];"
                 : "=r"(r0), "=r"(r1), "=r"(r2), "=r"(r3) : "r"(addr));
}
__device__ __forceinline__ void ldmx4t(uint32_t& r0, uint32_t& r1,
                                       uint32_t& r2, uint32_t& r3, uint32_t addr) {
    asm volatile("ldmatrix.sync.aligned.m8n8.x4.trans.shared.b16 {%0,%1,%2,%3}, [%4];"
                 : "=r"(r0), "=r"(r1), "=r"(r2), "=r"(r3) : "r"(addr));
}
__device__ __forceinline__ void cpa16(uint32_t dst, const void* src, int srcsz) {
    asm volatile("cp.async.ca.shared.global [%0], [%1], 16, %2;"
                 :: "r"(dst), "l"(src), "r"(srcsz) : "memory");
}
#define CP_COMMIT() asm volatile("cp.async.commit_group;" ::: "memory")
#define CP_WAIT0()  asm volatile("cp.async.wait_group 0;" ::: "memory")

// ---------------------------------------------------------------- embedding
__global__ void embed_kernel(const int* __restrict__ tok,
                             const float* __restrict__ wte,
                             const float* __restrict__ wpe,
                             float* __restrict__ x) {
    int idx = blockIdx.x * blockDim.x + threadIdx.x;
    if (idx >= TOKENS * EMB) return;
    int t = idx / EMB;
    int e = idx - t * EMB;
    x[idx] = wte[(size_t)tok[t] * EMB + e] + wpe[e];
}

// ------------------------------------------------ layernorm (fp16 output)
__global__ void ln_kernel(const float* __restrict__ x,
                          const float* __restrict__ w,
                          const float* __restrict__ bb,
                          __half* __restrict__ o) {
    int row = blockIdx.x;
    const float* xr = x + (size_t)row * EMB;
    int t = threadIdx.x;
    float v0 = xr[t], v1 = xr[t + 256], v2 = xr[t + 512];
    float s  = v0 + v1 + v2;
    float sq = v0 * v0 + v1 * v1 + v2 * v2;
    #pragma unroll
    for (int off = 16; off; off >>= 1) {
        s  += __shfl_xor_sync(0xffffffffu, s, off);
        sq += __shfl_xor_sync(0xffffffffu, sq, off);
    }
    __shared__ float rs[8], rq[8];
    __shared__ float s_mean, s_rstd;
    int wid = t >> 5;
    if ((t & 31) == 0) { rs[wid] = s; rq[wid] = sq; }
    __syncthreads();
    if (t == 0) {
        float S = 0.f, Q = 0.f;
        #pragma unroll
        for (int i = 0; i < 8; i++) { S += rs[i]; Q += rq[i]; }
        float mean = S * (1.f / EMB);
        s_mean = mean;
        s_rstd = rsqrtf(Q * (1.f / EMB) - mean * mean + 1e-5f);
    }
    __syncthreads();
    float mean = s_mean, rstd = s_rstd;
    __half* orow = o + (size_t)row * EMB;
    orow[t]       = __float2half_rn((v0 - mean) * rstd * w[t]       + bb[t]);
    orow[t + 256] = __float2half_rn((v1 - mean) * rstd * w[t + 256] + bb[t + 256]);
    orow[t + 512] = __float2half_rn((v2 - mean) * rstd * w[t + 512] + bb[t + 512]);
}

// --------------------------------------------- transpose + fp16 hi/lo split
__global__ void transpose_split_kernel(const float* __restrict__ in,
                                       __half* __restrict__ oh,
                                       __half* __restrict__ ol,
                                       int K, int N) {
    __shared__ float t[32][33];
    const size_t off = (size_t)blockIdx.z * K * N;
    int n0 = blockIdx.x * 32, k0 = blockIdx.y * 32;
    int x = threadIdx.x, y = threadIdx.y;
    #pragma unroll
    for (int i = 0; i < 32; i += 8)
        t[y + i][x] = in[off + (size_t)(k0 + y + i) * N + n0 + x];
    __syncthreads();
    #pragma unroll
    for (int i = 0; i < 32; i += 8) {
        float v = t[x][y + i];
        __half h = __float2half_rn(v);
        __half l = __float2half_rn(v - __half2float(h));
        size_t o = off + (size_t)(n0 + y + i) * K + k0 + x;
        oh[o] = h; ol[o] = l;
    }
}

// ---------------------------------------------- elementwise fp16 convert
__global__ void cvt_kernel(const float* __restrict__ in,
                           __half* __restrict__ oh, int n) {
    int i = blockIdx.x * blockDim.x + threadIdx.x;
    if (i >= n) return;
    oh[i] = __float2half_rn(in[i]);
}

// ------------------------------------------- fp16 mma.sync GEMM (k64 chunks)
// C[M,N] = A[M,K] @ B[N,K]^T.  A fp16 (producer-rounded).
// EPI 0: B=Bh+Bl, +bias -> half      | EPI 1: B=Bh+Bl, +bias+res(fp32) -> float
// EPI 2: B=Bh+Bl, +bias+gelu -> half | EPI 4: B=Bh only, plain, N-guard -> float
// Tile: 128 x NT (NT = 128 or 64), k-chunk 64, double-buffered cp.async.
#define BP 72                 // smem pitch in halves (144 B rows, conflict-free)
template <int EPI, int NT>
__global__ void __launch_bounds__(256, 2)
gemm_f16(const __half* __restrict__ Ah,
         const __half* __restrict__ Bh, const __half* __restrict__ Bl,
         const float* __restrict__ bias, const float* __restrict__ res,
         void* __restrict__ Cv, int M, int N, int K) {
    constexpr int ABUF = 128 * BP;
    constexpr int BBUF = NT * BP;
    constexpr int NBT  = NT / 32;      // mma n-tiles per warp (4 or 2)

    extern __shared__ __half sm[];
    __half* sA  = sm;                  // 2 x ABUF
    __half* sBh = sm + 2 * ABUF;       // 2 x BBUF
    __half* sBl = sBh + 2 * BBUF;      // 2 x BBUF (unused for EPI 4)
    const uint32_t uA  = (uint32_t)__cvta_generic_to_shared(sA);
    const uint32_t uBh = (uint32_t)__cvta_generic_to_shared(sBh);
    const uint32_t uBl = (uint32_t)__cvta_generic_to_shared(sBl);

    const int tid  = threadIdx.x;
    const int wid  = tid >> 5;
    const int lane = tid & 31;
    const int grp  = lane >> 2;
    const int tig  = lane & 3;
    const int bm = blockIdx.y * 128;
    const int bn = blockIdx.x * NT;
    const int wm0 = (wid & 1) * 64;
    const int wn0 = (wid >> 1) * (NT / 4);

    const int a_row = (lane & 15);
    const int a_k   = (lane >> 4) << 3;
    const int b_row = (lane & 7) + ((lane >> 4) << 3);
    const int b_k   = ((lane >> 3) & 1) << 3;

    float cf[4][NBT][4];
    #pragma unroll
    for (int i = 0; i < 4; i++)
        #pragma unroll
        for (int j = 0; j < NBT; j++)
            #pragma unroll
            for (int r = 0; r < 4; r++) cf[i][j][r] = 0.f;

    const int KC = K >> 6;   // 64-wide k chunks

    auto stage = [&](int k0, int p) {
        #pragma unroll
        for (int ps = 0; ps < 4; ps++) {
            int s = tid + ps * 256;
            int row = s >> 3;
            int c16 = (s & 7) * 8;
            uint32_t doff = (uint32_t)(p * ABUF + row * BP + c16) * 2;
            cpa16(uA + doff, Ah + (size_t)(bm + row) * K + k0 + c16, 16);
        }
        #pragma unroll
        for (int ps = 0; ps < NT / 32; ps++) {
            int s = tid + ps * 256;
            int row = s >> 3;
            int c16 = (s & 7) * 8;
            int gr = bn + row, sz = 16;
            if (EPI == 4 && gr >= N) { gr = 0; sz = 0; }
            uint32_t doff = (uint32_t)(p * BBUF + row * BP + c16) * 2;
            cpa16(uBh + doff, Bh + (size_t)gr * K + k0 + c16, sz);
            if (EPI != 4)
                cpa16(uBl + doff, Bl + (size_t)gr * K + k0 + c16, sz);
        }
        CP_COMMIT();
    };

    stage(0, 0);

    for (int c = 0; c < KC; c++) {
        const int p = c & 1;
        CP_WAIT0();
        __syncthreads();
        if (c + 1 < KC) stage((c + 1) << 6, 1 - p);

        const uint32_t bufA  = uA  + (uint32_t)(p * ABUF) * 2;
        const uint32_t bufBh = uBh + (uint32_t)(p * BBUF) * 2;
        const uint32_t bufBl = uBl + (uint32_t)(p * BBUF) * 2;
        #pragma unroll
        for (int ks = 0; ks < 4; ks++) {
            const int k0 = ks * 16;
            uint32_t bh[NBT][2], bl[NBT][2];
            uint32_t bo = (uint32_t)((wn0 + b_row) * BP + k0 + b_k) * 2;
            #pragma unroll
            for (int g = 0; g < NBT / 2; g++) {
                ldmx4(bh[2 * g][0], bh[2 * g][1], bh[2 * g + 1][0], bh[2 * g + 1][1],
                      bufBh + bo + (uint32_t)(g * 16 * BP) * 2);
                if (EPI != 4)
                    ldmx4(bl[2 * g][0], bl[2 * g][1], bl[2 * g + 1][0], bl[2 * g + 1][1],
                          bufBl + bo + (uint32_t)(g * 16 * BP) * 2);
            }
            #pragma unroll
            for (int mt = 0; mt < 4; mt++) {
                uint32_t a[4];
                uint32_t ao = (uint32_t)((wm0 + mt * 16 + a_row) * BP + k0 + a_k) * 2;
                ldmx4(a[0], a[1], a[2], a[3], bufA + ao);
                #pragma unroll
                for (int nt = 0; nt < NBT; nt++) {
                    mma_f16(cf[mt][nt], a, bh[nt]);
                    if (EPI != 4) mma_f16(cf[mt][nt], a, bl[nt]);
                }
            }
        }
    }

    // ---------------- epilogue ----------------
    #pragma unroll
    for (int mt = 0; mt < 4; mt++) {
        #pragma unroll
        for (int half = 0; half < 2; half++) {
            const int row = bm + wm0 + mt * 16 + grp + half * 8;
            #pragma unroll
            for (int nt = 0; nt < NBT; nt++) {
                const int col = bn + wn0 + nt * 8 + 2 * tig;
                float v0 = cf[mt][nt][half * 2 + 0];
                float v1 = cf[mt][nt][half * 2 + 1];
                if (EPI == 4) {
                    float* C = (float*)Cv;
                    if (col < N)     C[(size_t)row * N + col]     = v0;
                    if (col + 1 < N) C[(size_t)row * N + col + 1] = v1;
                } else {
                    v0 += bias[col];
                    v1 += bias[col + 1];
                    if (EPI == 1) {
                        const float* rp = res + (size_t)row * N + col;
                        v0 += rp[0]; v1 += rp[1];
                        *(float2*)((float*)Cv + (size_t)row * N + col) = make_float2(v0, v1);
                    } else {
                        if (EPI == 2) { v0 = gelu_f(v0); v1 = gelu_f(v1); }
                        *(uint32_t*)((__half*)Cv + (size_t)row * N + col) = pack_f16(v0, v1);
                    }
                }
            }
        }
    }
}

// ------------------------------------ fp16 mma.sync flash attention (v3)
// Load-balanced: block handles complementary Q tiles x and NT-1-x.
#define APT 72
#define ATILE (64 * APT)
__global__ void __launch_bounds__(128)
attn_mma(const __half* __restrict__ qkv, __half* __restrict__ y) {
    extern __shared__ __half sh[];
    __half* sQ = sh;
    __half* sK = sh + ATILE;
    __half* sV = sh + 3 * ATILE;
    const uint32_t uQ = (uint32_t)__cvta_generic_to_shared(sQ);
    const uint32_t uK = (uint32_t)__cvta_generic_to_shared(sK);
    const uint32_t uV = (uint32_t)__cvta_generic_to_shared(sV);

    const int NT = SEQ / 64;
    const int h = blockIdx.y, b = blockIdx.z;
    const int tid  = threadIdx.x;
    const int wid  = tid >> 5;
    const int lane = tid & 31;
    const int grp  = lane >> 2;
    const int tig  = lane & 3;
    const float scale = 0.036084391824351615f;  // 1/sqrt(768)

    const int a_row = lane & 15;
    const int a_k   = (lane >> 4) << 3;
    const int b_row = (lane & 7) + ((lane >> 4) << 3);
    const int b_k   = ((lane >> 3) & 1) << 3;

    auto stageKV = [&](int ks, int p) {
        #pragma unroll
        for (int ps = 0; ps < 4; ps++) {
            int s = tid + ps * 128;
            int row = s >> 3;
            int ch = (s & 7) * 8;
            const __half* base = qkv + ((size_t)b * SEQ + (size_t)ks * 64 + row) * QKVDIM
                               + h * HDIM + ch;
            uint32_t doff = (uint32_t)(p * ATILE + row * APT + ch) * 2;
            cpa16(uK + doff, base + EMB, 16);
            cpa16(uV + doff, base + 2 * EMB, 16);
        }
        CP_COMMIT();
    };

    #pragma unroll 1
    for (int qi = 0; qi < 2; qi++) {
        const int tq = qi == 0 ? (int)blockIdx.x : NT - 1 - (int)blockIdx.x;

        __syncthreads();
        #pragma unroll
        for (int ps = 0; ps < 4; ps++) {
            int s = tid + ps * 128;
            int row = s >> 3;
            int ch = (s & 7) * 8;
            cpa16(uQ + (uint32_t)(row * APT + ch) * 2,
                  qkv + ((size_t)b * SEQ + (size_t)tq * 64 + row) * QKVDIM + h * HDIM + ch, 16);
        }
        CP_COMMIT();
        stageKV(0, 0);
        CP_WAIT0();
        __syncthreads();

        uint32_t qf[4][4];
        #pragma unroll
        for (int kt = 0; kt < 4; kt++) {
            uint32_t ao = (uint32_t)((wid * 16 + a_row) * APT + kt * 16 + a_k) * 2;
            ldmx4(qf[kt][0], qf[kt][1], qf[kt][2], qf[kt][3], uQ + ao);
        }

        float o[8][4];
        #pragma unroll
        for (int nt = 0; nt < 8; nt++)
            #pragma unroll
            for (int r = 0; r < 4; r++) o[nt][r] = 0.f;
        float m0 = -1e30f, m1 = -1e30f, l0 = 0.f, l1 = 0.f;

        const int row_g0 = tq * 64 + wid * 16 + grp;
        const int row_g1 = row_g0 + 8;

        for (int ks = 0; ks <= tq; ks++) {
            const int p = ks & 1;
            if (ks > 0) { CP_WAIT0(); __syncthreads(); }
            if (ks + 1 <= tq) stageKV(ks + 1, 1 - p);

            const uint32_t bufK = uK + (uint32_t)(p * ATILE) * 2;
            const uint32_t bufV = uV + (uint32_t)(p * ATILE) * 2;

            float s[8][4];
            #pragma unroll
            for (int nt = 0; nt < 8; nt++)
                #pragma unroll
                for (int r = 0; r < 4; r++) s[nt][r] = 0.f;
            #pragma unroll
            for (int kt = 0; kt < 4; kt++) {
                #pragma unroll
                for (int ntp = 0; ntp < 4; ntp++) {
                    uint32_t kb[2][2];
                    uint32_t bo = (uint32_t)((ntp * 16 + b_row) * APT + kt * 16 + b_k) * 2;
                    ldmx4(kb[0][0], kb[0][1], kb[1][0], kb[1][1], bufK + bo);
                    mma_f16(s[2 * ntp + 0], qf[kt], kb[0]);
                    mma_f16(s[2 * ntp + 1], qf[kt], kb[1]);
                }
            }

            const bool diag = (ks == tq);
            #pragma unroll
            for (int nt = 0; nt < 8; nt++) {
                int c = ks * 64 + nt * 8 + 2 * tig;
                #pragma unroll
                for (int r = 0; r < 4; r++) s[nt][r] *= scale;
                if (diag) {
                    if (c > row_g0)     s[nt][0] = -1e30f;
                    if (c + 1 > row_g0) s[nt][1] = -1e30f;
                    if (c > row_g1)     s[nt][2] = -1e30f;
                    if (c + 1 > row_g1) s[nt][3] = -1e30f;
                }
            }

            float t0 = -1e30f, t1 = -1e30f;
            #pragma unroll
            for (int nt = 0; nt < 8; nt++) {
                t0 = fmaxf(t0, fmaxf(s[nt][0], s[nt][1]));
                t1 = fmaxf(t1, fmaxf(s[nt][2], s[nt][3]));
            }
            #pragma unroll
            for (int off = 1; off < 4; off <<= 1) {
                t0 = fmaxf(t0, __shfl_xor_sync(0xffffffffu, t0, off));
                t1 = fmaxf(t1, __shfl_xor_sync(0xffffffffu, t1, off));
            }
            float nm0 = fmaxf(m0, t0), nm1 = fmaxf(m1, t1);
            float cr0 = __expf(m0 - nm0), cr1 = __expf(m1 - nm1);
            m0 = nm0; m1 = nm1;
            float rs0 = 0.f, rs1 = 0.f;
            uint32_t p01[8], p23[8];
            #pragma unroll
            for (int nt = 0; nt < 8; nt++) {
                float e0 = __expf(s[nt][0] - nm0);
                float e1 = __expf(s[nt][1] - nm0);
                float e2 = __expf(s[nt][2] - nm1);
                float e3 = __expf(s[nt][3] - nm1);
                rs0 += e0 + e1; rs1 += e2 + e3;
                p01[nt] = pack_f16(e0, e1);
                p23[nt] = pack_f16(e2, e3);
            }
            #pragma unroll
            for (int off = 1; off < 4; off <<= 1) {
                rs0 += __shfl_xor_sync(0xffffffffu, rs0, off);
                rs1 += __shfl_xor_sync(0xffffffffu, rs1, off);
            }
            l0 = l0 * cr0 + rs0;
            l1 = l1 * cr1 + rs1;
            #pragma unroll
            for (int nt = 0; nt < 8; nt++) {
                o[nt][0] *= cr0; o[nt][1] *= cr0;
                o[nt][2] *= cr1; o[nt][3] *= cr1;
            }

            #pragma unroll
            for (int kt = 0; kt < 4; kt++) {
                uint32_t a[4] = { p01[2 * kt], p23[2 * kt], p01[2 * kt + 1], p23[2 * kt + 1] };
                #pragma unroll
                for (int ntp = 0; ntp < 4; ntp++) {
                    uint32_t vb[2][2];
                    uint32_t vo = (uint32_t)((kt * 16 + a_row) * APT + ntp * 16 + a_k) * 2;
                    ldmx4t(vb[0][0], vb[0][1], vb[1][0], vb[1][1], bufV + vo);
                    mma_f16(o[2 * ntp + 0], a, vb[0]);
                    mma_f16(o[2 * ntp + 1], a, vb[1]);
                }
            }
        }

        float inv0 = 1.f / l0, inv1 = 1.f / l1;
        __half* y0 = y + ((size_t)b * SEQ + (size_t)tq * 64 + wid * 16 + grp) * EMB + h * HDIM;
        __half* y1 = y0 + 8 * EMB;
        #pragma unroll
        for (int nt = 0; nt < 8; nt++) {
            int c = nt * 8 + 2 * tig;
            *(uint32_t*)(y0 + c) = pack_f16(o[nt][0] * inv0, o[nt][1] * inv0);
            *(uint32_t*)(y1 + c) = pack_f16(o[nt][2] * inv1, o[nt][3] * inv1);
        }
    }
}

// -------------------------------------------------------------------- launch
extern "C" void kernel_launch(void* const* d_in, const int* in_sizes, int n_in,
                              void* d_out, int out_size) {
    const int*   tokens = (const int*)  d_in[0];
    const float* wte    = (const float*)d_in[1];
    const float* wpe    = (const float*)d_in[2];
    const float* ln1w   = (const float*)d_in[3];
    const float* ln1b   = (const float*)d_in[4];
    const float* qkvw   = (const float*)d_in[5];
    const float* qkvb   = (const float*)d_in[6];
    const float* atpw   = (const float*)d_in[7];
    const float* atpb   = (const float*)d_in[8];
    const float* ln2w   = (const float*)d_in[9];
    const float* ln2b   = (const float*)d_in[10];
    const float* fcw    = (const float*)d_in[11];
    const float* fcb    = (const float*)d_in[12];
    const float* fpw    = (const float*)d_in[13];
    const float* fpb    = (const float*)d_in[14];
    const float* lnfw   = (const float*)d_in[15];
    const float* lnfb   = (const float*)d_in[16];
    const float* lmw    = (const float*)d_in[17];
    float* out = (float*)d_out;

    float* px;
    __half *pah, *pqkvh, *pyh, *pmh;
    __half *qh, *ql, *ah, *al, *fh, *fl, *ph, *pl, *lh;
    cudaGetSymbolAddress((void**)&px,    g_x);
    cudaGetSymbolAddress((void**)&pah,   g_ah);
    cudaGetSymbolAddress((void**)&pqkvh, g_qkvh);
    cudaGetSymbolAddress((void**)&pyh,   g_yh);
    cudaGetSymbolAddress((void**)&pmh,   g_mh);
    cudaGetSymbolAddress((void**)&qh, g_qkvH); cudaGetSymbolAddress((void**)&ql, g_qkvL);
    cudaGetSymbolAddress((void**)&ah, g_atpH); cudaGetSymbolAddress((void**)&al, g_atpL);
    cudaGetSymbolAddress((void**)&fh, g_fcH);  cudaGetSymbolAddress((void**)&fl, g_fcL);
    cudaGetSymbolAddress((void**)&ph, g_fpH);  cudaGetSymbolAddress((void**)&pl, g_fpL);
    cudaGetSymbolAddress((void**)&lh, g_lmH);

    // smem: A 2x128xBP; B(h,l or h only) 2xNTxBP each; halves * 2 bytes
    const int smem128s2 = (2 * 128 * BP + 4 * 128 * BP) * 2;  // 110592 (EPI 0/2, NT128)
    const int smem64s2  = (2 * 128 * BP + 4 * 64 * BP) * 2;   // 73728  (EPI 1,  NT64)
    const int smem128s1 = (2 * 128 * BP + 2 * 128 * BP) * 2;  // 73728  (EPI 4,  NT128)
    cudaFuncSetAttribute((gemm_f16<0, 128>), cudaFuncAttributeMaxDynamicSharedMemorySize, smem128s2);
    cudaFuncSetAttribute((gemm_f16<2, 128>), cudaFuncAttributeMaxDynamicSharedMemorySize, smem128s2);
    cudaFuncSetAttribute((gemm_f16<1, 64>),  cudaFuncAttributeMaxDynamicSharedMemorySize, smem64s2);
    cudaFuncSetAttribute((gemm_f16<4, 128>), cudaFuncAttributeMaxDynamicSharedMemorySize, smem128s1);

    const int asmem = 5 * ATILE * sizeof(__half);  // 46080
    cudaFuncSetAttribute(attn_mma, cudaFuncAttributeMaxDynamicSharedMemorySize, asmem);

    dim3 tb(32, 8);
    transpose_split_kernel<<<dim3(QKVDIM / 32, EMB / 32, NLAYER), tb>>>(qkvw, qh, ql, EMB, QKVDIM);
    transpose_split_kernel<<<dim3(EMB / 32,    EMB / 32, NLAYER), tb>>>(atpw, ah, al, EMB, EMB);
    transpose_split_kernel<<<dim3(FFDIM / 32,  EMB / 32, NLAYER), tb>>>(fcw,  fh, fl, EMB, FFDIM);
    transpose_split_kernel<<<dim3(EMB / 32,  FFDIM / 32, NLAYER), tb>>>(fpw,  ph, pl, FFDIM, EMB);
    cvt_kernel<<<(VOCAB * EMB + 255) / 256, 256>>>(lmw, lh, VOCAB * EMB);

    embed_kernel<<<(TOKENS * EMB + 255) / 256, 256>>>(tokens, wte, wpe, px);

    for (int i = 0; i < NLAYER; i++) {
        ln_kernel<<<TOKENS, 256>>>(px, ln1w + i * EMB, ln1b + i * EMB, pah);

        gemm_f16<0, 128><<<dim3(QKVDIM / 128, TOKENS / 128), 256, smem128s2>>>(
            pah, qh + (size_t)i * QKVDIM * EMB, ql + (size_t)i * QKVDIM * EMB,
            qkvb + i * QKVDIM, nullptr, pqkvh, TOKENS, QKVDIM, EMB);

        attn_mma<<<dim3(SEQ / 128, NHEAD, NBATCH), 128, asmem>>>(pqkvh, pyh);

        gemm_f16<1, 64><<<dim3(EMB / 64, TOKENS / 128), 256, smem64s2>>>(
            pyh, ah + (size_t)i * EMB * EMB, al + (size_t)i * EMB * EMB,
            atpb + i * EMB, px, px, TOKENS, EMB, EMB);

        ln_kernel<<<TOKENS, 256>>>(px, ln2w + i * EMB, ln2b + i * EMB, pah);

        gemm_f16<2, 128><<<dim3(FFDIM / 128, TOKENS / 128), 256, smem128s2>>>(
            pah, fh + (size_t)i * FFDIM * EMB, fl + (size_t)i * FFDIM * EMB,
            fcb + i * FFDIM, nullptr, pmh, TOKENS, FFDIM, EMB);

        gemm_f16<1, 64><<<dim3(EMB / 64, TOKENS / 128), 256, smem64s2>>>(
            pmh, ph + (size_t)i * EMB * FFDIM, pl + (size_t)i * EMB * FFDIM,
            fpb + i * EMB, px, px, TOKENS, EMB, FFDIM);
    }

    ln_kernel<<<TOKENS, 256>>>(px, lnfw, lnfb, pah);

    gemm_f16<4, 128><<<dim3((VOCAB + 127) / 128, TOKENS / 128), 256, smem128s1>>>(
        pah, lh, nullptr, nullptr, nullptr, out, TOKENS, VOCAB, EMB);
}

// round 11
// speedup vs baseline: 4.9131x; 1.0433x over previous
#include <cuda_runtime.h>
#include <cuda_fp16.h>
#include <math.h>
#include <stdint.h>

#define TOKENS 4096
#define EMB    768
#define NLAYER 12
#define NHEAD  12
#define HDIM   64
#define SEQ    1024
#define NBATCH 4
#define VOCAB  50257
#define FFDIM  3072
#define QKVDIM 2304

// -------------------- scratch (static device globals; no allocation) --------
__device__ float  g_x  [TOKENS * EMB];
__device__ __half g_ah [TOKENS * EMB];
__device__ __half g_qkvh[TOKENS * QKVDIM];
__device__ __half g_yh [TOKENS * EMB];
__device__ __half g_mh [TOKENS * FFDIM];
__device__ __half g_qkvH[(size_t)NLAYER * QKVDIM * EMB];
__device__ __half g_qkvL[(size_t)NLAYER * QKVDIM * EMB];
__device__ __half g_atpH[(size_t)NLAYER * EMB * EMB];
__device__ __half g_atpL[(size_t)NLAYER * EMB * EMB];
__device__ __half g_fcH [(size_t)NLAYER * FFDIM * EMB];
__device__ __half g_fcL [(size_t)NLAYER * FFDIM * EMB];
__device__ __half g_fpH [(size_t)NLAYER * EMB * FFDIM];
__device__ __half g_fpL [(size_t)NLAYER * EMB * FFDIM];
__device__ __half g_lmH [(size_t)VOCAB * EMB];

// ------------------------------------------------------------- helpers
__device__ __forceinline__ float gelu_f(float x) {
    float x3 = x * x * x;
    return 0.5f * x * (1.f + tanhf(0.7978845608028654f * (x + 0.044715f * x3)));
}
__device__ __forceinline__ uint32_t pack_f16(float x0, float x1) {
    uint32_t u;
    asm("{.reg .b16 l,h; cvt.rn.f16.f32 l,%1; cvt.rn.f16.f32 h,%2; mov.b32 %0,{l,h};}"
        : "=r"(u) : "f"(x0), "f"(x1));
    return u;
}
__device__ __forceinline__ void mma_f16(float* c, const uint32_t* a, const uint32_t* b) {
    asm volatile(
        "mma.sync.aligned.m16n8k16.row.col.f32.f16.f16.f32 "
        "{%0,%1,%2,%3}, {%4,%5,%6,%7}, {%8,%9}, {%0,%1,%2,%3};"
        : "+f"(c[0]), "+f"(c[1]), "+f"(c[2]), "+f"(c[3])
        : "r"(a[0]), "r"(a[1]), "r"(a[2]), "r"(a[3]), "r"(b[0]), "r"(b[1]));
}
__device__ __forceinline__ void ldmx4(uint32_t& r0, uint32_t& r1,
                                      uint32_t& r2, uint32_t& r3, uint32_t addr) {
    asm volatile("ldmatrix.sync.aligned.m8n8.x4.shared.b16 {%0,%1,%2,%3}, [%4];"
                 : "=r"(r0), "=r"(r1), "=r"(r2), "=r"(r3) : "r"(addr));
}
__device__ __forceinline__ void ldmx2(uint32_t& r0, uint32_t& r1, uint32_t addr) {
    asm volatile("ldmatrix.sync.aligned.m8n8.x2.shared.b16 {%0,%1}, [%2];"
                 : "=r"(r0), "=r"(r1) : "r"(addr));
}
__device__ __forceinline__ void ldmx4t(uint32_t& r0, uint32_t& r1,
                                       uint32_t& r2, uint32_t& r3, uint32_t addr) {
    asm volatile("ldmatrix.sync.aligned.m8n8.x4.trans.shared.b16 {%0,%1,%2,%3}, [%4];"
                 : "=r"(r0), "=r"(r1), "=r"(r2), "=r"(r3) : "r"(addr));
}
__device__ __forceinline__ void cpa16(uint32_t dst, const void* src, int srcsz) {
    asm volatile("cp.async.ca.shared.global [%0], [%1], 16, %2;"
                 :: "r"(dst), "l"(src), "r"(srcsz) : "memory");
}
#define CP_COMMIT() asm volatile("cp.async.commit_group;" ::: "memory")
#define CP_WAIT0()  asm volatile("cp.async.wait_group 0;" ::: "memory")

// ---------------------------------------------------------------- embedding
__global__ void embed_kernel(const int* __restrict__ tok,
                             const float* __restrict__ wte,
                             const float* __restrict__ wpe,
                             float* __restrict__ x) {
    int idx = blockIdx.x * blockDim.x + threadIdx.x;
    if (idx >= TOKENS * EMB) return;
    int t = idx / EMB;
    int e = idx - t * EMB;
    x[idx] = wte[(size_t)tok[t] * EMB + e] + wpe[e];
}

// --------------------------------- layernorm (warp-per-row, fp16 output)
// grid TOKENS/8, block 256 (8 warps), no __syncthreads.
__global__ void ln_kernel(const float* __restrict__ x,
                          const float* __restrict__ w,
                          const float* __restrict__ bb,
                          __half* __restrict__ o) {
    const int row  = blockIdx.x * 8 + (threadIdx.x >> 5);
    const int lane = threadIdx.x & 31;
    const float* xr = x + (size_t)row * EMB;

    float4 v[6];
    float s = 0.f, sq = 0.f;
    #pragma unroll
    for (int i = 0; i < 6; i++) {
        v[i] = *(const float4*)(xr + lane * 4 + i * 128);
        s  += v[i].x + v[i].y + v[i].z + v[i].w;
        sq += v[i].x * v[i].x + v[i].y * v[i].y
            + v[i].z * v[i].z + v[i].w * v[i].w;
    }
    #pragma unroll
    for (int off = 16; off; off >>= 1) {
        s  += __shfl_xor_sync(0xffffffffu, s, off);
        sq += __shfl_xor_sync(0xffffffffu, sq, off);
    }
    const float mean = s * (1.f / EMB);
    const float rstd = rsqrtf(sq * (1.f / EMB) - mean * mean + 1e-5f);

    __half* orow = o + (size_t)row * EMB;
    #pragma unroll
    for (int i = 0; i < 6; i++) {
        const int c = lane * 4 + i * 128;
        float4 wv = *(const float4*)(w + c);
        float4 bv = *(const float4*)(bb + c);
        float r0 = (v[i].x - mean) * rstd * wv.x + bv.x;
        float r1 = (v[i].y - mean) * rstd * wv.y + bv.y;
        float r2 = (v[i].z - mean) * rstd * wv.z + bv.z;
        float r3 = (v[i].w - mean) * rstd * wv.w + bv.w;
        *(uint2*)(orow + c) = make_uint2(pack_f16(r0, r1), pack_f16(r2, r3));
    }
}

// --------------------------------------------- transpose + fp16 hi/lo split
__global__ void transpose_split_kernel(const float* __restrict__ in,
                                       __half* __restrict__ oh,
                                       __half* __restrict__ ol,
                                       int K, int N) {
    __shared__ float t[32][33];
    const size_t off = (size_t)blockIdx.z * K * N;
    int n0 = blockIdx.x * 32, k0 = blockIdx.y * 32;
    int x = threadIdx.x, y = threadIdx.y;
    #pragma unroll
    for (int i = 0; i < 32; i += 8)
        t[y + i][x] = in[off + (size_t)(k0 + y + i) * N + n0 + x];
    __syncthreads();
    #pragma unroll
    for (int i = 0; i < 32; i += 8) {
        float v = t[x][y + i];
        __half h = __float2half_rn(v);
        __half l = __float2half_rn(v - __half2float(h));
        size_t o = off + (size_t)(n0 + y + i) * K + k0 + x;
        oh[o] = h; ol[o] = l;
    }
}

// ---------------------------------------------- elementwise fp16 convert
__global__ void cvt_kernel(const float* __restrict__ in,
                           __half* __restrict__ oh, int n) {
    int i = blockIdx.x * blockDim.x + threadIdx.x;
    if (i >= n) return;
    oh[i] = __float2half_rn(in[i]);
}

// ------------------------------------------- fp16 mma.sync GEMM (k64 chunks)
// C[M,N] = A[M,K] @ B[N,K]^T.  A fp16 (producer-rounded).
// EPI 0: B=Bh+Bl, +bias -> half      | EPI 1: B=Bh+Bl, +bias+res(fp32) -> float
// EPI 2: B=Bh+Bl, +bias+gelu -> half | EPI 4: B=Bh only, plain, N-guard -> float
// Tile: 128 x NT (NT in {128, 96}); NT must be divisible by 32.
#define BP 72                 // smem pitch in halves (144 B rows, conflict-free)
template <int EPI, int NT>
__global__ void __launch_bounds__(256, 2)
gemm_f16(const __half* __restrict__ Ah,
         const __half* __restrict__ Bh, const __half* __restrict__ Bl,
         const float* __restrict__ bias, const float* __restrict__ res,
         void* __restrict__ Cv, int M, int N, int K) {
    constexpr int ABUF = 128 * BP;
    constexpr int BBUF = NT * BP;
    constexpr int NBT  = NT / 32;      // mma n-tiles per warp (4, 3 or 2)

    extern __shared__ __half sm[];
    __half* sA  = sm;
    __half* sBh = sm + 2 * ABUF;
    __half* sBl = sBh + 2 * BBUF;
    const uint32_t uA  = (uint32_t)__cvta_generic_to_shared(sA);
    const uint32_t uBh = (uint32_t)__cvta_generic_to_shared(sBh);
    const uint32_t uBl = (uint32_t)__cvta_generic_to_shared(sBl);

    const int tid  = threadIdx.x;
    const int wid  = tid >> 5;
    const int lane = tid & 31;
    const int grp  = lane >> 2;
    const int tig  = lane & 3;
    const int bm = blockIdx.y * 128;
    const int bn = blockIdx.x * NT;
    const int wm0 = (wid & 1) * 64;
    const int wn0 = (wid >> 1) * (NT / 4);

    const int a_row = (lane & 15);
    const int a_k   = (lane >> 4) << 3;
    const int b_row = (lane & 7) + ((lane >> 4) << 3);
    const int b_k   = ((lane >> 3) & 1) << 3;
    // x2 variant (lanes 0-15 supply addresses; keep all lanes in-range)
    const int b2_row = lane & 7;
    const int b2_k   = ((lane >> 3) & 1) << 3;

    float cf[4][NBT][4];
    #pragma unroll
    for (int i = 0; i < 4; i++)
        #pragma unroll
        for (int j = 0; j < NBT; j++)
            #pragma unroll
            for (int r = 0; r < 4; r++) cf[i][j][r] = 0.f;

    const int KC = K >> 6;   // 64-wide k chunks

    auto stage = [&](int k0, int p) {
        #pragma unroll
        for (int ps = 0; ps < 4; ps++) {
            int s = tid + ps * 256;
            int row = s >> 3;
            int c16 = (s & 7) * 8;
            uint32_t doff = (uint32_t)(p * ABUF + row * BP + c16) * 2;
            cpa16(uA + doff, Ah + (size_t)(bm + row) * K + k0 + c16, 16);
        }
        #pragma unroll
        for (int ps = 0; ps < NT / 32; ps++) {
            int s = tid + ps * 256;
            int row = s >> 3;
            int c16 = (s & 7) * 8;
            int gr = bn + row, sz = 16;
            if (EPI == 4 && gr >= N) { gr = 0; sz = 0; }
            uint32_t doff = (uint32_t)(p * BBUF + row * BP + c16) * 2;
            cpa16(uBh + doff, Bh + (size_t)gr * K + k0 + c16, sz);
            if (EPI != 4)
                cpa16(uBl + doff, Bl + (size_t)gr * K + k0 + c16, sz);
        }
        CP_COMMIT();
    };

    stage(0, 0);

    for (int c = 0; c < KC; c++) {
        const int p = c & 1;
        CP_WAIT0();
        __syncthreads();
        if (c + 1 < KC) stage((c + 1) << 6, 1 - p);

        const uint32_t bufA  = uA  + (uint32_t)(p * ABUF) * 2;
        const uint32_t bufBh = uBh + (uint32_t)(p * BBUF) * 2;
        const uint32_t bufBl = uBl + (uint32_t)(p * BBUF) * 2;
        #pragma unroll
        for (int ks = 0; ks < 4; ks++) {
            const int k0 = ks * 16;
            uint32_t bh[NBT][2], bl[NBT][2];
            uint32_t bo = (uint32_t)((wn0 + b_row) * BP + k0 + b_k) * 2;
            #pragma unroll
            for (int g = 0; g < NBT / 2; g++) {
                ldmx4(bh[2 * g][0], bh[2 * g][1], bh[2 * g + 1][0], bh[2 * g + 1][1],
                      bufBh + bo + (uint32_t)(g * 16 * BP) * 2);
                if (EPI != 4)
                    ldmx4(bl[2 * g][0], bl[2 * g][1], bl[2 * g + 1][0], bl[2 * g + 1][1],
                          bufBl + bo + (uint32_t)(g * 16 * BP) * 2);
            }
            if (NBT & 1) {
                uint32_t bo2 = (uint32_t)((wn0 + (NBT - 1) * 8 + b2_row) * BP + k0 + b2_k) * 2;
                ldmx2(bh[NBT - 1][0], bh[NBT - 1][1], bufBh + bo2);
                if (EPI != 4)
                    ldmx2(bl[NBT - 1][0], bl[NBT - 1][1], bufBl + bo2);
            }
            #pragma unroll
            for (int mt = 0; mt < 4; mt++) {
                uint32_t a[4];
                uint32_t ao = (uint32_t)((wm0 + mt * 16 + a_row) * BP + k0 + a_k) * 2;
                ldmx4(a[0], a[1], a[2], a[3], bufA + ao);
                #pragma unroll
                for (int nt = 0; nt < NBT; nt++) {
                    mma_f16(cf[mt][nt], a, bh[nt]);
                    if (EPI != 4) mma_f16(cf[mt][nt], a, bl[nt]);
                }
            }
        }
    }

    // ---------------- epilogue ----------------
    #pragma unroll
    for (int mt = 0; mt < 4; mt++) {
        #pragma unroll
        for (int half = 0; half < 2; half++) {
            const int row = bm + wm0 + mt * 16 + grp + half * 8;
            #pragma unroll
            for (int nt = 0; nt < NBT; nt++) {
                const int col = bn + wn0 + nt * 8 + 2 * tig;
                float v0 = cf[mt][nt][half * 2 + 0];
                float v1 = cf[mt][nt][half * 2 + 1];
                if (EPI == 4) {
                    float* C = (float*)Cv;
                    if (col < N)     C[(size_t)row * N + col]     = v0;
                    if (col + 1 < N) C[(size_t)row * N + col + 1] = v1;
                } else {
                    v0 += bias[col];
                    v1 += bias[col + 1];
                    if (EPI == 1) {
                        const float* rp = res + (size_t)row * N + col;
                        v0 += rp[0]; v1 += rp[1];
                        *(float2*)((float*)Cv + (size_t)row * N + col) = make_float2(v0, v1);
                    } else {
                        if (EPI == 2) { v0 = gelu_f(v0); v1 = gelu_f(v1); }
                        *(uint32_t*)((__half*)Cv + (size_t)row * N + col) = pack_f16(v0, v1);
                    }
                }
            }
        }
    }
}

// ------------------------------------ fp16 mma.sync flash attention (v3)
#define APT 72
#define ATILE (64 * APT)
__global__ void __launch_bounds__(128)
attn_mma(const __half* __restrict__ qkv, __half* __restrict__ y) {
    extern __shared__ __half sh[];
    __half* sQ = sh;
    __half* sK = sh + ATILE;
    __half* sV = sh + 3 * ATILE;
    const uint32_t uQ = (uint32_t)__cvta_generic_to_shared(sQ);
    const uint32_t uK = (uint32_t)__cvta_generic_to_shared(sK);
    const uint32_t uV = (uint32_t)__cvta_generic_to_shared(sV);

    const int NT = SEQ / 64;
    const int h = blockIdx.y, b = blockIdx.z;
    const int tid  = threadIdx.x;
    const int wid  = tid >> 5;
    const int lane = tid & 31;
    const int grp  = lane >> 2;
    const int tig  = lane & 3;
    const float scale = 0.036084391824351615f;  // 1/sqrt(768)

    const int a_row = lane & 15;
    const int a_k   = (lane >> 4) << 3;
    const int b_row = (lane & 7) + ((lane >> 4) << 3);
    const int b_k   = ((lane >> 3) & 1) << 3;

    auto stageKV = [&](int ks, int p) {
        #pragma unroll
        for (int ps = 0; ps < 4; ps++) {
            int s = tid + ps * 128;
            int row = s >> 3;
            int ch = (s & 7) * 8;
            const __half* base = qkv + ((size_t)b * SEQ + (size_t)ks * 64 + row) * QKVDIM
                               + h * HDIM + ch;
            uint32_t doff = (uint32_t)(p * ATILE + row * APT + ch) * 2;
            cpa16(uK + doff, base + EMB, 16);
            cpa16(uV + doff, base + 2 * EMB, 16);
        }
        CP_COMMIT();
    };

    #pragma unroll 1
    for (int qi = 0; qi < 2; qi++) {
        const int tq = qi == 0 ? (int)blockIdx.x : NT - 1 - (int)blockIdx.x;

        __syncthreads();
        #pragma unroll
        for (int ps = 0; ps < 4; ps++) {
            int s = tid + ps * 128;
            int row = s >> 3;
            int ch = (s & 7) * 8;
            cpa16(uQ + (uint32_t)(row * APT + ch) * 2,
                  qkv + ((size_t)b * SEQ + (size_t)tq * 64 + row) * QKVDIM + h * HDIM + ch, 16);
        }
        CP_COMMIT();
        stageKV(0, 0);
        CP_WAIT0();
        __syncthreads();

        uint32_t qf[4][4];
        #pragma unroll
        for (int kt = 0; kt < 4; kt++) {
            uint32_t ao = (uint32_t)((wid * 16 + a_row) * APT + kt * 16 + a_k) * 2;
            ldmx4(qf[kt][0], qf[kt][1], qf[kt][2], qf[kt][3], uQ + ao);
        }

        float o[8][4];
        #pragma unroll
        for (int nt = 0; nt < 8; nt++)
            #pragma unroll
            for (int r = 0; r < 4; r++) o[nt][r] = 0.f;
        float m0 = -1e30f, m1 = -1e30f, l0 = 0.f, l1 = 0.f;

        const int row_g0 = tq * 64 + wid * 16 + grp;
        const int row_g1 = row_g0 + 8;

        for (int ks = 0; ks <= tq; ks++) {
            const int p = ks & 1;
            if (ks > 0) { CP_WAIT0(); __syncthreads(); }
            if (ks + 1 <= tq) stageKV(ks + 1, 1 - p);

            const uint32_t bufK = uK + (uint32_t)(p * ATILE) * 2;
            const uint32_t bufV = uV + (uint32_t)(p * ATILE) * 2;

            float s[8][4];
            #pragma unroll
            for (int nt = 0; nt < 8; nt++)
                #pragma unroll
                for (int r = 0; r < 4; r++) s[nt][r] = 0.f;
            #pragma unroll
            for (int kt = 0; kt < 4; kt++) {
                #pragma unroll
                for (int ntp = 0; ntp < 4; ntp++) {
                    uint32_t kb[2][2];
                    uint32_t bo = (uint32_t)((ntp * 16 + b_row) * APT + kt * 16 + b_k) * 2;
                    ldmx4(kb[0][0], kb[0][1], kb[1][0], kb[1][1], bufK + bo);
                    mma_f16(s[2 * ntp + 0], qf[kt], kb[0]);
                    mma_f16(s[2 * ntp + 1], qf[kt], kb[1]);
                }
            }

            const bool diag = (ks == tq);
            #pragma unroll
            for (int nt = 0; nt < 8; nt++) {
                int c = ks * 64 + nt * 8 + 2 * tig;
                #pragma unroll
                for (int r = 0; r < 4; r++) s[nt][r] *= scale;
                if (diag) {
                    if (c > row_g0)     s[nt][0] = -1e30f;
                    if (c + 1 > row_g0) s[nt][1] = -1e30f;
                    if (c > row_g1)     s[nt][2] = -1e30f;
                    if (c + 1 > row_g1) s[nt][3] = -1e30f;
                }
            }

            float t0 = -1e30f, t1 = -1e30f;
            #pragma unroll
            for (int nt = 0; nt < 8; nt++) {
                t0 = fmaxf(t0, fmaxf(s[nt][0], s[nt][1]));
                t1 = fmaxf(t1, fmaxf(s[nt][2], s[nt][3]));
            }
            #pragma unroll
            for (int off = 1; off < 4; off <<= 1) {
                t0 = fmaxf(t0, __shfl_xor_sync(0xffffffffu, t0, off));
                t1 = fmaxf(t1, __shfl_xor_sync(0xffffffffu, t1, off));
            }
            float nm0 = fmaxf(m0, t0), nm1 = fmaxf(m1, t1);
            float cr0 = __expf(m0 - nm0), cr1 = __expf(m1 - nm1);
            m0 = nm0; m1 = nm1;
            float rs0 = 0.f, rs1 = 0.f;
            uint32_t p01[8], p23[8];
            #pragma unroll
            for (int nt = 0; nt < 8; nt++) {
                float e0 = __expf(s[nt][0] - nm0);
                float e1 = __expf(s[nt][1] - nm0);
                float e2 = __expf(s[nt][2] - nm1);
                float e3 = __expf(s[nt][3] - nm1);
                rs0 += e0 + e1; rs1 += e2 + e3;
                p01[nt] = pack_f16(e0, e1);
                p23[nt] = pack_f16(e2, e3);
            }
            #pragma unroll
            for (int off = 1; off < 4; off <<= 1) {
                rs0 += __shfl_xor_sync(0xffffffffu, rs0, off);
                rs1 += __shfl_xor_sync(0xffffffffu, rs1, off);
            }
            l0 = l0 * cr0 + rs0;
            l1 = l1 * cr1 + rs1;
            #pragma unroll
            for (int nt = 0; nt < 8; nt++) {
                o[nt][0] *= cr0; o[nt][1] *= cr0;
                o[nt][2] *= cr1; o[nt][3] *= cr1;
            }

            #pragma unroll
            for (int kt = 0; kt < 4; kt++) {
                uint32_t a[4] = { p01[2 * kt], p23[2 * kt], p01[2 * kt + 1], p23[2 * kt + 1] };
                #pragma unroll
                for (int ntp = 0; ntp < 4; ntp++) {
                    uint32_t vb[2][2];
                    uint32_t vo = (uint32_t)((kt * 16 + a_row) * APT + ntp * 16 + a_k) * 2;
                    ldmx4t(vb[0][0], vb[0][1], vb[1][0], vb[1][1], bufV + vo);
                    mma_f16(o[2 * ntp + 0], a, vb[0]);
                    mma_f16(o[2 * ntp + 1], a, vb[1]);
                }
            }
        }

        float inv0 = 1.f / l0, inv1 = 1.f / l1;
        __half* y0 = y + ((size_t)b * SEQ + (size_t)tq * 64 + wid * 16 + grp) * EMB + h * HDIM;
        __half* y1 = y0 + 8 * EMB;
        #pragma unroll
        for (int nt = 0; nt < 8; nt++) {
            int c = nt * 8 + 2 * tig;
            *(uint32_t*)(y0 + c) = pack_f16(o[nt][0] * inv0, o[nt][1] * inv0);
            *(uint32_t*)(y1 + c) = pack_f16(o[nt][2] * inv1, o[nt][3] * inv1);
        }
    }
}

// -------------------------------------------------------------------- launch
extern "C" void kernel_launch(void* const* d_in, const int* in_sizes, int n_in,
                              void* d_out, int out_size) {
    const int*   tokens = (const int*)  d_in[0];
    const float* wte    = (const float*)d_in[1];
    const float* wpe    = (const float*)d_in[2];
    const float* ln1w   = (const float*)d_in[3];
    const float* ln1b   = (const float*)d_in[4];
    const float* qkvw   = (const float*)d_in[5];
    const float* qkvb   = (const float*)d_in[6];
    const float* atpw   = (const float*)d_in[7];
    const float* atpb   = (const float*)d_in[8];
    const float* ln2w   = (const float*)d_in[9];
    const float* ln2b   = (const float*)d_in[10];
    const float* fcw    = (const float*)d_in[11];
    const float* fcb    = (const float*)d_in[12];
    const float* fpw    = (const float*)d_in[13];
    const float* fpb    = (const float*)d_in[14];
    const float* lnfw   = (const float*)d_in[15];
    const float* lnfb   = (const float*)d_in[16];
    const float* lmw    = (const float*)d_in[17];
    float* out = (float*)d_out;

    float* px;
    __half *pah, *pqkvh, *pyh, *pmh;
    __half *qh, *ql, *ah, *al, *fh, *fl, *ph, *pl, *lh;
    cudaGetSymbolAddress((void**)&px,    g_x);
    cudaGetSymbolAddress((void**)&pah,   g_ah);
    cudaGetSymbolAddress((void**)&pqkvh, g_qkvh);
    cudaGetSymbolAddress((void**)&pyh,   g_yh);
    cudaGetSymbolAddress((void**)&pmh,   g_mh);
    cudaGetSymbolAddress((void**)&qh, g_qkvH); cudaGetSymbolAddress((void**)&ql, g_qkvL);
    cudaGetSymbolAddress((void**)&ah, g_atpH); cudaGetSymbolAddress((void**)&al, g_atpL);
    cudaGetSymbolAddress((void**)&fh, g_fcH);  cudaGetSymbolAddress((void**)&fl, g_fcL);
    cudaGetSymbolAddress((void**)&ph, g_fpH);  cudaGetSymbolAddress((void**)&pl, g_fpL);
    cudaGetSymbolAddress((void**)&lh, g_lmH);

    const int smem128s2 = (2 * 128 * BP + 4 * 128 * BP) * 2;  // 110592 (EPI 0/2, NT128)
    const int smem96s2  = (2 * 128 * BP + 4 * 96 * BP) * 2;   // 92160  (EPI 1,  NT96)
    const int smem128s1 = (2 * 128 * BP + 2 * 128 * BP) * 2;  // 73728  (EPI 4,  NT128)
    cudaFuncSetAttribute((gemm_f16<0, 128>), cudaFuncAttributeMaxDynamicSharedMemorySize, smem128s2);
    cudaFuncSetAttribute((gemm_f16<2, 128>), cudaFuncAttributeMaxDynamicSharedMemorySize, smem128s2);
    cudaFuncSetAttribute((gemm_f16<1, 96>),  cudaFuncAttributeMaxDynamicSharedMemorySize, smem96s2);
    cudaFuncSetAttribute((gemm_f16<4, 128>), cudaFuncAttributeMaxDynamicSharedMemorySize, smem128s1);

    const int asmem = 5 * ATILE * sizeof(__half);  // 46080
    cudaFuncSetAttribute(attn_mma, cudaFuncAttributeMaxDynamicSharedMemorySize, asmem);

    dim3 tb(32, 8);
    transpose_split_kernel<<<dim3(QKVDIM / 32, EMB / 32, NLAYER), tb>>>(qkvw, qh, ql, EMB, QKVDIM);
    transpose_split_kernel<<<dim3(EMB / 32,    EMB / 32, NLAYER), tb>>>(atpw, ah, al, EMB, EMB);
    transpose_split_kernel<<<dim3(FFDIM / 32,  EMB / 32, NLAYER), tb>>>(fcw,  fh, fl, EMB, FFDIM);
    transpose_split_kernel<<<dim3(EMB / 32,  FFDIM / 32, NLAYER), tb>>>(fpw,  ph, pl, FFDIM, EMB);
    cvt_kernel<<<(VOCAB * EMB + 255) / 256, 256>>>(lmw, lh, VOCAB * EMB);

    embed_kernel<<<(TOKENS * EMB + 255) / 256, 256>>>(tokens, wte, wpe, px);

    for (int i = 0; i < NLAYER; i++) {
        ln_kernel<<<TOKENS / 8, 256>>>(px, ln1w + i * EMB, ln1b + i * EMB, pah);

        gemm_f16<0, 128><<<dim3(QKVDIM / 128, TOKENS / 128), 256, smem128s2>>>(
            pah, qh + (size_t)i * QKVDIM * EMB, ql + (size_t)i * QKVDIM * EMB,
            qkvb + i * QKVDIM, nullptr, pqkvh, TOKENS, QKVDIM, EMB);

        attn_mma<<<dim3(SEQ / 128, NHEAD, NBATCH), 128, asmem>>>(pqkvh, pyh);

        gemm_f16<1, 96><<<dim3(EMB / 96, TOKENS / 128), 256, smem96s2>>>(
            pyh, ah + (size_t)i * EMB * EMB, al + (size_t)i * EMB * EMB,
            atpb + i * EMB, px, px, TOKENS, EMB, EMB);

        ln_kernel<<<TOKENS / 8, 256>>>(px, ln2w + i * EMB, ln2b + i * EMB, pah);

        gemm_f16<2, 128><<<dim3(FFDIM / 128, TOKENS / 128), 256, smem128s2>>>(
            pah, fh + (size_t)i * FFDIM * EMB, fl + (size_t)i * FFDIM * EMB,
            fcb + i * FFDIM, nullptr, pmh, TOKENS, FFDIM, EMB);

        gemm_f16<1, 96><<<dim3(EMB / 96, TOKENS / 128), 256, smem96s2>>>(
            pmh, ph + (size_t)i * EMB * FFDIM, pl + (size_t)i * EMB * FFDIM,
            fpb + i * EMB, px, px, TOKENS, EMB, FFDIM);
    }

    ln_kernel<<<TOKENS / 8, 256>>>(px, lnfw, lnfb, pah);

    gemm_f16<4, 128><<<dim3((VOCAB + 127) / 128, TOKENS / 128), 256, smem128s1>>>(
        pah, lh, nullptr, nullptr, nullptr, out, TOKENS, VOCAB, EMB);
}

// round 12
// speedup vs baseline: 5.3526x; 1.0895x over previous
#include <cuda_runtime.h>
#include <cuda_fp16.h>
#include <math.h>
#include <stdint.h>

#define TOKENS 4096
#define EMB    768
#define NLAYER 12
#define NHEAD  12
#define HDIM   64
#define SEQ    1024
#define NBATCH 4
#define VOCAB  50257
#define FFDIM  3072
#define QKVDIM 2304

// -------------------- scratch (static device globals; no allocation) --------
__device__ float  g_x  [TOKENS * EMB];
__device__ __half g_ah [TOKENS * EMB];
__device__ __half g_qkvh[TOKENS * QKVDIM];
__device__ __half g_yh [TOKENS * EMB];
__device__ __half g_mh [TOKENS * FFDIM];
__device__ __half g_qkvH[(size_t)NLAYER * QKVDIM * EMB];
__device__ __half g_atpH[(size_t)NLAYER * EMB * EMB];
__device__ __half g_atpL[(size_t)NLAYER * EMB * EMB];
__device__ __half g_fcH [(size_t)NLAYER * FFDIM * EMB];
__device__ __half g_fcL [(size_t)NLAYER * FFDIM * EMB];
__device__ __half g_fpH [(size_t)NLAYER * EMB * FFDIM];
__device__ __half g_fpL [(size_t)NLAYER * EMB * FFDIM];
__device__ __half g_lmH [(size_t)VOCAB * EMB];

// ------------------------------------------------------------- helpers
__device__ __forceinline__ float gelu_f(float x) {
    float x3 = x * x * x;
    return 0.5f * x * (1.f + tanhf(0.7978845608028654f * (x + 0.044715f * x3)));
}
__device__ __forceinline__ uint32_t pack_f16(float x0, float x1) {
    uint32_t u;
    asm("{.reg .b16 l,h; cvt.rn.f16.f32 l,%1; cvt.rn.f16.f32 h,%2; mov.b32 %0,{l,h};}"
        : "=r"(u) : "f"(x0), "f"(x1));
    return u;
}
__device__ __forceinline__ void mma_f16(float* c, const uint32_t* a, const uint32_t* b) {
    asm volatile(
        "mma.sync.aligned.m16n8k16.row.col.f32.f16.f16.f32 "
        "{%0,%1,%2,%3}, {%4,%5,%6,%7}, {%8,%9}, {%0,%1,%2,%3};"
        : "+f"(c[0]), "+f"(c[1]), "+f"(c[2]), "+f"(c[3])
        : "r"(a[0]), "r"(a[1]), "r"(a[2]), "r"(a[3]), "r"(b[0]), "r"(b[1]));
}
__device__ __forceinline__ void ldmx4(uint32_t& r0, uint32_t& r1,
                                      uint32_t& r2, uint32_t& r3, uint32_t addr) {
    asm volatile("ldmatrix.sync.aligned.m8n8.x4.shared.b16 {%0,%1,%2,%3}, [%4];"
                 : "=r"(r0), "=r"(r1), "=r"(r2), "=r"(r3) : "r"(addr));
}
__device__ __forceinline__ void ldmx2(uint32_t& r0, uint32_t& r1, uint32_t addr) {
    asm volatile("ldmatrix.sync.aligned.m8n8.x2.shared.b16 {%0,%1}, [%2];"
                 : "=r"(r0), "=r"(r1) : "r"(addr));
}
__device__ __forceinline__ void ldmx4t(uint32_t& r0, uint32_t& r1,
                                       uint32_t& r2, uint32_t& r3, uint32_t addr) {
    asm volatile("ldmatrix.sync.aligned.m8n8.x4.trans.shared.b16 {%0,%1,%2,%3}, [%4];"
                 : "=r"(r0), "=r"(r1), "=r"(r2), "=r"(r3) : "r"(addr));
}
__device__ __forceinline__ void cpa16(uint32_t dst, const void* src, int srcsz) {
    asm volatile("cp.async.ca.shared.global [%0], [%1], 16, %2;"
                 :: "r"(dst), "l"(src), "r"(srcsz) : "memory");
}
#define CP_COMMIT() asm volatile("cp.async.commit_group;" ::: "memory")
#define CP_WAIT0()  asm volatile("cp.async.wait_group 0;" ::: "memory")

// ---------------------------------------------------------------- embedding
__global__ void embed_kernel(const int* __restrict__ tok,
                             const float* __restrict__ wte,
                             const float* __restrict__ wpe,
                             float* __restrict__ x) {
    int idx = blockIdx.x * blockDim.x + threadIdx.x;
    if (idx >= TOKENS * EMB) return;
    int t = idx / EMB;
    int e = idx - t * EMB;
    x[idx] = wte[(size_t)tok[t] * EMB + e] + wpe[e];
}

// --------------------------------- layernorm (warp-per-row, fp16 output)
__global__ void ln_kernel(const float* __restrict__ x,
                          const float* __restrict__ w,
                          const float* __restrict__ bb,
                          __half* __restrict__ o) {
    const int row  = blockIdx.x * 8 + (threadIdx.x >> 5);
    const int lane = threadIdx.x & 31;
    const float* xr = x + (size_t)row * EMB;

    float4 v[6];
    float s = 0.f, sq = 0.f;
    #pragma unroll
    for (int i = 0; i < 6; i++) {
        v[i] = *(const float4*)(xr + lane * 4 + i * 128);
        s  += v[i].x + v[i].y + v[i].z + v[i].w;
        sq += v[i].x * v[i].x + v[i].y * v[i].y
            + v[i].z * v[i].z + v[i].w * v[i].w;
    }
    #pragma unroll
    for (int off = 16; off; off >>= 1) {
        s  += __shfl_xor_sync(0xffffffffu, s, off);
        sq += __shfl_xor_sync(0xffffffffu, sq, off);
    }
    const float mean = s * (1.f / EMB);
    const float rstd = rsqrtf(sq * (1.f / EMB) - mean * mean + 1e-5f);

    __half* orow = o + (size_t)row * EMB;
    #pragma unroll
    for (int i = 0; i < 6; i++) {
        const int c = lane * 4 + i * 128;
        float4 wv = *(const float4*)(w + c);
        float4 bv = *(const float4*)(bb + c);
        float r0 = (v[i].x - mean) * rstd * wv.x + bv.x;
        float r1 = (v[i].y - mean) * rstd * wv.y + bv.y;
        float r2 = (v[i].z - mean) * rstd * wv.z + bv.z;
        float r3 = (v[i].w - mean) * rstd * wv.w + bv.w;
        *(uint2*)(orow + c) = make_uint2(pack_f16(r0, r1), pack_f16(r2, r3));
    }
}

// --------------------------------------------- transpose + fp16 hi/lo split
__global__ void transpose_split_kernel(const float* __restrict__ in,
                                       __half* __restrict__ oh,
                                       __half* __restrict__ ol,
                                       int K, int N) {
    __shared__ float t[32][33];
    const size_t off = (size_t)blockIdx.z * K * N;
    int n0 = blockIdx.x * 32, k0 = blockIdx.y * 32;
    int x = threadIdx.x, y = threadIdx.y;
    #pragma unroll
    for (int i = 0; i < 32; i += 8)
        t[y + i][x] = in[off + (size_t)(k0 + y + i) * N + n0 + x];
    __syncthreads();
    #pragma unroll
    for (int i = 0; i < 32; i += 8) {
        float v = t[x][y + i];
        __half h = __float2half_rn(v);
        __half l = __float2half_rn(v - __half2float(h));
        size_t o = off + (size_t)(n0 + y + i) * K + k0 + x;
        oh[o] = h; ol[o] = l;
    }
}

// ------------------------------------------ transpose + fp16 (hi only)
__global__ void transpose_cvt_kernel(const float* __restrict__ in,
                                     __half* __restrict__ oh,
                                     int K, int N) {
    __shared__ float t[32][33];
    const size_t off = (size_t)blockIdx.z * K * N;
    int n0 = blockIdx.x * 32, k0 = blockIdx.y * 32;
    int x = threadIdx.x, y = threadIdx.y;
    #pragma unroll
    for (int i = 0; i < 32; i += 8)
        t[y + i][x] = in[off + (size_t)(k0 + y + i) * N + n0 + x];
    __syncthreads();
    #pragma unroll
    for (int i = 0; i < 32; i += 8)
        oh[off + (size_t)(n0 + y + i) * K + k0 + x] = __float2half_rn(t[x][y + i]);
}

// ---------------------------------------------- elementwise fp16 convert
__global__ void cvt_kernel(const float* __restrict__ in,
                           __half* __restrict__ oh, int n) {
    int i = blockIdx.x * blockDim.x + threadIdx.x;
    if (i >= n) return;
    oh[i] = __float2half_rn(in[i]);
}

// ------------------------------------------- fp16 mma.sync GEMM (k64 chunks)
// C[M,N] = A[M,K] @ B[N,K]^T.  A fp16 (producer-rounded).
// SPLIT: B = Bh + Bl (two MMAs) vs Bh only.
// EPI 0: +bias -> half | EPI 1: +bias+res(fp32) -> float
// EPI 2: +bias+gelu -> half | EPI 4: plain, N-guard -> float
#define BP 72
template <int EPI, int NT, bool SPLIT>
__global__ void __launch_bounds__(256, 2)
gemm_f16(const __half* __restrict__ Ah,
         const __half* __restrict__ Bh, const __half* __restrict__ Bl,
         const float* __restrict__ bias, const float* __restrict__ res,
         void* __restrict__ Cv, int M, int N, int K) {
    constexpr int ABUF = 128 * BP;
    constexpr int BBUF = NT * BP;
    constexpr int NBT  = NT / 32;

    extern __shared__ __half sm[];
    __half* sA  = sm;
    __half* sBh = sm + 2 * ABUF;
    __half* sBl = sBh + 2 * BBUF;
    const uint32_t uA  = (uint32_t)__cvta_generic_to_shared(sA);
    const uint32_t uBh = (uint32_t)__cvta_generic_to_shared(sBh);
    const uint32_t uBl = (uint32_t)__cvta_generic_to_shared(sBl);

    const int tid  = threadIdx.x;
    const int wid  = tid >> 5;
    const int lane = tid & 31;
    const int grp  = lane >> 2;
    const int tig  = lane & 3;
    const int bm = blockIdx.y * 128;
    const int bn = blockIdx.x * NT;
    const int wm0 = (wid & 1) * 64;
    const int wn0 = (wid >> 1) * (NT / 4);

    const int a_row = (lane & 15);
    const int a_k   = (lane >> 4) << 3;
    const int b_row = (lane & 7) + ((lane >> 4) << 3);
    const int b_k   = ((lane >> 3) & 1) << 3;
    const int b2_row = lane & 7;
    const int b2_k   = ((lane >> 3) & 1) << 3;

    float cf[4][NBT][4];
    #pragma unroll
    for (int i = 0; i < 4; i++)
        #pragma unroll
        for (int j = 0; j < NBT; j++)
            #pragma unroll
            for (int r = 0; r < 4; r++) cf[i][j][r] = 0.f;

    const int KC = K >> 6;

    auto stage = [&](int k0, int p) {
        #pragma unroll
        for (int ps = 0; ps < 4; ps++) {
            int s = tid + ps * 256;
            int row = s >> 3;
            int c16 = (s & 7) * 8;
            uint32_t doff = (uint32_t)(p * ABUF + row * BP + c16) * 2;
            cpa16(uA + doff, Ah + (size_t)(bm + row) * K + k0 + c16, 16);
        }
        #pragma unroll
        for (int ps = 0; ps < NT / 32; ps++) {
            int s = tid + ps * 256;
            int row = s >> 3;
            int c16 = (s & 7) * 8;
            int gr = bn + row, sz = 16;
            if (EPI == 4 && gr >= N) { gr = 0; sz = 0; }
            uint32_t doff = (uint32_t)(p * BBUF + row * BP + c16) * 2;
            cpa16(uBh + doff, Bh + (size_t)gr * K + k0 + c16, sz);
            if (SPLIT)
                cpa16(uBl + doff, Bl + (size_t)gr * K + k0 + c16, sz);
        }
        CP_COMMIT();
    };

    stage(0, 0);

    for (int c = 0; c < KC; c++) {
        const int p = c & 1;
        CP_WAIT0();
        __syncthreads();
        if (c + 1 < KC) stage((c + 1) << 6, 1 - p);

        const uint32_t bufA  = uA  + (uint32_t)(p * ABUF) * 2;
        const uint32_t bufBh = uBh + (uint32_t)(p * BBUF) * 2;
        const uint32_t bufBl = uBl + (uint32_t)(p * BBUF) * 2;
        #pragma unroll
        for (int ks = 0; ks < 4; ks++) {
            const int k0 = ks * 16;
            uint32_t bh[NBT][2], bl[NBT][2];
            uint32_t bo = (uint32_t)((wn0 + b_row) * BP + k0 + b_k) * 2;
            #pragma unroll
            for (int g = 0; g < NBT / 2; g++) {
                ldmx4(bh[2 * g][0], bh[2 * g][1], bh[2 * g + 1][0], bh[2 * g + 1][1],
                      bufBh + bo + (uint32_t)(g * 16 * BP) * 2);
                if (SPLIT)
                    ldmx4(bl[2 * g][0], bl[2 * g][1], bl[2 * g + 1][0], bl[2 * g + 1][1],
                          bufBl + bo + (uint32_t)(g * 16 * BP) * 2);
            }
            if (NBT & 1) {
                uint32_t bo2 = (uint32_t)((wn0 + (NBT - 1) * 8 + b2_row) * BP + k0 + b2_k) * 2;
                ldmx2(bh[NBT - 1][0], bh[NBT - 1][1], bufBh + bo2);
                if (SPLIT)
                    ldmx2(bl[NBT - 1][0], bl[NBT - 1][1], bufBl + bo2);
            }
            #pragma unroll
            for (int mt = 0; mt < 4; mt++) {
                uint32_t a[4];
                uint32_t ao = (uint32_t)((wm0 + mt * 16 + a_row) * BP + k0 + a_k) * 2;
                ldmx4(a[0], a[1], a[2], a[3], bufA + ao);
                #pragma unroll
                for (int nt = 0; nt < NBT; nt++) {
                    mma_f16(cf[mt][nt], a, bh[nt]);
                    if (SPLIT) mma_f16(cf[mt][nt], a, bl[nt]);
                }
            }
        }
    }

    // ---------------- epilogue ----------------
    #pragma unroll
    for (int mt = 0; mt < 4; mt++) {
        #pragma unroll
        for (int half = 0; half < 2; half++) {
            const int row = bm + wm0 + mt * 16 + grp + half * 8;
            #pragma unroll
            for (int nt = 0; nt < NBT; nt++) {
                const int col = bn + wn0 + nt * 8 + 2 * tig;
                float v0 = cf[mt][nt][half * 2 + 0];
                float v1 = cf[mt][nt][half * 2 + 1];
                if (EPI == 4) {
                    float* C = (float*)Cv;
                    if (col < N)     C[(size_t)row * N + col]     = v0;
                    if (col + 1 < N) C[(size_t)row * N + col + 1] = v1;
                } else {
                    v0 += bias[col];
                    v1 += bias[col + 1];
                    if (EPI == 1) {
                        const float* rp = res + (size_t)row * N + col;
                        v0 += rp[0]; v1 += rp[1];
                        *(float2*)((float*)Cv + (size_t)row * N + col) = make_float2(v0, v1);
                    } else {
                        if (EPI == 2) { v0 = gelu_f(v0); v1 = gelu_f(v1); }
                        *(uint32_t*)((__half*)Cv + (size_t)row * N + col) = pack_f16(v0, v1);
                    }
                }
            }
        }
    }
}

// ------------------------------------ fp16 mma.sync flash attention (v3)
#define APT 72
#define ATILE (64 * APT)
__global__ void __launch_bounds__(128)
attn_mma(const __half* __restrict__ qkv, __half* __restrict__ y) {
    extern __shared__ __half sh[];
    __half* sQ = sh;
    __half* sK = sh + ATILE;
    __half* sV = sh + 3 * ATILE;
    const uint32_t uQ = (uint32_t)__cvta_generic_to_shared(sQ);
    const uint32_t uK = (uint32_t)__cvta_generic_to_shared(sK);
    const uint32_t uV = (uint32_t)__cvta_generic_to_shared(sV);

    const int NT = SEQ / 64;
    const int h = blockIdx.y, b = blockIdx.z;
    const int tid  = threadIdx.x;
    const int wid  = tid >> 5;
    const int lane = tid & 31;
    const int grp  = lane >> 2;
    const int tig  = lane & 3;
    const float scale = 0.036084391824351615f;  // 1/sqrt(768)

    const int a_row = lane & 15;
    const int a_k   = (lane >> 4) << 3;
    const int b_row = (lane & 7) + ((lane >> 4) << 3);
    const int b_k   = ((lane >> 3) & 1) << 3;

    auto stageKV = [&](int ks, int p) {
        #pragma unroll
        for (int ps = 0; ps < 4; ps++) {
            int s = tid + ps * 128;
            int row = s >> 3;
            int ch = (s & 7) * 8;
            const __half* base = qkv + ((size_t)b * SEQ + (size_t)ks * 64 + row) * QKVDIM
                               + h * HDIM + ch;
            uint32_t doff = (uint32_t)(p * ATILE + row * APT + ch) * 2;
            cpa16(uK + doff, base + EMB, 16);
            cpa16(uV + doff, base + 2 * EMB, 16);
        }
        CP_COMMIT();
    };

    #pragma unroll 1
    for (int qi = 0; qi < 2; qi++) {
        const int tq = qi == 0 ? (int)blockIdx.x : NT - 1 - (int)blockIdx.x;

        __syncthreads();
        #pragma unroll
        for (int ps = 0; ps < 4; ps++) {
            int s = tid + ps * 128;
            int row = s >> 3;
            int ch = (s & 7) * 8;
            cpa16(uQ + (uint32_t)(row * APT + ch) * 2,
                  qkv + ((size_t)b * SEQ + (size_t)tq * 64 + row) * QKVDIM + h * HDIM + ch, 16);
        }
        CP_COMMIT();
        stageKV(0, 0);
        CP_WAIT0();
        __syncthreads();

        uint32_t qf[4][4];
        #pragma unroll
        for (int kt = 0; kt < 4; kt++) {
            uint32_t ao = (uint32_t)((wid * 16 + a_row) * APT + kt * 16 + a_k) * 2;
            ldmx4(qf[kt][0], qf[kt][1], qf[kt][2], qf[kt][3], uQ + ao);
        }

        float o[8][4];
        #pragma unroll
        for (int nt = 0; nt < 8; nt++)
            #pragma unroll
            for (int r = 0; r < 4; r++) o[nt][r] = 0.f;
        float m0 = -1e30f, m1 = -1e30f, l0 = 0.f, l1 = 0.f;

        const int row_g0 = tq * 64 + wid * 16 + grp;
        const int row_g1 = row_g0 + 8;

        for (int ks = 0; ks <= tq; ks++) {
            const int p = ks & 1;
            if (ks > 0) { CP_WAIT0(); __syncthreads(); }
            if (ks + 1 <= tq) stageKV(ks + 1, 1 - p);

            const uint32_t bufK = uK + (uint32_t)(p * ATILE) * 2;
            const uint32_t bufV = uV + (uint32_t)(p * ATILE) * 2;

            float s[8][4];
            #pragma unroll
            for (int nt = 0; nt < 8; nt++)
                #pragma unroll
                for (int r = 0; r < 4; r++) s[nt][r] = 0.f;
            #pragma unroll
            for (int kt = 0; kt < 4; kt++) {
                #pragma unroll
                for (int ntp = 0; ntp < 4; ntp++) {
                    uint32_t kb[2][2];
                    uint32_t bo = (uint32_t)((ntp * 16 + b_row) * APT + kt * 16 + b_k) * 2;
                    ldmx4(kb[0][0], kb[0][1], kb[1][0], kb[1][1], bufK + bo);
                    mma_f16(s[2 * ntp + 0], qf[kt], kb[0]);
                    mma_f16(s[2 * ntp + 1], qf[kt], kb[1]);
                }
            }

            const bool diag = (ks == tq);
            #pragma unroll
            for (int nt = 0; nt < 8; nt++) {
                int c = ks * 64 + nt * 8 + 2 * tig;
                #pragma unroll
                for (int r = 0; r < 4; r++) s[nt][r] *= scale;
                if (diag) {
                    if (c > row_g0)     s[nt][0] = -1e30f;
                    if (c + 1 > row_g0) s[nt][1] = -1e30f;
                    if (c > row_g1)     s[nt][2] = -1e30f;
                    if (c + 1 > row_g1) s[nt][3] = -1e30f;
                }
            }

            float t0 = -1e30f, t1 = -1e30f;
            #pragma unroll
            for (int nt = 0; nt < 8; nt++) {
                t0 = fmaxf(t0, fmaxf(s[nt][0], s[nt][1]));
                t1 = fmaxf(t1, fmaxf(s[nt][2], s[nt][3]));
            }
            #pragma unroll
            for (int off = 1; off < 4; off <<= 1) {
                t0 = fmaxf(t0, __shfl_xor_sync(0xffffffffu, t0, off));
                t1 = fmaxf(t1, __shfl_xor_sync(0xffffffffu, t1, off));
            }
            float nm0 = fmaxf(m0, t0), nm1 = fmaxf(m1, t1);
            float cr0 = __expf(m0 - nm0), cr1 = __expf(m1 - nm1);
            m0 = nm0; m1 = nm1;
            float rs0 = 0.f, rs1 = 0.f;
            uint32_t p01[8], p23[8];
            #pragma unroll
            for (int nt = 0; nt < 8; nt++) {
                float e0 = __expf(s[nt][0] - nm0);
                float e1 = __expf(s[nt][1] - nm0);
                float e2 = __expf(s[nt][2] - nm1);
                float e3 = __expf(s[nt][3] - nm1);
                rs0 += e0 + e1; rs1 += e2 + e3;
                p01[nt] = pack_f16(e0, e1);
                p23[nt] = pack_f16(e2, e3);
            }
            #pragma unroll
            for (int off = 1; off < 4; off <<= 1) {
                rs0 += __shfl_xor_sync(0xffffffffu, rs0, off);
                rs1 += __shfl_xor_sync(0xffffffffu, rs1, off);
            }
            l0 = l0 * cr0 + rs0;
            l1 = l1 * cr1 + rs1;
            #pragma unroll
            for (int nt = 0; nt < 8; nt++) {
                o[nt][0] *= cr0; o[nt][1] *= cr0;
                o[nt][2] *= cr1; o[nt][3] *= cr1;
            }

            #pragma unroll
            for (int kt = 0; kt < 4; kt++) {
                uint32_t a[4] = { p01[2 * kt], p23[2 * kt], p01[2 * kt + 1], p23[2 * kt + 1] };
                #pragma unroll
                for (int ntp = 0; ntp < 4; ntp++) {
                    uint32_t vb[2][2];
                    uint32_t vo = (uint32_t)((kt * 16 + a_row) * APT + ntp * 16 + a_k) * 2;
                    ldmx4t(vb[0][0], vb[0][1], vb[1][0], vb[1][1], bufV + vo);
                    mma_f16(o[2 * ntp + 0], a, vb[0]);
                    mma_f16(o[2 * ntp + 1], a, vb[1]);
                }
            }
        }

        float inv0 = 1.f / l0, inv1 = 1.f / l1;
        __half* y0 = y + ((size_t)b * SEQ + (size_t)tq * 64 + wid * 16 + grp) * EMB + h * HDIM;
        __half* y1 = y0 + 8 * EMB;
        #pragma unroll
        for (int nt = 0; nt < 8; nt++) {
            int c = nt * 8 + 2 * tig;
            *(uint32_t*)(y0 + c) = pack_f16(o[nt][0] * inv0, o[nt][1] * inv0);
            *(uint32_t*)(y1 + c) = pack_f16(o[nt][2] * inv1, o[nt][3] * inv1);
        }
    }
}

// -------------------------------------------------------------------- launch
extern "C" void kernel_launch(void* const* d_in, const int* in_sizes, int n_in,
                              void* d_out, int out_size) {
    const int*   tokens = (const int*)  d_in[0];
    const float* wte    = (const float*)d_in[1];
    const float* wpe    = (const float*)d_in[2];
    const float* ln1w   = (const float*)d_in[3];
    const float* ln1b   = (const float*)d_in[4];
    const float* qkvw   = (const float*)d_in[5];
    const float* qkvb   = (const float*)d_in[6];
    const float* atpw   = (const float*)d_in[7];
    const float* atpb   = (const float*)d_in[8];
    const float* ln2w   = (const float*)d_in[9];
    const float* ln2b   = (const float*)d_in[10];
    const float* fcw    = (const float*)d_in[11];
    const float* fcb    = (const float*)d_in[12];
    const float* fpw    = (const float*)d_in[13];
    const float* fpb    = (const float*)d_in[14];
    const float* lnfw   = (const float*)d_in[15];
    const float* lnfb   = (const float*)d_in[16];
    const float* lmw    = (const float*)d_in[17];
    float* out = (float*)d_out;

    float* px;
    __half *pah, *pqkvh, *pyh, *pmh;
    __half *qh, *ah, *al, *fh, *fl, *ph, *pl, *lh;
    cudaGetSymbolAddress((void**)&px,    g_x);
    cudaGetSymbolAddress((void**)&pah,   g_ah);
    cudaGetSymbolAddress((void**)&pqkvh, g_qkvh);
    cudaGetSymbolAddress((void**)&pyh,   g_yh);
    cudaGetSymbolAddress((void**)&pmh,   g_mh);
    cudaGetSymbolAddress((void**)&qh, g_qkvH);
    cudaGetSymbolAddress((void**)&ah, g_atpH); cudaGetSymbolAddress((void**)&al, g_atpL);
    cudaGetSymbolAddress((void**)&fh, g_fcH);  cudaGetSymbolAddress((void**)&fl, g_fcL);
    cudaGetSymbolAddress((void**)&ph, g_fpH);  cudaGetSymbolAddress((void**)&pl, g_fpL);
    cudaGetSymbolAddress((void**)&lh, g_lmH);

    const int smem128s2 = (2 * 128 * BP + 4 * 128 * BP) * 2;  // 110592 (fc, split)
    const int smem96s2  = (2 * 128 * BP + 4 * 96 * BP) * 2;   // 92160  (proj/fp, split)
    const int smem128s1 = (2 * 128 * BP + 2 * 128 * BP) * 2;  // 73728  (qkv, lm)
    cudaFuncSetAttribute((gemm_f16<0, 128, false>), cudaFuncAttributeMaxDynamicSharedMemorySize, smem128s1);
    cudaFuncSetAttribute((gemm_f16<2, 128, true>),  cudaFuncAttributeMaxDynamicSharedMemorySize, smem128s2);
    cudaFuncSetAttribute((gemm_f16<1, 96, true>),   cudaFuncAttributeMaxDynamicSharedMemorySize, smem96s2);
    cudaFuncSetAttribute((gemm_f16<4, 128, false>), cudaFuncAttributeMaxDynamicSharedMemorySize, smem128s1);

    const int asmem = 5 * ATILE * sizeof(__half);  // 46080
    cudaFuncSetAttribute(attn_mma, cudaFuncAttributeMaxDynamicSharedMemorySize, asmem);

    dim3 tb(32, 8);
    transpose_cvt_kernel<<<dim3(QKVDIM / 32, EMB / 32, NLAYER), tb>>>(qkvw, qh, EMB, QKVDIM);
    transpose_split_kernel<<<dim3(EMB / 32,    EMB / 32, NLAYER), tb>>>(atpw, ah, al, EMB, EMB);
    transpose_split_kernel<<<dim3(FFDIM / 32,  EMB / 32, NLAYER), tb>>>(fcw,  fh, fl, EMB, FFDIM);
    transpose_split_kernel<<<dim3(EMB / 32,  FFDIM / 32, NLAYER), tb>>>(fpw,  ph, pl, FFDIM, EMB);
    cvt_kernel<<<(VOCAB * EMB + 255) / 256, 256>>>(lmw, lh, VOCAB * EMB);

    embed_kernel<<<(TOKENS * EMB + 255) / 256, 256>>>(tokens, wte, wpe, px);

    for (int i = 0; i < NLAYER; i++) {
        ln_kernel<<<TOKENS / 8, 256>>>(px, ln1w + i * EMB, ln1b + i * EMB, pah);

        gemm_f16<0, 128, false><<<dim3(QKVDIM / 128, TOKENS / 128), 256, smem128s1>>>(
            pah, qh + (size_t)i * QKVDIM * EMB, nullptr,
            qkvb + i * QKVDIM, nullptr, pqkvh, TOKENS, QKVDIM, EMB);

        attn_mma<<<dim3(SEQ / 128, NHEAD, NBATCH), 128, asmem>>>(pqkvh, pyh);

        gemm_f16<1, 96, true><<<dim3(EMB / 96, TOKENS / 128), 256, smem96s2>>>(
            pyh, ah + (size_t)i * EMB * EMB, al + (size_t)i * EMB * EMB,
            atpb + i * EMB, px, px, TOKENS, EMB, EMB);

        ln_kernel<<<TOKENS / 8, 256>>>(px, ln2w + i * EMB, ln2b + i * EMB, pah);

        gemm_f16<2, 128, true><<<dim3(FFDIM / 128, TOKENS / 128), 256, smem128s2>>>(
            pah, fh + (size_t)i * FFDIM * EMB, fl + (size_t)i * FFDIM * EMB,
            fcb + i * FFDIM, nullptr, pmh, TOKENS, FFDIM, EMB);

        gemm_f16<1, 96, true><<<dim3(EMB / 96, TOKENS / 128), 256, smem96s2>>>(
            pmh, ph + (size_t)i * EMB * FFDIM, pl + (size_t)i * EMB * FFDIM,
            fpb + i * EMB, px, px, TOKENS, EMB, FFDIM);
    }

    ln_kernel<<<TOKENS / 8, 256>>>(px, lnfw, lnfb, pah);

    gemm_f16<4, 128, false><<<dim3((VOCAB + 127) / 128, TOKENS / 128), 256, smem128s1>>>(
        pah, lh, nullptr, nullptr, nullptr, out, TOKENS, VOCAB, EMB);
}

// round 13
// speedup vs baseline: 5.8084x; 1.0852x over previous
#include <cuda_runtime.h>
#include <cuda_fp16.h>
#include <math.h>
#include <stdint.h>

#define TOKENS 4096
#define EMB    768
#define NLAYER 12
#define NHEAD  12
#define HDIM   64
#define SEQ    1024
#define NBATCH 4
#define VOCAB  50257
#define FFDIM  3072
#define QKVDIM 2304

// -------------------- scratch (static device globals; no allocation) --------
__device__ float  g_x  [TOKENS * EMB];
__device__ __half g_ah [TOKENS * EMB];
__device__ __half g_qkvh[TOKENS * QKVDIM];
__device__ __half g_yh [TOKENS * EMB];
__device__ __half g_mh [TOKENS * FFDIM];
__device__ __half g_qkvH[(size_t)NLAYER * QKVDIM * EMB];
__device__ __half g_atpH[(size_t)NLAYER * EMB * EMB];
__device__ __half g_atpL[(size_t)NLAYER * EMB * EMB];
__device__ __half g_fcH [(size_t)NLAYER * FFDIM * EMB];
__device__ __half g_fcL [(size_t)NLAYER * FFDIM * EMB];
__device__ __half g_fpH [(size_t)NLAYER * EMB * FFDIM];
__device__ __half g_lmH [(size_t)VOCAB * EMB];

// ------------------------------------------------------------- helpers
__device__ __forceinline__ float gelu_f(float x) {
    float x3 = x * x * x;
    return 0.5f * x * (1.f + tanhf(0.7978845608028654f * (x + 0.044715f * x3)));
}
__device__ __forceinline__ uint32_t pack_f16(float x0, float x1) {
    uint32_t u;
    asm("{.reg .b16 l,h; cvt.rn.f16.f32 l,%1; cvt.rn.f16.f32 h,%2; mov.b32 %0,{l,h};}"
        : "=r"(u) : "f"(x0), "f"(x1));
    return u;
}
__device__ __forceinline__ void mma_f16(float* c, const uint32_t* a, const uint32_t* b) {
    asm volatile(
        "mma.sync.aligned.m16n8k16.row.col.f32.f16.f16.f32 "
        "{%0,%1,%2,%3}, {%4,%5,%6,%7}, {%8,%9}, {%0,%1,%2,%3};"
        : "+f"(c[0]), "+f"(c[1]), "+f"(c[2]), "+f"(c[3])
        : "r"(a[0]), "r"(a[1]), "r"(a[2]), "r"(a[3]), "r"(b[0]), "r"(b[1]));
}
__device__ __forceinline__ void ldmx4(uint32_t& r0, uint32_t& r1,
                                      uint32_t& r2, uint32_t& r3, uint32_t addr) {
    asm volatile("ldmatrix.sync.aligned.m8n8.x4.shared.b16 {%0,%1,%2,%3}, [%4];"
                 : "=r"(r0), "=r"(r1), "=r"(r2), "=r"(r3) : "r"(addr));
}
__device__ __forceinline__ void ldmx2(uint32_t& r0, uint32_t& r1, uint32_t addr) {
    asm volatile("ldmatrix.sync.aligned.m8n8.x2.shared.b16 {%0,%1}, [%2];"
                 : "=r"(r0), "=r"(r1) : "r"(addr));
}
__device__ __forceinline__ void ldmx4t(uint32_t& r0, uint32_t& r1,
                                       uint32_t& r2, uint32_t& r3, uint32_t addr) {
    asm volatile("ldmatrix.sync.aligned.m8n8.x4.trans.shared.b16 {%0,%1,%2,%3}, [%4];"
                 : "=r"(r0), "=r"(r1), "=r"(r2), "=r"(r3) : "r"(addr));
}
__device__ __forceinline__ void cpa16(uint32_t dst, const void* src, int srcsz) {
    asm volatile("cp.async.ca.shared.global [%0], [%1], 16, %2;"
                 :: "r"(dst), "l"(src), "r"(srcsz) : "memory");
}
#define CP_COMMIT() asm volatile("cp.async.commit_group;" ::: "memory")
#define CP_WAIT0()  asm volatile("cp.async.wait_group 0;" ::: "memory")

// ---------------------------------------------------------------- embedding
__global__ void embed_kernel(const int* __restrict__ tok,
                             const float* __restrict__ wte,
                             const float* __restrict__ wpe,
                             float* __restrict__ x) {
    int idx = blockIdx.x * blockDim.x + threadIdx.x;
    if (idx >= TOKENS * EMB) return;
    int t = idx / EMB;
    int e = idx - t * EMB;
    x[idx] = wte[(size_t)tok[t] * EMB + e] + wpe[e];
}

// --------------------------------- layernorm (warp-per-row, fp16 output)
__global__ void ln_kernel(const float* __restrict__ x,
                          const float* __restrict__ w,
                          const float* __restrict__ bb,
                          __half* __restrict__ o) {
    const int row  = blockIdx.x * 8 + (threadIdx.x >> 5);
    const int lane = threadIdx.x & 31;
    const float* xr = x + (size_t)row * EMB;

    float4 v[6];
    float s = 0.f, sq = 0.f;
    #pragma unroll
    for (int i = 0; i < 6; i++) {
        v[i] = *(const float4*)(xr + lane * 4 + i * 128);
        s  += v[i].x + v[i].y + v[i].z + v[i].w;
        sq += v[i].x * v[i].x + v[i].y * v[i].y
            + v[i].z * v[i].z + v[i].w * v[i].w;
    }
    #pragma unroll
    for (int off = 16; off; off >>= 1) {
        s  += __shfl_xor_sync(0xffffffffu, s, off);
        sq += __shfl_xor_sync(0xffffffffu, sq, off);
    }
    const float mean = s * (1.f / EMB);
    const float rstd = rsqrtf(sq * (1.f / EMB) - mean * mean + 1e-5f);

    __half* orow = o + (size_t)row * EMB;
    #pragma unroll
    for (int i = 0; i < 6; i++) {
        const int c = lane * 4 + i * 128;
        float4 wv = *(const float4*)(w + c);
        float4 bv = *(const float4*)(bb + c);
        float r0 = (v[i].x - mean) * rstd * wv.x + bv.x;
        float r1 = (v[i].y - mean) * rstd * wv.y + bv.y;
        float r2 = (v[i].z - mean) * rstd * wv.z + bv.z;
        float r3 = (v[i].w - mean) * rstd * wv.w + bv.w;
        *(uint2*)(orow + c) = make_uint2(pack_f16(r0, r1), pack_f16(r2, r3));
    }
}

// --------------------------------------------- transpose + fp16 hi/lo split
__global__ void transpose_split_kernel(const float* __restrict__ in,
                                       __half* __restrict__ oh,
                                       __half* __restrict__ ol,
                                       int K, int N) {
    __shared__ float t[32][33];
    const size_t off = (size_t)blockIdx.z * K * N;
    int n0 = blockIdx.x * 32, k0 = blockIdx.y * 32;
    int x = threadIdx.x, y = threadIdx.y;
    #pragma unroll
    for (int i = 0; i < 32; i += 8)
        t[y + i][x] = in[off + (size_t)(k0 + y + i) * N + n0 + x];
    __syncthreads();
    #pragma unroll
    for (int i = 0; i < 32; i += 8) {
        float v = t[x][y + i];
        __half h = __float2half_rn(v);
        __half l = __float2half_rn(v - __half2float(h));
        size_t o = off + (size_t)(n0 + y + i) * K + k0 + x;
        oh[o] = h; ol[o] = l;
    }
}

// ------------------------------------------ transpose + fp16 (hi only)
__global__ void transpose_cvt_kernel(const float* __restrict__ in,
                                     __half* __restrict__ oh,
                                     int K, int N) {
    __shared__ float t[32][33];
    const size_t off = (size_t)blockIdx.z * K * N;
    int n0 = blockIdx.x * 32, k0 = blockIdx.y * 32;
    int x = threadIdx.x, y = threadIdx.y;
    #pragma unroll
    for (int i = 0; i < 32; i += 8)
        t[y + i][x] = in[off + (size_t)(k0 + y + i) * N + n0 + x];
    __syncthreads();
    #pragma unroll
    for (int i = 0; i < 32; i += 8)
        oh[off + (size_t)(n0 + y + i) * K + k0 + x] = __float2half_rn(t[x][y + i]);
}

// ---------------------------------------------- elementwise fp16 convert
__global__ void cvt_kernel(const float* __restrict__ in,
                           __half* __restrict__ oh, int n) {
    int i = blockIdx.x * blockDim.x + threadIdx.x;
    if (i >= n) return;
    oh[i] = __float2half_rn(in[i]);
}

// ------------------------------------------- fp16 mma.sync GEMM (k64 chunks)
// C[M,N] = A[M,K] @ B[N,K]^T.  A fp16 (producer-rounded).
// SPLIT: B = Bh + Bl (two MMAs) vs Bh only.
// EPI 0: +bias -> half | EPI 1: +bias+res(fp32) -> float
// EPI 2: +bias+gelu -> half | EPI 4: plain, N-guard -> float
#define BP 72
template <int EPI, int NT, bool SPLIT>
__global__ void __launch_bounds__(256, 2)
gemm_f16(const __half* __restrict__ Ah,
         const __half* __restrict__ Bh, const __half* __restrict__ Bl,
         const float* __restrict__ bias, const float* __restrict__ res,
         void* __restrict__ Cv, int M, int N, int K) {
    constexpr int ABUF = 128 * BP;
    constexpr int BBUF = NT * BP;
    constexpr int NBT  = NT / 32;

    extern __shared__ __half sm[];
    __half* sA  = sm;
    __half* sBh = sm + 2 * ABUF;
    __half* sBl = sBh + 2 * BBUF;
    const uint32_t uA  = (uint32_t)__cvta_generic_to_shared(sA);
    const uint32_t uBh = (uint32_t)__cvta_generic_to_shared(sBh);
    const uint32_t uBl = (uint32_t)__cvta_generic_to_shared(sBl);

    const int tid  = threadIdx.x;
    const int wid  = tid >> 5;
    const int lane = tid & 31;
    const int grp  = lane >> 2;
    const int tig  = lane & 3;
    const int bm = blockIdx.y * 128;
    const int bn = blockIdx.x * NT;
    const int wm0 = (wid & 1) * 64;
    const int wn0 = (wid >> 1) * (NT / 4);

    const int a_row = (lane & 15);
    const int a_k   = (lane >> 4) << 3;
    const int b_row = (lane & 7) + ((lane >> 4) << 3);
    const int b_k   = ((lane >> 3) & 1) << 3;
    const int b2_row = lane & 7;
    const int b2_k   = ((lane >> 3) & 1) << 3;

    float cf[4][NBT][4];
    #pragma unroll
    for (int i = 0; i < 4; i++)
        #pragma unroll
        for (int j = 0; j < NBT; j++)
            #pragma unroll
            for (int r = 0; r < 4; r++) cf[i][j][r] = 0.f;

    const int KC = K >> 6;

    auto stage = [&](int k0, int p) {
        #pragma unroll
        for (int ps = 0; ps < 4; ps++) {
            int s = tid + ps * 256;
            int row = s >> 3;
            int c16 = (s & 7) * 8;
            uint32_t doff = (uint32_t)(p * ABUF + row * BP + c16) * 2;
            cpa16(uA + doff, Ah + (size_t)(bm + row) * K + k0 + c16, 16);
        }
        #pragma unroll
        for (int ps = 0; ps < NT / 32; ps++) {
            int s = tid + ps * 256;
            int row = s >> 3;
            int c16 = (s & 7) * 8;
            int gr = bn + row, sz = 16;
            if (EPI == 4 && gr >= N) { gr = 0; sz = 0; }
            uint32_t doff = (uint32_t)(p * BBUF + row * BP + c16) * 2;
            cpa16(uBh + doff, Bh + (size_t)gr * K + k0 + c16, sz);
            if (SPLIT)
                cpa16(uBl + doff, Bl + (size_t)gr * K + k0 + c16, sz);
        }
        CP_COMMIT();
    };

    stage(0, 0);

    for (int c = 0; c < KC; c++) {
        const int p = c & 1;
        CP_WAIT0();
        __syncthreads();
        if (c + 1 < KC) stage((c + 1) << 6, 1 - p);

        const uint32_t bufA  = uA  + (uint32_t)(p * ABUF) * 2;
        const uint32_t bufBh = uBh + (uint32_t)(p * BBUF) * 2;
        const uint32_t bufBl = uBl + (uint32_t)(p * BBUF) * 2;
        #pragma unroll
        for (int ks = 0; ks < 4; ks++) {
            const int k0 = ks * 16;
            uint32_t bh[NBT][2], bl[NBT][2];
            uint32_t bo = (uint32_t)((wn0 + b_row) * BP + k0 + b_k) * 2;
            #pragma unroll
            for (int g = 0; g < NBT / 2; g++) {
                ldmx4(bh[2 * g][0], bh[2 * g][1], bh[2 * g + 1][0], bh[2 * g + 1][1],
                      bufBh + bo + (uint32_t)(g * 16 * BP) * 2);
                if (SPLIT)
                    ldmx4(bl[2 * g][0], bl[2 * g][1], bl[2 * g + 1][0], bl[2 * g + 1][1],
                          bufBl + bo + (uint32_t)(g * 16 * BP) * 2);
            }
            if (NBT & 1) {
                uint32_t bo2 = (uint32_t)((wn0 + (NBT - 1) * 8 + b2_row) * BP + k0 + b2_k) * 2;
                ldmx2(bh[NBT - 1][0], bh[NBT - 1][1], bufBh + bo2);
                if (SPLIT)
                    ldmx2(bl[NBT - 1][0], bl[NBT - 1][1], bufBl + bo2);
            }
            #pragma unroll
            for (int mt = 0; mt < 4; mt++) {
                uint32_t a[4];
                uint32_t ao = (uint32_t)((wm0 + mt * 16 + a_row) * BP + k0 + a_k) * 2;
                ldmx4(a[0], a[1], a[2], a[3], bufA + ao);
                #pragma unroll
                for (int nt = 0; nt < NBT; nt++) {
                    mma_f16(cf[mt][nt], a, bh[nt]);
                    if (SPLIT) mma_f16(cf[mt][nt], a, bl[nt]);
                }
            }
        }
    }

    // ---------------- epilogue ----------------
    #pragma unroll
    for (int mt = 0; mt < 4; mt++) {
        #pragma unroll
        for (int half = 0; half < 2; half++) {
            const int row = bm + wm0 + mt * 16 + grp + half * 8;
            #pragma unroll
            for (int nt = 0; nt < NBT; nt++) {
                const int col = bn + wn0 + nt * 8 + 2 * tig;
                float v0 = cf[mt][nt][half * 2 + 0];
                float v1 = cf[mt][nt][half * 2 + 1];
                if (EPI == 4) {
                    float* C = (float*)Cv;
                    if (col < N)     C[(size_t)row * N + col]     = v0;
                    if (col + 1 < N) C[(size_t)row * N + col + 1] = v1;
                } else {
                    v0 += bias[col];
                    v1 += bias[col + 1];
                    if (EPI == 1) {
                        const float* rp = res + (size_t)row * N + col;
                        v0 += rp[0]; v1 += rp[1];
                        *(float2*)((float*)Cv + (size_t)row * N + col) = make_float2(v0, v1);
                    } else {
                        if (EPI == 2) { v0 = gelu_f(v0); v1 = gelu_f(v1); }
                        *(uint32_t*)((__half*)Cv + (size_t)row * N + col) = pack_f16(v0, v1);
                    }
                }
            }
        }
    }
}

// ------------------------------------ fp16 mma.sync flash attention (v3)
#define APT 72
#define ATILE (64 * APT)
__global__ void __launch_bounds__(128)
attn_mma(const __half* __restrict__ qkv, __half* __restrict__ y) {
    extern __shared__ __half sh[];
    __half* sQ = sh;
    __half* sK = sh + ATILE;
    __half* sV = sh + 3 * ATILE;
    const uint32_t uQ = (uint32_t)__cvta_generic_to_shared(sQ);
    const uint32_t uK = (uint32_t)__cvta_generic_to_shared(sK);
    const uint32_t uV = (uint32_t)__cvta_generic_to_shared(sV);

    const int NT = SEQ / 64;
    const int h = blockIdx.y, b = blockIdx.z;
    const int tid  = threadIdx.x;
    const int wid  = tid >> 5;
    const int lane = tid & 31;
    const int grp  = lane >> 2;
    const int tig  = lane & 3;
    const float scale = 0.036084391824351615f;  // 1/sqrt(768)

    const int a_row = lane & 15;
    const int a_k   = (lane >> 4) << 3;
    const int b_row = (lane & 7) + ((lane >> 4) << 3);
    const int b_k   = ((lane >> 3) & 1) << 3;

    auto stageKV = [&](int ks, int p) {
        #pragma unroll
        for (int ps = 0; ps < 4; ps++) {
            int s = tid + ps * 128;
            int row = s >> 3;
            int ch = (s & 7) * 8;
            const __half* base = qkv + ((size_t)b * SEQ + (size_t)ks * 64 + row) * QKVDIM
                               + h * HDIM + ch;
            uint32_t doff = (uint32_t)(p * ATILE + row * APT + ch) * 2;
            cpa16(uK + doff, base + EMB, 16);
            cpa16(uV + doff, base + 2 * EMB, 16);
        }
        CP_COMMIT();
    };

    #pragma unroll 1
    for (int qi = 0; qi < 2; qi++) {
        const int tq = qi == 0 ? (int)blockIdx.x : NT - 1 - (int)blockIdx.x;

        __syncthreads();
        #pragma unroll
        for (int ps = 0; ps < 4; ps++) {
            int s = tid + ps * 128;
            int row = s >> 3;
            int ch = (s & 7) * 8;
            cpa16(uQ + (uint32_t)(row * APT + ch) * 2,
                  qkv + ((size_t)b * SEQ + (size_t)tq * 64 + row) * QKVDIM + h * HDIM + ch, 16);
        }
        CP_COMMIT();
        stageKV(0, 0);
        CP_WAIT0();
        __syncthreads();

        uint32_t qf[4][4];
        #pragma unroll
        for (int kt = 0; kt < 4; kt++) {
            uint32_t ao = (uint32_t)((wid * 16 + a_row) * APT + kt * 16 + a_k) * 2;
            ldmx4(qf[kt][0], qf[kt][1], qf[kt][2], qf[kt][3], uQ + ao);
        }

        float o[8][4];
        #pragma unroll
        for (int nt = 0; nt < 8; nt++)
            #pragma unroll
            for (int r = 0; r < 4; r++) o[nt][r] = 0.f;
        float m0 = -1e30f, m1 = -1e30f, l0 = 0.f, l1 = 0.f;

        const int row_g0 = tq * 64 + wid * 16 + grp;
        const int row_g1 = row_g0 + 8;

        for (int ks = 0; ks <= tq; ks++) {
            const int p = ks & 1;
            if (ks > 0) { CP_WAIT0(); __syncthreads(); }
            if (ks + 1 <= tq) stageKV(ks + 1, 1 - p);

            const uint32_t bufK = uK + (uint32_t)(p * ATILE) * 2;
            const uint32_t bufV = uV + (uint32_t)(p * ATILE) * 2;

            float s[8][4];
            #pragma unroll
            for (int nt = 0; nt < 8; nt++)
                #pragma unroll
                for (int r = 0; r < 4; r++) s[nt][r] = 0.f;
            #pragma unroll
            for (int kt = 0; kt < 4; kt++) {
                #pragma unroll
                for (int ntp = 0; ntp < 4; ntp++) {
                    uint32_t kb[2][2];
                    uint32_t bo = (uint32_t)((ntp * 16 + b_row) * APT + kt * 16 + b_k) * 2;
                    ldmx4(kb[0][0], kb[0][1], kb[1][0], kb[1][1], bufK + bo);
                    mma_f16(s[2 * ntp + 0], qf[kt], kb[0]);
                    mma_f16(s[2 * ntp + 1], qf[kt], kb[1]);
                }
            }

            const bool diag = (ks == tq);
            #pragma unroll
            for (int nt = 0; nt < 8; nt++) {
                int c = ks * 64 + nt * 8 + 2 * tig;
                #pragma unroll
                for (int r = 0; r < 4; r++) s[nt][r] *= scale;
                if (diag) {
                    if (c > row_g0)     s[nt][0] = -1e30f;
                    if (c + 1 > row_g0) s[nt][1] = -1e30f;
                    if (c > row_g1)     s[nt][2] = -1e30f;
                    if (c + 1 > row_g1) s[nt][3] = -1e30f;
                }
            }

            float t0 = -1e30f, t1 = -1e30f;
            #pragma unroll
            for (int nt = 0; nt < 8; nt++) {
                t0 = fmaxf(t0, fmaxf(s[nt][0], s[nt][1]));
                t1 = fmaxf(t1, fmaxf(s[nt][2], s[nt][3]));
            }
            #pragma unroll
            for (int off = 1; off < 4; off <<= 1) {
                t0 = fmaxf(t0, __shfl_xor_sync(0xffffffffu, t0, off));
                t1 = fmaxf(t1, __shfl_xor_sync(0xffffffffu, t1, off));
            }
            float nm0 = fmaxf(m0, t0), nm1 = fmaxf(m1, t1);
            float cr0 = __expf(m0 - nm0), cr1 = __expf(m1 - nm1);
            m0 = nm0; m1 = nm1;
            float rs0 = 0.f, rs1 = 0.f;
            uint32_t p01[8], p23[8];
            #pragma unroll
            for (int nt = 0; nt < 8; nt++) {
                float e0 = __expf(s[nt][0] - nm0);
                float e1 = __expf(s[nt][1] - nm0);
                float e2 = __expf(s[nt][2] - nm1);
                float e3 = __expf(s[nt][3] - nm1);
                rs0 += e0 + e1; rs1 += e2 + e3;
                p01[nt] = pack_f16(e0, e1);
                p23[nt] = pack_f16(e2, e3);
            }
            #pragma unroll
            for (int off = 1; off < 4; off <<= 1) {
                rs0 += __shfl_xor_sync(0xffffffffu, rs0, off);
                rs1 += __shfl_xor_sync(0xffffffffu, rs1, off);
            }
            l0 = l0 * cr0 + rs0;
            l1 = l1 * cr1 + rs1;
            #pragma unroll
            for (int nt = 0; nt < 8; nt++) {
                o[nt][0] *= cr0; o[nt][1] *= cr0;
                o[nt][2] *= cr1; o[nt][3] *= cr1;
            }

            #pragma unroll
            for (int kt = 0; kt < 4; kt++) {
                uint32_t a[4] = { p01[2 * kt], p23[2 * kt], p01[2 * kt + 1], p23[2 * kt + 1] };
                #pragma unroll
                for (int ntp = 0; ntp < 4; ntp++) {
                    uint32_t vb[2][2];
                    uint32_t vo = (uint32_t)((kt * 16 + a_row) * APT + ntp * 16 + a_k) * 2;
                    ldmx4t(vb[0][0], vb[0][1], vb[1][0], vb[1][1], bufV + vo);
                    mma_f16(o[2 * ntp + 0], a, vb[0]);
                    mma_f16(o[2 * ntp + 1], a, vb[1]);
                }
            }
        }

        float inv0 = 1.f / l0, inv1 = 1.f / l1;
        __half* y0 = y + ((size_t)b * SEQ + (size_t)tq * 64 + wid * 16 + grp) * EMB + h * HDIM;
        __half* y1 = y0 + 8 * EMB;
        #pragma unroll
        for (int nt = 0; nt < 8; nt++) {
            int c = nt * 8 + 2 * tig;
            *(uint32_t*)(y0 + c) = pack_f16(o[nt][0] * inv0, o[nt][1] * inv0);
            *(uint32_t*)(y1 + c) = pack_f16(o[nt][2] * inv1, o[nt][3] * inv1);
        }
    }
}

// -------------------------------------------------------------------- launch
extern "C" void kernel_launch(void* const* d_in, const int* in_sizes, int n_in,
                              void* d_out, int out_size) {
    const int*   tokens = (const int*)  d_in[0];
    const float* wte    = (const float*)d_in[1];
    const float* wpe    = (const float*)d_in[2];
    const float* ln1w   = (const float*)d_in[3];
    const float* ln1b   = (const float*)d_in[4];
    const float* qkvw   = (const float*)d_in[5];
    const float* qkvb   = (const float*)d_in[6];
    const float* atpw   = (const float*)d_in[7];
    const float* atpb   = (const float*)d_in[8];
    const float* ln2w   = (const float*)d_in[9];
    const float* ln2b   = (const float*)d_in[10];
    const float* fcw    = (const float*)d_in[11];
    const float* fcb    = (const float*)d_in[12];
    const float* fpw    = (const float*)d_in[13];
    const float* fpb    = (const float*)d_in[14];
    const float* lnfw   = (const float*)d_in[15];
    const float* lnfb   = (const float*)d_in[16];
    const float* lmw    = (const float*)d_in[17];
    float* out = (float*)d_out;

    float* px;
    __half *pah, *pqkvh, *pyh, *pmh;
    __half *qh, *ah, *al, *fh, *fl, *ph, *lh;
    cudaGetSymbolAddress((void**)&px,    g_x);
    cudaGetSymbolAddress((void**)&pah,   g_ah);
    cudaGetSymbolAddress((void**)&pqkvh, g_qkvh);
    cudaGetSymbolAddress((void**)&pyh,   g_yh);
    cudaGetSymbolAddress((void**)&pmh,   g_mh);
    cudaGetSymbolAddress((void**)&qh, g_qkvH);
    cudaGetSymbolAddress((void**)&ah, g_atpH); cudaGetSymbolAddress((void**)&al, g_atpL);
    cudaGetSymbolAddress((void**)&fh, g_fcH);  cudaGetSymbolAddress((void**)&fl, g_fcL);
    cudaGetSymbolAddress((void**)&ph, g_fpH);
    cudaGetSymbolAddress((void**)&lh, g_lmH);

    const int smem128s2 = (2 * 128 * BP + 4 * 128 * BP) * 2;  // 110592 (fc, split)
    const int smem96s2  = (2 * 128 * BP + 4 * 96 * BP) * 2;   // 92160  (proj, split)
    const int smem96s1  = (2 * 128 * BP + 2 * 96 * BP) * 2;   // 64512  (fp, single)
    const int smem128s1 = (2 * 128 * BP + 2 * 128 * BP) * 2;  // 73728  (qkv, lm)
    cudaFuncSetAttribute((gemm_f16<0, 128, false>), cudaFuncAttributeMaxDynamicSharedMemorySize, smem128s1);
    cudaFuncSetAttribute((gemm_f16<2, 128, true>),  cudaFuncAttributeMaxDynamicSharedMemorySize, smem128s2);
    cudaFuncSetAttribute((gemm_f16<1, 96, true>),   cudaFuncAttributeMaxDynamicSharedMemorySize, smem96s2);
    cudaFuncSetAttribute((gemm_f16<1, 96, false>),  cudaFuncAttributeMaxDynamicSharedMemorySize, smem96s1);
    cudaFuncSetAttribute((gemm_f16<4, 128, false>), cudaFuncAttributeMaxDynamicSharedMemorySize, smem128s1);

    const int asmem = 5 * ATILE * sizeof(__half);  // 46080
    cudaFuncSetAttribute(attn_mma, cudaFuncAttributeMaxDynamicSharedMemorySize, asmem);

    dim3 tb(32, 8);
    transpose_cvt_kernel<<<dim3(QKVDIM / 32, EMB / 32, NLAYER), tb>>>(qkvw, qh, EMB, QKVDIM);
    transpose_split_kernel<<<dim3(EMB / 32,    EMB / 32, NLAYER), tb>>>(atpw, ah, al, EMB, EMB);
    transpose_split_kernel<<<dim3(FFDIM / 32,  EMB / 32, NLAYER), tb>>>(fcw,  fh, fl, EMB, FFDIM);
    transpose_cvt_kernel<<<dim3(EMB / 32,  FFDIM / 32, NLAYER), tb>>>(fpw,  ph, FFDIM, EMB);
    cvt_kernel<<<(VOCAB * EMB + 255) / 256, 256>>>(lmw, lh, VOCAB * EMB);

    embed_kernel<<<(TOKENS * EMB + 255) / 256, 256>>>(tokens, wte, wpe, px);

    for (int i = 0; i < NLAYER; i++) {
        ln_kernel<<<TOKENS / 8, 256>>>(px, ln1w + i * EMB, ln1b + i * EMB, pah);

        gemm_f16<0, 128, false><<<dim3(QKVDIM / 128, TOKENS / 128), 256, smem128s1>>>(
            pah, qh + (size_t)i * QKVDIM * EMB, nullptr,
            qkvb + i * QKVDIM, nullptr, pqkvh, TOKENS, QKVDIM, EMB);

        attn_mma<<<dim3(SEQ / 128, NHEAD, NBATCH), 128, asmem>>>(pqkvh, pyh);

        gemm_f16<1, 96, true><<<dim3(EMB / 96, TOKENS / 128), 256, smem96s2>>>(
            pyh, ah + (size_t)i * EMB * EMB, al + (size_t)i * EMB * EMB,
            atpb + i * EMB, px, px, TOKENS, EMB, EMB);

        ln_kernel<<<TOKENS / 8, 256>>>(px, ln2w + i * EMB, ln2b + i * EMB, pah);

        gemm_f16<2, 128, true><<<dim3(FFDIM / 128, TOKENS / 128), 256, smem128s2>>>(
            pah, fh + (size_t)i * FFDIM * EMB, fl + (size_t)i * FFDIM * EMB,
            fcb + i * FFDIM, nullptr, pmh, TOKENS, FFDIM, EMB);

        gemm_f16<1, 96, false><<<dim3(EMB / 96, TOKENS / 128), 256, smem96s1>>>(
            pmh, ph + (size_t)i * EMB * FFDIM, nullptr,
            fpb + i * EMB, px, px, TOKENS, EMB, FFDIM);
    }

    ln_kernel<<<TOKENS / 8, 256>>>(px, lnfw, lnfb, pah);

    gemm_f16<4, 128, false><<<dim3((VOCAB + 127) / 128, TOKENS / 128), 256, smem128s1>>>(
        pah, lh, nullptr, nullptr, nullptr, out, TOKENS, VOCAB, EMB);
}

// round 14
// speedup vs baseline: 5.9297x; 1.0209x over previous
#include <cuda_runtime.h>
#include <cuda_fp16.h>
#include <math.h>
#include <stdint.h>

#define TOKENS 4096
#define EMB    768
#define NLAYER 12
#define NHEAD  12
#define HDIM   64
#define SEQ    1024
#define NBATCH 4
#define VOCAB  50257
#define FFDIM  3072
#define QKVDIM 2304

// -------------------- scratch (static device globals; no allocation) --------
__device__ float  g_x  [TOKENS * EMB];
__device__ __half g_ah [TOKENS * EMB];
__device__ __half g_qkvh[TOKENS * QKVDIM];
__device__ __half g_yh [TOKENS * EMB];
__device__ __half g_mh [TOKENS * FFDIM];
__device__ __half g_qkvH[(size_t)NLAYER * QKVDIM * EMB];
__device__ __half g_atpH[(size_t)NLAYER * EMB * EMB];
__device__ __half g_fcH [(size_t)NLAYER * FFDIM * EMB];
__device__ __half g_fcL [(size_t)NLAYER * FFDIM * EMB];
__device__ __half g_fpH [(size_t)NLAYER * EMB * FFDIM];
__device__ __half g_lmH [(size_t)VOCAB * EMB];

// ------------------------------------------------------------- helpers
__device__ __forceinline__ float gelu_f(float x) {
    float x3 = x * x * x;
    return 0.5f * x * (1.f + tanhf(0.7978845608028654f * (x + 0.044715f * x3)));
}
__device__ __forceinline__ uint32_t pack_f16(float x0, float x1) {
    uint32_t u;
    asm("{.reg .b16 l,h; cvt.rn.f16.f32 l,%1; cvt.rn.f16.f32 h,%2; mov.b32 %0,{l,h};}"
        : "=r"(u) : "f"(x0), "f"(x1));
    return u;
}
__device__ __forceinline__ void mma_f16(float* c, const uint32_t* a, const uint32_t* b) {
    asm volatile(
        "mma.sync.aligned.m16n8k16.row.col.f32.f16.f16.f32 "
        "{%0,%1,%2,%3}, {%4,%5,%6,%7}, {%8,%9}, {%0,%1,%2,%3};"
        : "+f"(c[0]), "+f"(c[1]), "+f"(c[2]), "+f"(c[3])
        : "r"(a[0]), "r"(a[1]), "r"(a[2]), "r"(a[3]), "r"(b[0]), "r"(b[1]));
}
__device__ __forceinline__ void ldmx4(uint32_t& r0, uint32_t& r1,
                                      uint32_t& r2, uint32_t& r3, uint32_t addr) {
    asm volatile("ldmatrix.sync.aligned.m8n8.x4.shared.b16 {%0,%1,%2,%3}, [%4];"
                 : "=r"(r0), "=r"(r1), "=r"(r2), "=r"(r3) : "r"(addr));
}
__device__ __forceinline__ void ldmx2(uint32_t& r0, uint32_t& r1, uint32_t addr) {
    asm volatile("ldmatrix.sync.aligned.m8n8.x2.shared.b16 {%0,%1}, [%2];"
                 : "=r"(r0), "=r"(r1) : "r"(addr));
}
__device__ __forceinline__ void ldmx4t(uint32_t& r0, uint32_t& r1,
                                       uint32_t& r2, uint32_t& r3, uint32_t addr) {
    asm volatile("ldmatrix.sync.aligned.m8n8.x4.trans.shared.b16 {%0,%1,%2,%3}, [%4];"
                 : "=r"(r0), "=r"(r1), "=r"(r2), "=r"(r3) : "r"(addr));
}
__device__ __forceinline__ void cpa16(uint32_t dst, const void* src, int srcsz) {
    asm volatile("cp.async.ca.shared.global [%0], [%1], 16, %2;"
                 :: "r"(dst), "l"(src), "r"(srcsz) : "memory");
}
#define CP_COMMIT() asm volatile("cp.async.commit_group;" ::: "memory")
#define CP_WAIT0()  asm volatile("cp.async.wait_group 0;" ::: "memory")

// ---------------------------------------------------------------- embedding
__global__ void embed_kernel(const int* __restrict__ tok,
                             const float* __restrict__ wte,
                             const float* __restrict__ wpe,
                             float* __restrict__ x) {
    int idx = blockIdx.x * blockDim.x + threadIdx.x;
    if (idx >= TOKENS * EMB) return;
    int t = idx / EMB;
    int e = idx - t * EMB;
    x[idx] = wte[(size_t)tok[t] * EMB + e] + wpe[e];
}

// --------------------------------- layernorm (warp-per-row, fp16 output)
__global__ void ln_kernel(const float* __restrict__ x,
                          const float* __restrict__ w,
                          const float* __restrict__ bb,
                          __half* __restrict__ o) {
    const int row  = blockIdx.x * 8 + (threadIdx.x >> 5);
    const int lane = threadIdx.x & 31;
    const float* xr = x + (size_t)row * EMB;

    float4 v[6];
    float s = 0.f, sq = 0.f;
    #pragma unroll
    for (int i = 0; i < 6; i++) {
        v[i] = *(const float4*)(xr + lane * 4 + i * 128);
        s  += v[i].x + v[i].y + v[i].z + v[i].w;
        sq += v[i].x * v[i].x + v[i].y * v[i].y
            + v[i].z * v[i].z + v[i].w * v[i].w;
    }
    #pragma unroll
    for (int off = 16; off; off >>= 1) {
        s  += __shfl_xor_sync(0xffffffffu, s, off);
        sq += __shfl_xor_sync(0xffffffffu, sq, off);
    }
    const float mean = s * (1.f / EMB);
    const float rstd = rsqrtf(sq * (1.f / EMB) - mean * mean + 1e-5f);

    __half* orow = o + (size_t)row * EMB;
    #pragma unroll
    for (int i = 0; i < 6; i++) {
        const int c = lane * 4 + i * 128;
        float4 wv = *(const float4*)(w + c);
        float4 bv = *(const float4*)(bb + c);
        float r0 = (v[i].x - mean) * rstd * wv.x + bv.x;
        float r1 = (v[i].y - mean) * rstd * wv.y + bv.y;
        float r2 = (v[i].z - mean) * rstd * wv.z + bv.z;
        float r3 = (v[i].w - mean) * rstd * wv.w + bv.w;
        *(uint2*)(orow + c) = make_uint2(pack_f16(r0, r1), pack_f16(r2, r3));
    }
}

// --------------------------------------------- transpose + fp16 hi/lo split
__global__ void transpose_split_kernel(const float* __restrict__ in,
                                       __half* __restrict__ oh,
                                       __half* __restrict__ ol,
                                       int K, int N) {
    __shared__ float t[32][33];
    const size_t off = (size_t)blockIdx.z * K * N;
    int n0 = blockIdx.x * 32, k0 = blockIdx.y * 32;
    int x = threadIdx.x, y = threadIdx.y;
    #pragma unroll
    for (int i = 0; i < 32; i += 8)
        t[y + i][x] = in[off + (size_t)(k0 + y + i) * N + n0 + x];
    __syncthreads();
    #pragma unroll
    for (int i = 0; i < 32; i += 8) {
        float v = t[x][y + i];
        __half h = __float2half_rn(v);
        __half l = __float2half_rn(v - __half2float(h));
        size_t o = off + (size_t)(n0 + y + i) * K + k0 + x;
        oh[o] = h; ol[o] = l;
    }
}

// ------------------------------------------ transpose + fp16 (hi only)
__global__ void transpose_cvt_kernel(const float* __restrict__ in,
                                     __half* __restrict__ oh,
                                     int K, int N) {
    __shared__ float t[32][33];
    const size_t off = (size_t)blockIdx.z * K * N;
    int n0 = blockIdx.x * 32, k0 = blockIdx.y * 32;
    int x = threadIdx.x, y = threadIdx.y;
    #pragma unroll
    for (int i = 0; i < 32; i += 8)
        t[y + i][x] = in[off + (size_t)(k0 + y + i) * N + n0 + x];
    __syncthreads();
    #pragma unroll
    for (int i = 0; i < 32; i += 8)
        oh[off + (size_t)(n0 + y + i) * K + k0 + x] = __float2half_rn(t[x][y + i]);
}

// ---------------------------------------------- elementwise fp16 convert
__global__ void cvt_kernel(const float* __restrict__ in,
                           __half* __restrict__ oh, int n) {
    int i = blockIdx.x * blockDim.x + threadIdx.x;
    if (i >= n) return;
    oh[i] = __float2half_rn(in[i]);
}

// ------------------------------------------- fp16 mma.sync GEMM (k64 chunks)
// C[M,N] = A[M,K] @ B[N,K]^T.  A fp16 (producer-rounded).
// SPLIT: B = Bh + Bl (two MMAs) vs Bh only.
// EPI 0: +bias -> half | EPI 1: +bias+res(fp32) -> float
// EPI 2: +bias+gelu -> half | EPI 4: plain, N-guard -> float (M-major raster)
#define BP 72
template <int EPI, int NT, bool SPLIT>
__global__ void __launch_bounds__(256, 2)
gemm_f16(const __half* __restrict__ Ah,
         const __half* __restrict__ Bh, const __half* __restrict__ Bl,
         const float* __restrict__ bias, const float* __restrict__ res,
         void* __restrict__ Cv, int M, int N, int K) {
    constexpr int ABUF = 128 * BP;
    constexpr int BBUF = NT * BP;
    constexpr int NBT  = NT / 32;

    extern __shared__ __half sm[];
    __half* sA  = sm;
    __half* sBh = sm + 2 * ABUF;
    __half* sBl = sBh + 2 * BBUF;
    const uint32_t uA  = (uint32_t)__cvta_generic_to_shared(sA);
    const uint32_t uBh = (uint32_t)__cvta_generic_to_shared(sBh);
    const uint32_t uBl = (uint32_t)__cvta_generic_to_shared(sBl);

    const int tid  = threadIdx.x;
    const int wid  = tid >> 5;
    const int lane = tid & 31;
    const int grp  = lane >> 2;
    const int tig  = lane & 3;
    // EPI 4 (LM head): M-major raster — consecutive CTAs share the B tile,
    // keeping the per-wave B working set L2-resident (B streamed from DRAM once).
    const int bm = (EPI == 4 ? blockIdx.x : blockIdx.y) * 128;
    const int bn = (EPI == 4 ? blockIdx.y : blockIdx.x) * NT;
    const int wm0 = (wid & 1) * 64;
    const int wn0 = (wid >> 1) * (NT / 4);

    const int a_row = (lane & 15);
    const int a_k   = (lane >> 4) << 3;
    const int b_row = (lane & 7) + ((lane >> 4) << 3);
    const int b_k   = ((lane >> 3) & 1) << 3;
    const int b2_row = lane & 7;
    const int b2_k   = ((lane >> 3) & 1) << 3;

    float cf[4][NBT][4];
    #pragma unroll
    for (int i = 0; i < 4; i++)
        #pragma unroll
        for (int j = 0; j < NBT; j++)
            #pragma unroll
            for (int r = 0; r < 4; r++) cf[i][j][r] = 0.f;

    const int KC = K >> 6;

    auto stage = [&](int k0, int p) {
        #pragma unroll
        for (int ps = 0; ps < 4; ps++) {
            int s = tid + ps * 256;
            int row = s >> 3;
            int c16 = (s & 7) * 8;
            uint32_t doff = (uint32_t)(p * ABUF + row * BP + c16) * 2;
            cpa16(uA + doff, Ah + (size_t)(bm + row) * K + k0 + c16, 16);
        }
        #pragma unroll
        for (int ps = 0; ps < NT / 32; ps++) {
            int s = tid + ps * 256;
            int row = s >> 3;
            int c16 = (s & 7) * 8;
            int gr = bn + row, sz = 16;
            if (EPI == 4 && gr >= N) { gr = 0; sz = 0; }
            uint32_t doff = (uint32_t)(p * BBUF + row * BP + c16) * 2;
            cpa16(uBh + doff, Bh + (size_t)gr * K + k0 + c16, sz);
            if (SPLIT)
                cpa16(uBl + doff, Bl + (size_t)gr * K + k0 + c16, sz);
        }
        CP_COMMIT();
    };

    stage(0, 0);

    for (int c = 0; c < KC; c++) {
        const int p = c & 1;
        CP_WAIT0();
        __syncthreads();
        if (c + 1 < KC) stage((c + 1) << 6, 1 - p);

        const uint32_t bufA  = uA  + (uint32_t)(p * ABUF) * 2;
        const uint32_t bufBh = uBh + (uint32_t)(p * BBUF) * 2;
        const uint32_t bufBl = uBl + (uint32_t)(p * BBUF) * 2;
        #pragma unroll
        for (int ks = 0; ks < 4; ks++) {
            const int k0 = ks * 16;
            uint32_t bh[NBT][2], bl[NBT][2];
            uint32_t bo = (uint32_t)((wn0 + b_row) * BP + k0 + b_k) * 2;
            #pragma unroll
            for (int g = 0; g < NBT / 2; g++) {
                ldmx4(bh[2 * g][0], bh[2 * g][1], bh[2 * g + 1][0], bh[2 * g + 1][1],
                      bufBh + bo + (uint32_t)(g * 16 * BP) * 2);
                if (SPLIT)
                    ldmx4(bl[2 * g][0], bl[2 * g][1], bl[2 * g + 1][0], bl[2 * g + 1][1],
                          bufBl + bo + (uint32_t)(g * 16 * BP) * 2);
            }
            if (NBT & 1) {
                uint32_t bo2 = (uint32_t)((wn0 + (NBT - 1) * 8 + b2_row) * BP + k0 + b2_k) * 2;
                ldmx2(bh[NBT - 1][0], bh[NBT - 1][1], bufBh + bo2);
                if (SPLIT)
                    ldmx2(bl[NBT - 1][0], bl[NBT - 1][1], bufBl + bo2);
            }
            #pragma unroll
            for (int mt = 0; mt < 4; mt++) {
                uint32_t a[4];
                uint32_t ao = (uint32_t)((wm0 + mt * 16 + a_row) * BP + k0 + a_k) * 2;
                ldmx4(a[0], a[1], a[2], a[3], bufA + ao);
                #pragma unroll
                for (int nt = 0; nt < NBT; nt++) {
                    mma_f16(cf[mt][nt], a, bh[nt]);
                    if (SPLIT) mma_f16(cf[mt][nt], a, bl[nt]);
                }
            }
        }
    }

    // ---------------- epilogue ----------------
    #pragma unroll
    for (int mt = 0; mt < 4; mt++) {
        #pragma unroll
        for (int half = 0; half < 2; half++) {
            const int row = bm + wm0 + mt * 16 + grp + half * 8;
            #pragma unroll
            for (int nt = 0; nt < NBT; nt++) {
                const int col = bn + wn0 + nt * 8 + 2 * tig;
                float v0 = cf[mt][nt][half * 2 + 0];
                float v1 = cf[mt][nt][half * 2 + 1];
                if (EPI == 4) {
                    float* C = (float*)Cv;
                    if (col < N)     C[(size_t)row * N + col]     = v0;
                    if (col + 1 < N) C[(size_t)row * N + col + 1] = v1;
                } else {
                    v0 += bias[col];
                    v1 += bias[col + 1];
                    if (EPI == 1) {
                        const float* rp = res + (size_t)row * N + col;
                        v0 += rp[0]; v1 += rp[1];
                        *(float2*)((float*)Cv + (size_t)row * N + col) = make_float2(v0, v1);
                    } else {
                        if (EPI == 2) { v0 = gelu_f(v0); v1 = gelu_f(v1); }
                        *(uint32_t*)((__half*)Cv + (size_t)row * N + col) = pack_f16(v0, v1);
                    }
                }
            }
        }
    }
}

// ------------------------------------ fp16 mma.sync flash attention (v3)
#define APT 72
#define ATILE (64 * APT)
__global__ void __launch_bounds__(128)
attn_mma(const __half* __restrict__ qkv, __half* __restrict__ y) {
    extern __shared__ __half sh[];
    __half* sQ = sh;
    __half* sK = sh + ATILE;
    __half* sV = sh + 3 * ATILE;
    const uint32_t uQ = (uint32_t)__cvta_generic_to_shared(sQ);
    const uint32_t uK = (uint32_t)__cvta_generic_to_shared(sK);
    const uint32_t uV = (uint32_t)__cvta_generic_to_shared(sV);

    const int NT = SEQ / 64;
    const int h = blockIdx.y, b = blockIdx.z;
    const int tid  = threadIdx.x;
    const int wid  = tid >> 5;
    const int lane = tid & 31;
    const int grp  = lane >> 2;
    const int tig  = lane & 3;
    const float scale = 0.036084391824351615f;  // 1/sqrt(768)

    const int a_row = lane & 15;
    const int a_k   = (lane >> 4) << 3;
    const int b_row = (lane & 7) + ((lane >> 4) << 3);
    const int b_k   = ((lane >> 3) & 1) << 3;

    auto stageKV = [&](int ks, int p) {
        #pragma unroll
        for (int ps = 0; ps < 4; ps++) {
            int s = tid + ps * 128;
            int row = s >> 3;
            int ch = (s & 7) * 8;
            const __half* base = qkv + ((size_t)b * SEQ + (size_t)ks * 64 + row) * QKVDIM
                               + h * HDIM + ch;
            uint32_t doff = (uint32_t)(p * ATILE + row * APT + ch) * 2;
            cpa16(uK + doff, base + EMB, 16);
            cpa16(uV + doff, base + 2 * EMB, 16);
        }
        CP_COMMIT();
    };

    #pragma unroll 1
    for (int qi = 0; qi < 2; qi++) {
        const int tq = qi == 0 ? (int)blockIdx.x : NT - 1 - (int)blockIdx.x;

        __syncthreads();
        #pragma unroll
        for (int ps = 0; ps < 4; ps++) {
            int s = tid + ps * 128;
            int row = s >> 3;
            int ch = (s & 7) * 8;
            cpa16(uQ + (uint32_t)(row * APT + ch) * 2,
                  qkv + ((size_t)b * SEQ + (size_t)tq * 64 + row) * QKVDIM + h * HDIM + ch, 16);
        }
        CP_COMMIT();
        stageKV(0, 0);
        CP_WAIT0();
        __syncthreads();

        uint32_t qf[4][4];
        #pragma unroll
        for (int kt = 0; kt < 4; kt++) {
            uint32_t ao = (uint32_t)((wid * 16 + a_row) * APT + kt * 16 + a_k) * 2;
            ldmx4(qf[kt][0], qf[kt][1], qf[kt][2], qf[kt][3], uQ + ao);
        }

        float o[8][4];
        #pragma unroll
        for (int nt = 0; nt < 8; nt++)
            #pragma unroll
            for (int r = 0; r < 4; r++) o[nt][r] = 0.f;
        float m0 = -1e30f, m1 = -1e30f, l0 = 0.f, l1 = 0.f;

        const int row_g0 = tq * 64 + wid * 16 + grp;
        const int row_g1 = row_g0 + 8;

        for (int ks = 0; ks <= tq; ks++) {
            const int p = ks & 1;
            if (ks > 0) { CP_WAIT0(); __syncthreads(); }
            if (ks + 1 <= tq) stageKV(ks + 1, 1 - p);

            const uint32_t bufK = uK + (uint32_t)(p * ATILE) * 2;
            const uint32_t bufV = uV + (uint32_t)(p * ATILE) * 2;

            float s[8][4];
            #pragma unroll
            for (int nt = 0; nt < 8; nt++)
                #pragma unroll
                for (int r = 0; r < 4; r++) s[nt][r] = 0.f;
            #pragma unroll
            for (int kt = 0; kt < 4; kt++) {
                #pragma unroll
                for (int ntp = 0; ntp < 4; ntp++) {
                    uint32_t kb[2][2];
                    uint32_t bo = (uint32_t)((ntp * 16 + b_row) * APT + kt * 16 + b_k) * 2;
                    ldmx4(kb[0][0], kb[0][1], kb[1][0], kb[1][1], bufK + bo);
                    mma_f16(s[2 * ntp + 0], qf[kt], kb[0]);
                    mma_f16(s[2 * ntp + 1], qf[kt], kb[1]);
                }
            }

            const bool diag = (ks == tq);
            #pragma unroll
            for (int nt = 0; nt < 8; nt++) {
                int c = ks * 64 + nt * 8 + 2 * tig;
                #pragma unroll
                for (int r = 0; r < 4; r++) s[nt][r] *= scale;
                if (diag) {
                    if (c > row_g0)     s[nt][0] = -1e30f;
                    if (c + 1 > row_g0) s[nt][1] = -1e30f;
                    if (c > row_g1)     s[nt][2] = -1e30f;
                    if (c + 1 > row_g1) s[nt][3] = -1e30f;
                }
            }

            float t0 = -1e30f, t1 = -1e30f;
            #pragma unroll
            for (int nt = 0; nt < 8; nt++) {
                t0 = fmaxf(t0, fmaxf(s[nt][0], s[nt][1]));
                t1 = fmaxf(t1, fmaxf(s[nt][2], s[nt][3]));
            }
            #pragma unroll
            for (int off = 1; off < 4; off <<= 1) {
                t0 = fmaxf(t0, __shfl_xor_sync(0xffffffffu, t0, off));
                t1 = fmaxf(t1, __shfl_xor_sync(0xffffffffu, t1, off));
            }
            float nm0 = fmaxf(m0, t0), nm1 = fmaxf(m1, t1);
            float cr0 = __expf(m0 - nm0), cr1 = __expf(m1 - nm1);
            m0 = nm0; m1 = nm1;
            float rs0 = 0.f, rs1 = 0.f;
            uint32_t p01[8], p23[8];
            #pragma unroll
            for (int nt = 0; nt < 8; nt++) {
                float e0 = __expf(s[nt][0] - nm0);
                float e1 = __expf(s[nt][1] - nm0);
                float e2 = __expf(s[nt][2] - nm1);
                float e3 = __expf(s[nt][3] - nm1);
                rs0 += e0 + e1; rs1 += e2 + e3;
                p01[nt] = pack_f16(e0, e1);
                p23[nt] = pack_f16(e2, e3);
            }
            #pragma unroll
            for (int off = 1; off < 4; off <<= 1) {
                rs0 += __shfl_xor_sync(0xffffffffu, rs0, off);
                rs1 += __shfl_xor_sync(0xffffffffu, rs1, off);
            }
            l0 = l0 * cr0 + rs0;
            l1 = l1 * cr1 + rs1;
            #pragma unroll
            for (int nt = 0; nt < 8; nt++) {
                o[nt][0] *= cr0; o[nt][1] *= cr0;
                o[nt][2] *= cr1; o[nt][3] *= cr1;
            }

            #pragma unroll
            for (int kt = 0; kt < 4; kt++) {
                uint32_t a[4] = { p01[2 * kt], p23[2 * kt], p01[2 * kt + 1], p23[2 * kt + 1] };
                #pragma unroll
                for (int ntp = 0; ntp < 4; ntp++) {
                    uint32_t vb[2][2];
                    uint32_t vo = (uint32_t)((kt * 16 + a_row) * APT + ntp * 16 + a_k) * 2;
                    ldmx4t(vb[0][0], vb[0][1], vb[1][0], vb[1][1], bufV + vo);
                    mma_f16(o[2 * ntp + 0], a, vb[0]);
                    mma_f16(o[2 * ntp + 1], a, vb[1]);
                }
            }
        }

        float inv0 = 1.f / l0, inv1 = 1.f / l1;
        __half* y0 = y + ((size_t)b * SEQ + (size_t)tq * 64 + wid * 16 + grp) * EMB + h * HDIM;
        __half* y1 = y0 + 8 * EMB;
        #pragma unroll
        for (int nt = 0; nt < 8; nt++) {
            int c = nt * 8 + 2 * tig;
            *(uint32_t*)(y0 + c) = pack_f16(o[nt][0] * inv0, o[nt][1] * inv0);
            *(uint32_t*)(y1 + c) = pack_f16(o[nt][2] * inv1, o[nt][3] * inv1);
        }
    }
}

// -------------------------------------------------------------------- launch
extern "C" void kernel_launch(void* const* d_in, const int* in_sizes, int n_in,
                              void* d_out, int out_size) {
    const int*   tokens = (const int*)  d_in[0];
    const float* wte    = (const float*)d_in[1];
    const float* wpe    = (const float*)d_in[2];
    const float* ln1w   = (const float*)d_in[3];
    const float* ln1b   = (const float*)d_in[4];
    const float* qkvw   = (const float*)d_in[5];
    const float* qkvb   = (const float*)d_in[6];
    const float* atpw   = (const float*)d_in[7];
    const float* atpb   = (const float*)d_in[8];
    const float* ln2w   = (const float*)d_in[9];
    const float* ln2b   = (const float*)d_in[10];
    const float* fcw    = (const float*)d_in[11];
    const float* fcb    = (const float*)d_in[12];
    const float* fpw    = (const float*)d_in[13];
    const float* fpb    = (const float*)d_in[14];
    const float* lnfw   = (const float*)d_in[15];
    const float* lnfb   = (const float*)d_in[16];
    const float* lmw    = (const float*)d_in[17];
    float* out = (float*)d_out;

    float* px;
    __half *pah, *pqkvh, *pyh, *pmh;
    __half *qh, *ah, *fh, *fl, *ph, *lh;
    cudaGetSymbolAddress((void**)&px,    g_x);
    cudaGetSymbolAddress((void**)&pah,   g_ah);
    cudaGetSymbolAddress((void**)&pqkvh, g_qkvh);
    cudaGetSymbolAddress((void**)&pyh,   g_yh);
    cudaGetSymbolAddress((void**)&pmh,   g_mh);
    cudaGetSymbolAddress((void**)&qh, g_qkvH);
    cudaGetSymbolAddress((void**)&ah, g_atpH);
    cudaGetSymbolAddress((void**)&fh, g_fcH);  cudaGetSymbolAddress((void**)&fl, g_fcL);
    cudaGetSymbolAddress((void**)&ph, g_fpH);
    cudaGetSymbolAddress((void**)&lh, g_lmH);

    const int smem128s2 = (2 * 128 * BP + 4 * 128 * BP) * 2;  // 110592 (fc, split)
    const int smem96s1  = (2 * 128 * BP + 2 * 96 * BP) * 2;   // 64512  (proj/fp, single)
    const int smem128s1 = (2 * 128 * BP + 2 * 128 * BP) * 2;  // 73728  (qkv, lm)
    cudaFuncSetAttribute((gemm_f16<0, 128, false>), cudaFuncAttributeMaxDynamicSharedMemorySize, smem128s1);
    cudaFuncSetAttribute((gemm_f16<2, 128, true>),  cudaFuncAttributeMaxDynamicSharedMemorySize, smem128s2);
    cudaFuncSetAttribute((gemm_f16<1, 96, false>),  cudaFuncAttributeMaxDynamicSharedMemorySize, smem96s1);
    cudaFuncSetAttribute((gemm_f16<4, 128, false>), cudaFuncAttributeMaxDynamicSharedMemorySize, smem128s1);

    const int asmem = 5 * ATILE * sizeof(__half);  // 46080
    cudaFuncSetAttribute(attn_mma, cudaFuncAttributeMaxDynamicSharedMemorySize, asmem);

    dim3 tb(32, 8);
    transpose_cvt_kernel<<<dim3(QKVDIM / 32, EMB / 32, NLAYER), tb>>>(qkvw, qh, EMB, QKVDIM);
    transpose_cvt_kernel<<<dim3(EMB / 32,    EMB / 32, NLAYER), tb>>>(atpw, ah, EMB, EMB);
    transpose_split_kernel<<<dim3(FFDIM / 32,  EMB / 32, NLAYER), tb>>>(fcw,  fh, fl, EMB, FFDIM);
    transpose_cvt_kernel<<<dim3(EMB / 32,  FFDIM / 32, NLAYER), tb>>>(fpw,  ph, FFDIM, EMB);
    cvt_kernel<<<(VOCAB * EMB + 255) / 256, 256>>>(lmw, lh, VOCAB * EMB);

    embed_kernel<<<(TOKENS * EMB + 255) / 256, 256>>>(tokens, wte, wpe, px);

    for (int i = 0; i < NLAYER; i++) {
        ln_kernel<<<TOKENS / 8, 256>>>(px, ln1w + i * EMB, ln1b + i * EMB, pah);

        gemm_f16<0, 128, false><<<dim3(QKVDIM / 128, TOKENS / 128), 256, smem128s1>>>(
            pah, qh + (size_t)i * QKVDIM * EMB, nullptr,
            qkvb + i * QKVDIM, nullptr, pqkvh, TOKENS, QKVDIM, EMB);

        attn_mma<<<dim3(SEQ / 128, NHEAD, NBATCH), 128, asmem>>>(pqkvh, pyh);

        gemm_f16<1, 96, false><<<dim3(EMB / 96, TOKENS / 128), 256, smem96s1>>>(
            pyh, ah + (size_t)i * EMB * EMB, nullptr,
            atpb + i * EMB, px, px, TOKENS, EMB, EMB);

        ln_kernel<<<TOKENS / 8, 256>>>(px, ln2w + i * EMB, ln2b + i * EMB, pah);

        gemm_f16<2, 128, true><<<dim3(FFDIM / 128, TOKENS / 128), 256, smem128s2>>>(
            pah, fh + (size_t)i * FFDIM * EMB, fl + (size_t)i * FFDIM * EMB,
            fcb + i * FFDIM, nullptr, pmh, TOKENS, FFDIM, EMB);

        gemm_f16<1, 96, false><<<dim3(EMB / 96, TOKENS / 128), 256, smem96s1>>>(
            pmh, ph + (size_t)i * EMB * FFDIM, nullptr,
            fpb + i * EMB, px, px, TOKENS, EMB, FFDIM);
    }

    ln_kernel<<<TOKENS / 8, 256>>>(px, lnfw, lnfb, pah);

    // LM head: M-major raster (x = M tiles, y = N tiles) for L2 reuse of B
    gemm_f16<4, 128, false><<<dim3(TOKENS / 128, (VOCAB + 127) / 128), 256, smem128s1>>>(
        pah, lh, nullptr, nullptr, nullptr, out, TOKENS, VOCAB, EMB);
}